// round 1
// baseline (speedup 1.0000x reference)
#include <cuda_runtime.h>
#include <math.h>

// ---------------- problem constants ----------------
#define Bsz   131072
#define Dd    256
#define S1c   128
#define Lc    8
#define NCc   10
#define BN_EPS 1e-5f
// D*GCONST precomputed: 256 * -0.9189385332046727
#define DGCONST -235.24826450039622f

// ---------------- tiling ----------------
#define BLKM 64          // rows per CTA
#define KT   32          // k tile
#define WTS  260         // padded weight-tile row stride (floats), 16B aligned, conflict-friendly
#define NBLK (Bsz/BLKM)  // 2048 CTAs

#define SMEM_FLOATS (2*BLKM*Dd + KT*WTS + 2*Dd)
#define SMEM_BYTES  (SMEM_FLOATS*4)

// ---------------- scratch (static device memory; no allocs) ----------------
__device__ float g_bufA[(size_t)Bsz*Dd];
__device__ float g_bufB[(size_t)Bsz*Dd];
__device__ float g_ld[Bsz];
__device__ float g_scale[Lc*Dd];
__device__ float g_sumlog[Lc];
__device__ float g_part[(size_t)NBLK*2*Dd];
__device__ float g_stats[2*Dd];

// ---------------- prep: scale = 0.2*softplus(0.5*g), sumlog per layer ----------------
__global__ void prep_kernel(const float* __restrict__ gs) {
    __shared__ float red[256];
    int l = blockIdx.x, d = threadIdx.x;
    float x  = 0.5f * gs[l*Dd + d];
    float sp = (x > 20.f) ? x : log1pf(expf(x));
    float s  = 0.2f * sp;
    g_scale[l*Dd + d] = s;
    red[d] = logf(s);
    __syncthreads();
    #pragma unroll
    for (int o = 128; o; o >>= 1) {
        if (d < o) red[d] += red[d + o];
        __syncthreads();
    }
    if (d == 0) g_sumlog[l] = red[0];
}

// ---------------- fused flow layer ----------------
// x_out = ([x1, x2*exp(s)+a2] * scale + o) @ P^T,  s = 1.9*tanh(a1),
// a = 0.1*(relu(x1@W1+b1)@W2 + b2);  ld += rowsum(s) + sum(log scale)
__global__ void __launch_bounds__(256, 1) flow_kernel(
    const float* __restrict__ xin, float* __restrict__ xout,
    const float* __restrict__ W1, const float* __restrict__ b1,
    const float* __restrict__ W2, const float* __restrict__ b2,
    const float* __restrict__ P,  const float* __restrict__ go, int layer)
{
    extern __shared__ float sm[];
    float* Xs  = sm;                 // [BLKM][Dd]
    float* Hs  = Xs + BLKM*Dd;       // [BLKM][Dd]  (hidden, then s)
    float* Wt  = Hs + BLKM*Dd;       // [KT][WTS]
    float* SCs = Wt + KT*WTS;        // [Dd]
    float* OOs = SCs + Dd;           // [Dd]

    const float* w1  = W1 + (size_t)layer*S1c*Dd;
    const float* w2  = W2 + (size_t)layer*Dd*Dd;
    const float* pp  = P  + (size_t)layer*Dd*Dd;
    const float* bb1 = b1 + layer*Dd;
    const float* bb2 = b2 + layer*Dd;

    const int tid  = threadIdx.x;
    const int row0 = blockIdx.x * BLKM;
    const int ty   = tid >> 5, tx = tid & 31;
    const int r0   = ty * 8,  c0 = tx * 8;

    // load X tile (coalesced float4)
    {
        const float4* src = (const float4*)(xin + (size_t)row0 * Dd);
        float4* dst = (float4*)Xs;
        #pragma unroll 4
        for (int i = tid; i < BLKM*Dd/4; i += 256) dst[i] = src[i];
    }
    if (tid < Dd) { SCs[tid] = g_scale[layer*Dd + tid]; OOs[tid] = go[layer*Dd + tid]; }
    __syncthreads();

    float acc[8][8];

    // ================= GEMM1: H = relu(X[:, :128] @ W1 + b1) =================
    {
        float binit[8];
        #pragma unroll
        for (int j = 0; j < 8; j++) binit[j] = __ldg(bb1 + c0 + j);
        #pragma unroll
        for (int i = 0; i < 8; i++)
            #pragma unroll
            for (int j = 0; j < 8; j++) acc[i][j] = binit[j];

        for (int k0 = 0; k0 < S1c; k0 += KT) {
            for (int i = tid; i < KT*Dd/4; i += 256) {
                int kk = i / (Dd/4), c4 = i % (Dd/4);
                float4 v = ((const float4*)(w1 + (size_t)(k0+kk)*Dd))[c4];
                *((float4*)&Wt[kk*WTS + c4*4]) = v;
            }
            __syncthreads();
            #pragma unroll 8
            for (int k = 0; k < KT; k++) {
                float a[8];
                #pragma unroll
                for (int i = 0; i < 8; i++) a[i] = Xs[(r0+i)*Dd + k0 + k];
                float4 bv0 = *(const float4*)&Wt[k*WTS + c0];
                float4 bv1 = *(const float4*)&Wt[k*WTS + c0 + 4];
                float b[8] = {bv0.x, bv0.y, bv0.z, bv0.w, bv1.x, bv1.y, bv1.z, bv1.w};
                #pragma unroll
                for (int i = 0; i < 8; i++)
                    #pragma unroll
                    for (int j = 0; j < 8; j++) acc[i][j] += a[i] * b[j];
            }
            __syncthreads();
        }
        #pragma unroll
        for (int i = 0; i < 8; i++)
            #pragma unroll
            for (int j = 0; j < 8; j++) Hs[(r0+i)*Dd + c0 + j] = fmaxf(acc[i][j], 0.f);
    }

    // ================= GEMM2: A2 = H @ W2 + b2 =================
    {
        float binit[8];
        #pragma unroll
        for (int j = 0; j < 8; j++) binit[j] = __ldg(bb2 + c0 + j);
        #pragma unroll
        for (int i = 0; i < 8; i++)
            #pragma unroll
            for (int j = 0; j < 8; j++) acc[i][j] = binit[j];

        for (int k0 = 0; k0 < Dd; k0 += KT) {
            for (int i = tid; i < KT*Dd/4; i += 256) {
                int kk = i / (Dd/4), c4 = i % (Dd/4);
                float4 v = ((const float4*)(w2 + (size_t)(k0+kk)*Dd))[c4];
                *((float4*)&Wt[kk*WTS + c4*4]) = v;
            }
            __syncthreads();
            #pragma unroll 8
            for (int k = 0; k < KT; k++) {
                float a[8];
                #pragma unroll
                for (int i = 0; i < 8; i++) a[i] = Hs[(r0+i)*Dd + k0 + k];
                float4 bv0 = *(const float4*)&Wt[k*WTS + c0];
                float4 bv1 = *(const float4*)&Wt[k*WTS + c0 + 4];
                float b[8] = {bv0.x, bv0.y, bv0.z, bv0.w, bv1.x, bv1.y, bv1.z, bv1.w};
                #pragma unroll
                for (int i = 0; i < 8; i++)
                    #pragma unroll
                    for (int j = 0; j < 8; j++) acc[i][j] += a[i] * b[j];
            }
            __syncthreads();
        }
    }

    // ================= coupling epilogue =================
    // acc holds raw H@W2+b2; a = 0.1*acc.
    if (tx < 16) {   // owns cols [0,128): write s into Hs[:, 0:128]
        #pragma unroll
        for (int i = 0; i < 8; i++)
            #pragma unroll
            for (int j = 0; j < 8; j++)
                Hs[(r0+i)*Dd + c0 + j] = 1.9f * tanhf(0.1f * acc[i][j]);
    }
    __syncthreads();

    #pragma unroll
    for (int i = 0; i < 8; i++) {
        #pragma unroll
        for (int j = 0; j < 8; j++) {
            int c = c0 + j, r = r0 + i;
            float v;
            if (tx < 16) {
                v = Xs[r*Dd + c];                                   // x1 unchanged
            } else {
                float s = Hs[r*Dd + (c - 128)];
                v = Xs[r*Dd + c] * expf(s) + 0.1f * acc[i][j];      // x2' = x2*e^s + a2
            }
            Xs[r*Dd + c] = v * SCs[c] + OOs[c];                     // actnorm
        }
    }
    // logdet update (skewed column order -> conflict-free, deterministic per row)
    if (tid < BLKM) {
        float rs = 0.f;
        #pragma unroll 8
        for (int k = 0; k < S1c; k++) {
            int kk = (k + tid) & (S1c - 1);
            rs += Hs[tid*Dd + kk];
        }
        float prev = layer ? g_ld[row0 + tid] : 0.f;
        g_ld[row0 + tid] = prev + rs + g_sumlog[layer];
    }
    __syncthreads();

    // ================= GEMM3: XO = Xc @ P^T =================
    {
        #pragma unroll
        for (int i = 0; i < 8; i++)
            #pragma unroll
            for (int j = 0; j < 8; j++) acc[i][j] = 0.f;

        for (int k0 = 0; k0 < Dd; k0 += KT) {
            for (int i = tid; i < KT*Dd; i += 256) {
                int kk = i & (KT-1), n = i >> 5;
                Wt[kk*WTS + n] = pp[(size_t)n*Dd + k0 + kk];   // transpose stage
            }
            __syncthreads();
            #pragma unroll 8
            for (int k = 0; k < KT; k++) {
                float a[8];
                #pragma unroll
                for (int i = 0; i < 8; i++) a[i] = Xs[(r0+i)*Dd + k0 + k];
                float4 bv0 = *(const float4*)&Wt[k*WTS + c0];
                float4 bv1 = *(const float4*)&Wt[k*WTS + c0 + 4];
                float b[8] = {bv0.x, bv0.y, bv0.z, bv0.w, bv1.x, bv1.y, bv1.z, bv1.w};
                #pragma unroll
                for (int i = 0; i < 8; i++)
                    #pragma unroll
                    for (int j = 0; j < 8; j++) acc[i][j] += a[i] * b[j];
            }
            __syncthreads();
        }
        #pragma unroll
        for (int i = 0; i < 8; i++) {
            float4 v0 = make_float4(acc[i][0], acc[i][1], acc[i][2], acc[i][3]);
            float4 v1 = make_float4(acc[i][4], acc[i][5], acc[i][6], acc[i][7]);
            float4* o = (float4*)(xout + (size_t)(row0 + r0 + i)*Dd + c0);
            o[0] = v0; o[1] = v1;
        }
    }
}

// ---------------- head stage 1: h = z@Wh1 + bh1, + per-CTA column partials ----------------
__global__ void __launch_bounds__(256, 1) head1_kernel(
    const float* __restrict__ z, float* __restrict__ h,
    const float* __restrict__ Wh1, const float* __restrict__ bh1)
{
    extern __shared__ float sm[];
    float* Xs = sm;                // [BLKM][Dd]
    float* Ps = Xs + BLKM*Dd;      // partials: [8][Dd] sums, [8][Dd] sumsq
    float* Wt = Ps + BLKM*Dd;      // [KT][WTS]

    const int tid  = threadIdx.x;
    const int row0 = blockIdx.x * BLKM;
    const int ty   = tid >> 5, tx = tid & 31;
    const int r0   = ty * 8,  c0 = tx * 8;

    {
        const float4* src = (const float4*)(z + (size_t)row0 * Dd);
        float4* dst = (float4*)Xs;
        #pragma unroll 4
        for (int i = tid; i < BLKM*Dd/4; i += 256) dst[i] = src[i];
    }
    __syncthreads();

    float acc[8][8];
    float binit[8];
    #pragma unroll
    for (int j = 0; j < 8; j++) binit[j] = __ldg(bh1 + c0 + j);
    #pragma unroll
    for (int i = 0; i < 8; i++)
        #pragma unroll
        for (int j = 0; j < 8; j++) acc[i][j] = binit[j];

    for (int k0 = 0; k0 < Dd; k0 += KT) {
        for (int i = tid; i < KT*Dd/4; i += 256) {
            int kk = i / (Dd/4), c4 = i % (Dd/4);
            float4 v = ((const float4*)(Wh1 + (size_t)(k0+kk)*Dd))[c4];
            *((float4*)&Wt[kk*WTS + c4*4]) = v;
        }
        __syncthreads();
        #pragma unroll 8
        for (int k = 0; k < KT; k++) {
            float a[8];
            #pragma unroll
            for (int i = 0; i < 8; i++) a[i] = Xs[(r0+i)*Dd + k0 + k];
            float4 bv0 = *(const float4*)&Wt[k*WTS + c0];
            float4 bv1 = *(const float4*)&Wt[k*WTS + c0 + 4];
            float b[8] = {bv0.x, bv0.y, bv0.z, bv0.w, bv1.x, bv1.y, bv1.z, bv1.w};
            #pragma unroll
            for (int i = 0; i < 8; i++)
                #pragma unroll
                for (int j = 0; j < 8; j++) acc[i][j] += a[i] * b[j];
        }
        __syncthreads();
    }

    // write h + deterministic column partials
    float cs[8], cq[8];
    #pragma unroll
    for (int j = 0; j < 8; j++) { cs[j] = 0.f; cq[j] = 0.f; }
    #pragma unroll
    for (int i = 0; i < 8; i++) {
        float4 v0 = make_float4(acc[i][0], acc[i][1], acc[i][2], acc[i][3]);
        float4 v1 = make_float4(acc[i][4], acc[i][5], acc[i][6], acc[i][7]);
        float4* o = (float4*)(h + (size_t)(row0 + r0 + i)*Dd + c0);
        o[0] = v0; o[1] = v1;
        #pragma unroll
        for (int j = 0; j < 8; j++) { float x = acc[i][j]; cs[j] += x; cq[j] += x*x; }
    }
    #pragma unroll
    for (int j = 0; j < 8; j++) {
        Ps[ty*Dd + c0 + j]       = cs[j];
        Ps[(8+ty)*Dd + c0 + j]   = cq[j];
    }
    __syncthreads();
    if (tid < Dd) {
        float s = 0.f, q = 0.f;
        #pragma unroll
        for (int g = 0; g < 8; g++) { s += Ps[g*Dd + tid]; q += Ps[(8+g)*Dd + tid]; }
        g_part[(size_t)blockIdx.x*2*Dd + tid]       = s;
        g_part[(size_t)blockIdx.x*2*Dd + Dd + tid]  = q;
    }
}

// ---------------- head stage 2: fold BN into affine (deterministic reduce) ----------------
__global__ void stats_kernel(const float* __restrict__ gamma, const float* __restrict__ beta) {
    int c = threadIdx.x;
    float s0=0.f,s1=0.f,s2=0.f,s3=0.f, q0=0.f,q1=0.f,q2=0.f,q3=0.f;
    for (int i = 0; i < NBLK; i += 4) {
        s0 += g_part[(size_t)(i+0)*2*Dd + c];      q0 += g_part[(size_t)(i+0)*2*Dd + Dd + c];
        s1 += g_part[(size_t)(i+1)*2*Dd + c];      q1 += g_part[(size_t)(i+1)*2*Dd + Dd + c];
        s2 += g_part[(size_t)(i+2)*2*Dd + c];      q2 += g_part[(size_t)(i+2)*2*Dd + Dd + c];
        s3 += g_part[(size_t)(i+3)*2*Dd + c];      q3 += g_part[(size_t)(i+3)*2*Dd + Dd + c];
    }
    float s = (s0+s1)+(s2+s3), q = (q0+q1)+(q2+q3);
    float mu  = s * (1.f/Bsz);
    float var = q * (1.f/Bsz) - mu*mu;
    float a = gamma[c] * rsqrtf(var + BN_EPS);
    g_stats[c]      = a;
    g_stats[Dd + c] = beta[c] - mu * a;
}

// ---------------- log_px ----------------
__global__ void logpx_kernel(const float* __restrict__ z, float* __restrict__ out) {
    int warp = threadIdx.x >> 5, lane = threadIdx.x & 31;
    size_t row = (size_t)blockIdx.x * 8 + warp;
    const float4* zr = (const float4*)(z + row*Dd);
    float4 v0 = zr[lane*2], v1 = zr[lane*2 + 1];
    float ss = v0.x*v0.x + v0.y*v0.y + v0.z*v0.z + v0.w*v0.w
             + v1.x*v1.x + v1.y*v1.y + v1.z*v1.z + v1.w*v1.w;
    #pragma unroll
    for (int o = 16; o; o >>= 1) ss += __shfl_down_sync(0xffffffffu, ss, o);
    if (lane == 0)
        out[row] = (DGCONST - 0.5f*ss + g_ld[row]) * (1.0f/Dd);
}

// ---------------- logits: relu(BN(h)) @ Wh2 + bh2 ----------------
__global__ void __launch_bounds__(256) logits_kernel(
    const float* __restrict__ h, const float* __restrict__ Wh2,
    const float* __restrict__ bh2, float* __restrict__ out)
{
    __shared__ float w2s[Dd*NCc];
    __shared__ float As[Dd], Bs[Dd];
    int tid = threadIdx.x;
    for (int i = tid; i < Dd*NCc; i += 256) w2s[i] = Wh2[i];
    if (tid < Dd) { As[tid] = g_stats[tid]; Bs[tid] = g_stats[Dd + tid]; }
    __syncthreads();

    int warp = tid >> 5, lane = tid & 31;
    size_t row = (size_t)blockIdx.x * 8 + warp;
    const float4* hr = (const float4*)(h + row*Dd);
    float4 v0 = hr[lane*2], v1 = hr[lane*2 + 1];
    int k0 = lane * 8;
    float hn[8];
    hn[0] = fmaxf(v0.x*As[k0+0] + Bs[k0+0], 0.f);
    hn[1] = fmaxf(v0.y*As[k0+1] + Bs[k0+1], 0.f);
    hn[2] = fmaxf(v0.z*As[k0+2] + Bs[k0+2], 0.f);
    hn[3] = fmaxf(v0.w*As[k0+3] + Bs[k0+3], 0.f);
    hn[4] = fmaxf(v1.x*As[k0+4] + Bs[k0+4], 0.f);
    hn[5] = fmaxf(v1.y*As[k0+5] + Bs[k0+5], 0.f);
    hn[6] = fmaxf(v1.z*As[k0+6] + Bs[k0+6], 0.f);
    hn[7] = fmaxf(v1.w*As[k0+7] + Bs[k0+7], 0.f);

    float acc[NCc];
    #pragma unroll
    for (int c = 0; c < NCc; c++) acc[c] = 0.f;
    #pragma unroll
    for (int kk = 0; kk < 8; kk++) {
        float x = hn[kk];
        const float* wr = &w2s[(k0+kk)*NCc];
        #pragma unroll
        for (int c = 0; c < NCc; c++) acc[c] += x * wr[c];
    }
    #pragma unroll
    for (int c = 0; c < NCc; c++) {
        #pragma unroll
        for (int o = 16; o; o >>= 1) acc[c] += __shfl_down_sync(0xffffffffu, acc[c], o);
    }
    if (lane == 0) {
        #pragma unroll
        for (int c = 0; c < NCc; c++) out[row*NCc + c] = acc[c] + __ldg(bh2 + c);
    }
}

// ---------------- launch ----------------
extern "C" void kernel_launch(void* const* d_in, const int* in_sizes, int n_in,
                              void* d_out, int out_size)
{
    const float* feat  = (const float*)d_in[0];
    const float* W1    = (const float*)d_in[1];
    const float* b1    = (const float*)d_in[2];
    const float* W2    = (const float*)d_in[3];
    const float* b2    = (const float*)d_in[4];
    const float* gs    = (const float*)d_in[5];
    const float* go    = (const float*)d_in[6];
    const float* P     = (const float*)d_in[7];
    const float* Wh1   = (const float*)d_in[8];
    const float* bh1   = (const float*)d_in[9];
    const float* gamma = (const float*)d_in[10];
    const float* beta  = (const float*)d_in[11];
    const float* Wh2   = (const float*)d_in[12];
    const float* bh2   = (const float*)d_in[13];
    float* out = (float*)d_out;

    cudaFuncSetAttribute(flow_kernel,  cudaFuncAttributeMaxDynamicSharedMemorySize, SMEM_BYTES);
    cudaFuncSetAttribute(head1_kernel, cudaFuncAttributeMaxDynamicSharedMemorySize, SMEM_BYTES);

    float *bufA = nullptr, *bufB = nullptr;
    cudaGetSymbolAddress((void**)&bufA, g_bufA);
    cudaGetSymbolAddress((void**)&bufB, g_bufB);

    prep_kernel<<<Lc, 256>>>(gs);

    const float* cin = feat;
    for (int l = 0; l < Lc; l++) {
        float* cout = (l & 1) ? bufB : bufA;
        flow_kernel<<<NBLK, 256, SMEM_BYTES>>>(cin, cout, W1, b1, W2, b2, P, go, l);
        cin = cout;
    }
    // z lives in bufB after layer 7
    head1_kernel<<<NBLK, 256, SMEM_BYTES>>>(bufB, bufA, Wh1, bh1);
    stats_kernel<<<1, 256>>>(gamma, beta);
    logpx_kernel<<<Bsz/8, 256>>>(bufB, out);
    logits_kernel<<<Bsz/8, 256>>>(bufA, Wh2, bh2, out + Bsz);
}

// round 2
// speedup vs baseline: 1.4061x; 1.4061x over previous
#include <cuda_runtime.h>
#include <math.h>

// ---------------- problem constants ----------------
#define Bsz   131072
#define Dd    256
#define S1c   128
#define Lc    8
#define NCc   10
#define BN_EPS 1e-5f
#define DGCONST -235.24826450039622f   // D * GCONST

// ---------------- tiling ----------------
#define BLKM 64           // rows per CTA
#define KT   32           // k tile
#define WTS  260          // padded weight-tile row stride (floats)
#define NTHR 512
#define NBLK (Bsz/BLKM)   // 2048 CTAs

#define SMEM_FLOATS (2*BLKM*Dd + 2*KT*WTS + 2*Dd)
#define SMEM_BYTES  (SMEM_FLOATS*4)

typedef unsigned long long ull;

// ---------------- scratch (static device memory; no allocs) ----------------
__device__ float g_bufA[(size_t)Bsz*Dd];
__device__ float g_bufB[(size_t)Bsz*Dd];
__device__ float g_ld[Bsz];
__device__ float g_scale[Lc*Dd];
__device__ float g_sumlog[Lc];
__device__ float g_PT[(size_t)Lc*Dd*Dd];
__device__ float g_part[(size_t)NBLK*2*Dd];
__device__ float g_stats[2*Dd];

// ---------------- f32x2 packed helpers ----------------
__device__ __forceinline__ ull pack2(float x, float y) {
    ull r; asm("mov.b64 %0, {%1, %2};" : "=l"(r) : "f"(x), "f"(y)); return r;
}
__device__ __forceinline__ ull fma2(ull a, ull b, ull c) {
    ull d; asm("fma.rn.f32x2 %0, %1, %2, %3;" : "=l"(d) : "l"(a), "l"(b), "l"(c)); return d;
}
__device__ __forceinline__ float2 unpack2(ull v) {
    float2 f; asm("mov.b64 {%0, %1}, %2;" : "=f"(f.x), "=f"(f.y) : "l"(v)); return f;
}

// ---------------- cp.async helpers ----------------
__device__ __forceinline__ void cpa16(float* dst_smem, const float* src) {
    unsigned saddr = (unsigned)__cvta_generic_to_shared(dst_smem);
    asm volatile("cp.async.cg.shared.global [%0], [%1], 16;" :: "r"(saddr), "l"(src));
}
#define CP_COMMIT  asm volatile("cp.async.commit_group;")
#define CP_WAIT1   asm volatile("cp.async.wait_group 1;")
#define CP_WAIT0   asm volatile("cp.async.wait_group 0;")

// ---------------- prep: scale = 0.2*softplus(0.5*g), sumlog per layer ----------------
__global__ void prep_kernel(const float* __restrict__ gs) {
    __shared__ float red[256];
    int l = blockIdx.x, d = threadIdx.x;
    float x  = 0.5f * gs[l*Dd + d];
    float sp = (x > 20.f) ? x : log1pf(expf(x));
    float s  = 0.2f * sp;
    g_scale[l*Dd + d] = s;
    red[d] = logf(s);
    __syncthreads();
    #pragma unroll
    for (int o = 128; o; o >>= 1) {
        if (d < o) red[d] += red[d + o];
        __syncthreads();
    }
    if (d == 0) g_sumlog[l] = red[0];
}

// ---------------- P transpose: g_PT[l][k][n] = P[l][n][k] ----------------
__global__ void ptrans_kernel(const float* __restrict__ P) {
    __shared__ float t[32][33];
    int l  = blockIdx.z;
    int k0 = blockIdx.x * 32, n0 = blockIdx.y * 32;
    const float* src = P   + (size_t)l*Dd*Dd;
    float*       dst = g_PT + (size_t)l*Dd*Dd;
    #pragma unroll
    for (int r = threadIdx.y; r < 32; r += 8)
        t[r][threadIdx.x] = src[(size_t)(n0 + r)*Dd + k0 + threadIdx.x];
    __syncthreads();
    #pragma unroll
    for (int r = threadIdx.y; r < 32; r += 8)
        dst[(size_t)(k0 + r)*Dd + n0 + threadIdx.x] = t[threadIdx.x][r];
}

// ---------------- core GEMM microkernel (f32x2, cp.async double buffer) ----------------
// acc[i][p] accumulates rows r0..r0+7, col pairs (c0+2p, c0+2p+1), p=0,1 covering 4 cols.
// As: smem activations [*, Dd]; Wg: global weights [Ktot][256] (K-major rows).
__device__ __forceinline__ void gemm_acc(
    const float* __restrict__ As, const float* __restrict__ Wg,
    float* Wt, int Ktot, int r0, int c0, int tid, ull acc[8][2])
{
    const int NT4 = KT * (Dd/4);   // 2048 float4 per tile
    // stage tile 0
    #pragma unroll
    for (int t = tid; t < NT4; t += NTHR) {
        int kk = t >> 6, c4 = t & 63;
        cpa16(Wt + kk*WTS + c4*4, Wg + (size_t)kk*Dd + c4*4);
    }
    CP_COMMIT;
    const int ntiles = Ktot / KT;
    for (int kt = 0; kt < ntiles; kt++) {
        const float* cur = Wt + (kt & 1) * KT * WTS;
        if (kt + 1 < ntiles) {
            float* nxt = Wt + ((kt + 1) & 1) * KT * WTS;
            const float* wsrc = Wg + (size_t)(kt + 1) * KT * Dd;
            #pragma unroll
            for (int t = tid; t < NT4; t += NTHR) {
                int kk = t >> 6, c4 = t & 63;
                cpa16(nxt + kk*WTS + c4*4, wsrc + (size_t)kk*Dd + c4*4);
            }
            CP_COMMIT;
            CP_WAIT1;
        } else {
            CP_WAIT0;
        }
        __syncthreads();
        const float* arow = As + (size_t)r0*Dd + kt*KT;
        #pragma unroll
        for (int k4 = 0; k4 < KT; k4 += 4) {
            float4 av[8];
            #pragma unroll
            for (int i = 0; i < 8; i++)
                av[i] = *(const float4*)(arow + (size_t)i*Dd + k4);
            #pragma unroll
            for (int kk = 0; kk < 4; kk++) {
                ulonglong2 bv = *(const ulonglong2*)(cur + (k4 + kk)*WTS + c0);
                #pragma unroll
                for (int i = 0; i < 8; i++) {
                    float a = (kk == 0) ? av[i].x : (kk == 1) ? av[i].y
                            : (kk == 2) ? av[i].z : av[i].w;
                    ull aa = pack2(a, a);
                    acc[i][0] = fma2(aa, bv.x, acc[i][0]);
                    acc[i][1] = fma2(aa, bv.y, acc[i][1]);
                }
            }
        }
        __syncthreads();
    }
}

// ---------------- fused flow layer ----------------
__global__ void __launch_bounds__(NTHR, 1) flow_kernel(
    const float* __restrict__ xin, float* __restrict__ xout,
    const float* __restrict__ W1, const float* __restrict__ b1,
    const float* __restrict__ W2, const float* __restrict__ b2,
    const float* __restrict__ go, int layer)
{
    extern __shared__ float sm[];
    float* Xs  = sm;                   // [BLKM][Dd]
    float* Hs  = Xs + BLKM*Dd;         // [BLKM][Dd]
    float* Wt  = Hs + BLKM*Dd;         // [2][KT][WTS]
    float* SCs = Wt + 2*KT*WTS;        // [Dd]
    float* OOs = SCs + Dd;             // [Dd]

    const float* w1  = W1   + (size_t)layer*S1c*Dd;
    const float* w2  = W2   + (size_t)layer*Dd*Dd;
    const float* pt  = g_PT + (size_t)layer*Dd*Dd;
    const float* bb1 = b1 + layer*Dd;
    const float* bb2 = b2 + layer*Dd;

    const int tid  = threadIdx.x;
    const int row0 = blockIdx.x * BLKM;
    const int tx   = tid & 31;
    const int colhalf = (tid >> 5) & 1;
    const int r0   = (tid >> 6) * 8;
    const int c0   = colhalf * 128 + tx * 4;

    // load X tile (coalesced float4)
    {
        const float4* src = (const float4*)(xin + (size_t)row0 * Dd);
        float4* dst = (float4*)Xs;
        #pragma unroll
        for (int i = tid; i < BLKM*Dd/4; i += NTHR) dst[i] = src[i];
    }
    if (tid < Dd) { SCs[tid] = g_scale[layer*Dd + tid]; OOs[tid] = go[layer*Dd + tid]; }
    __syncthreads();

    ull acc[8][2];

    // ===== GEMM1: H = relu(X[:, :128] @ W1 + b1) =====
    {
        ull i0 = pack2(__ldg(bb1 + c0),     __ldg(bb1 + c0 + 1));
        ull i1 = pack2(__ldg(bb1 + c0 + 2), __ldg(bb1 + c0 + 3));
        #pragma unroll
        for (int i = 0; i < 8; i++) { acc[i][0] = i0; acc[i][1] = i1; }
        gemm_acc(Xs, w1, Wt, S1c, r0, c0, tid, acc);
        #pragma unroll
        for (int i = 0; i < 8; i++) {
            float2 p0 = unpack2(acc[i][0]), p1 = unpack2(acc[i][1]);
            float* h = &Hs[(size_t)(r0 + i)*Dd + c0];
            h[0] = fmaxf(p0.x, 0.f); h[1] = fmaxf(p0.y, 0.f);
            h[2] = fmaxf(p1.x, 0.f); h[3] = fmaxf(p1.y, 0.f);
        }
        // gemm_acc's first internal syncthreads (in GEMM2) orders these writes
    }

    // ===== GEMM2: A2raw = H @ W2 + b2 =====
    {
        ull i0 = pack2(__ldg(bb2 + c0),     __ldg(bb2 + c0 + 1));
        ull i1 = pack2(__ldg(bb2 + c0 + 2), __ldg(bb2 + c0 + 3));
        #pragma unroll
        for (int i = 0; i < 8; i++) { acc[i][0] = i0; acc[i][1] = i1; }
        gemm_acc(Hs, w2, Wt, Dd, r0, c0, tid, acc);
    }

    // ===== coupling epilogue =====
    float ar[8][4];
    #pragma unroll
    for (int i = 0; i < 8; i++) {
        float2 p0 = unpack2(acc[i][0]), p1 = unpack2(acc[i][1]);
        ar[i][0] = p0.x; ar[i][1] = p0.y; ar[i][2] = p1.x; ar[i][3] = p1.y;
    }
    if (colhalf == 0) {
        // s = 1.9*tanh(0.1*a1) -> Hs[:, 0:128]; x1 path: actnorm only
        #pragma unroll
        for (int i = 0; i < 8; i++) {
            int r = r0 + i;
            #pragma unroll
            for (int j = 0; j < 4; j++) {
                int c = c0 + j;
                Hs[(size_t)r*Dd + c] = 1.9f * tanhf(0.1f * ar[i][j]);
                Xs[(size_t)r*Dd + c] = Xs[(size_t)r*Dd + c] * SCs[c] + OOs[c];
            }
        }
    }
    __syncthreads();
    if (colhalf == 1) {
        #pragma unroll
        for (int i = 0; i < 8; i++) {
            int r = r0 + i;
            #pragma unroll
            for (int j = 0; j < 4; j++) {
                int c = c0 + j;
                float s = Hs[(size_t)r*Dd + (c - 128)];
                float v = Xs[(size_t)r*Dd + c] * expf(s) + 0.1f * ar[i][j];
                Xs[(size_t)r*Dd + c] = v * SCs[c] + OOs[c];
            }
        }
    }
    // logdet (deterministic, skewed to avoid conflicts)
    if (tid < BLKM) {
        float rs = 0.f;
        #pragma unroll 8
        for (int k = 0; k < S1c; k++) {
            int kk = (k + tid) & (S1c - 1);
            rs += Hs[(size_t)tid*Dd + kk];
        }
        float prev = layer ? g_ld[row0 + tid] : 0.f;
        g_ld[row0 + tid] = prev + rs + g_sumlog[layer];
    }
    // colhalf==1 Xs writes are ordered by gemm_acc's internal sync below

    // ===== GEMM3: XO = Xc @ P^T (pre-transposed PT is K-major) =====
    {
        #pragma unroll
        for (int i = 0; i < 8; i++) { acc[i][0] = 0ull; acc[i][1] = 0ull; }
        gemm_acc(Xs, pt, Wt, Dd, r0, c0, tid, acc);
        #pragma unroll
        for (int i = 0; i < 8; i++) {
            float2 p0 = unpack2(acc[i][0]), p1 = unpack2(acc[i][1]);
            float4 v = make_float4(p0.x, p0.y, p1.x, p1.y);
            *(float4*)(xout + (size_t)(row0 + r0 + i)*Dd + c0) = v;
        }
    }
}

// ---------------- head stage 1: h = z@Wh1 + bh1 + per-CTA BN partials ----------------
__global__ void __launch_bounds__(NTHR, 1) head1_kernel(
    const float* __restrict__ z, float* __restrict__ h,
    const float* __restrict__ Wh1, const float* __restrict__ bh1)
{
    extern __shared__ float sm[];
    float* Xs = sm;                 // [BLKM][Dd]
    float* Ps = Xs + BLKM*Dd;       // partials: [8][Dd] sums then [8][Dd] sumsq
    float* Wt = Ps + BLKM*Dd;       // [2][KT][WTS]

    const int tid  = threadIdx.x;
    const int row0 = blockIdx.x * BLKM;
    const int tx   = tid & 31;
    const int colhalf = (tid >> 5) & 1;
    const int band = tid >> 6;                 // 0..7
    const int r0   = band * 8;
    const int c0   = colhalf * 128 + tx * 4;

    {
        const float4* src = (const float4*)(z + (size_t)row0 * Dd);
        float4* dst = (float4*)Xs;
        #pragma unroll
        for (int i = tid; i < BLKM*Dd/4; i += NTHR) dst[i] = src[i];
    }
    __syncthreads();

    ull acc[8][2];
    ull i0 = pack2(__ldg(bh1 + c0),     __ldg(bh1 + c0 + 1));
    ull i1 = pack2(__ldg(bh1 + c0 + 2), __ldg(bh1 + c0 + 3));
    #pragma unroll
    for (int i = 0; i < 8; i++) { acc[i][0] = i0; acc[i][1] = i1; }
    gemm_acc(Xs, Wh1, Wt, Dd, r0, c0, tid, acc);

    float cs[4] = {0.f,0.f,0.f,0.f}, cq[4] = {0.f,0.f,0.f,0.f};
    #pragma unroll
    for (int i = 0; i < 8; i++) {
        float2 p0 = unpack2(acc[i][0]), p1 = unpack2(acc[i][1]);
        float v[4] = {p0.x, p0.y, p1.x, p1.y};
        *(float4*)(h + (size_t)(row0 + r0 + i)*Dd + c0) = make_float4(v[0],v[1],v[2],v[3]);
        #pragma unroll
        for (int j = 0; j < 4; j++) { cs[j] += v[j]; cq[j] += v[j]*v[j]; }
    }
    #pragma unroll
    for (int j = 0; j < 4; j++) {
        Ps[(size_t)band*Dd + c0 + j]        = cs[j];
        Ps[(size_t)(8+band)*Dd + c0 + j]    = cq[j];
    }
    __syncthreads();
    if (tid < Dd) {
        float s = 0.f, q = 0.f;
        #pragma unroll
        for (int g = 0; g < 8; g++) { s += Ps[(size_t)g*Dd + tid]; q += Ps[(size_t)(8+g)*Dd + tid]; }
        g_part[(size_t)blockIdx.x*2*Dd + tid]      = s;
        g_part[(size_t)blockIdx.x*2*Dd + Dd + tid] = q;
    }
}

// ---------------- BN stats fold (deterministic) ----------------
__global__ void stats_kernel(const float* __restrict__ gamma, const float* __restrict__ beta) {
    int c = threadIdx.x;
    float s0=0.f,s1=0.f,s2=0.f,s3=0.f, q0=0.f,q1=0.f,q2=0.f,q3=0.f;
    for (int i = 0; i < NBLK; i += 4) {
        s0 += g_part[(size_t)(i+0)*2*Dd + c];   q0 += g_part[(size_t)(i+0)*2*Dd + Dd + c];
        s1 += g_part[(size_t)(i+1)*2*Dd + c];   q1 += g_part[(size_t)(i+1)*2*Dd + Dd + c];
        s2 += g_part[(size_t)(i+2)*2*Dd + c];   q2 += g_part[(size_t)(i+2)*2*Dd + Dd + c];
        s3 += g_part[(size_t)(i+3)*2*Dd + c];   q3 += g_part[(size_t)(i+3)*2*Dd + Dd + c];
    }
    float s = (s0+s1)+(s2+s3), q = (q0+q1)+(q2+q3);
    float mu  = s * (1.f/Bsz);
    float var = q * (1.f/Bsz) - mu*mu;
    float a = gamma[c] * rsqrtf(var + BN_EPS);
    g_stats[c]      = a;
    g_stats[Dd + c] = beta[c] - mu * a;
}

// ---------------- log_px ----------------
__global__ void logpx_kernel(const float* __restrict__ z, float* __restrict__ out) {
    int warp = threadIdx.x >> 5, lane = threadIdx.x & 31;
    size_t row = (size_t)blockIdx.x * 8 + warp;
    const float4* zr = (const float4*)(z + row*Dd);
    float4 v0 = zr[lane*2], v1 = zr[lane*2 + 1];
    float ss = v0.x*v0.x + v0.y*v0.y + v0.z*v0.z + v0.w*v0.w
             + v1.x*v1.x + v1.y*v1.y + v1.z*v1.z + v1.w*v1.w;
    #pragma unroll
    for (int o = 16; o; o >>= 1) ss += __shfl_down_sync(0xffffffffu, ss, o);
    if (lane == 0)
        out[row] = (DGCONST - 0.5f*ss + g_ld[row]) * (1.0f/Dd);
}

// ---------------- logits: relu(BN(h)) @ Wh2 + bh2 ----------------
__global__ void __launch_bounds__(256) logits_kernel(
    const float* __restrict__ h, const float* __restrict__ Wh2,
    const float* __restrict__ bh2, float* __restrict__ out)
{
    __shared__ float w2s[Dd*NCc];
    __shared__ float As[Dd], Bs[Dd];
    int tid = threadIdx.x;
    for (int i = tid; i < Dd*NCc; i += 256) w2s[i] = Wh2[i];
    if (tid < Dd) { As[tid] = g_stats[tid]; Bs[tid] = g_stats[Dd + tid]; }
    __syncthreads();

    int warp = tid >> 5, lane = tid & 31;
    size_t row = (size_t)blockIdx.x * 8 + warp;
    const float4* hr = (const float4*)(h + row*Dd);
    float4 v0 = hr[lane*2], v1 = hr[lane*2 + 1];
    int k0 = lane * 8;
    float hn[8];
    hn[0] = fmaxf(v0.x*As[k0+0] + Bs[k0+0], 0.f);
    hn[1] = fmaxf(v0.y*As[k0+1] + Bs[k0+1], 0.f);
    hn[2] = fmaxf(v0.z*As[k0+2] + Bs[k0+2], 0.f);
    hn[3] = fmaxf(v0.w*As[k0+3] + Bs[k0+3], 0.f);
    hn[4] = fmaxf(v1.x*As[k0+4] + Bs[k0+4], 0.f);
    hn[5] = fmaxf(v1.y*As[k0+5] + Bs[k0+5], 0.f);
    hn[6] = fmaxf(v1.z*As[k0+6] + Bs[k0+6], 0.f);
    hn[7] = fmaxf(v1.w*As[k0+7] + Bs[k0+7], 0.f);

    float acc[NCc];
    #pragma unroll
    for (int c = 0; c < NCc; c++) acc[c] = 0.f;
    #pragma unroll
    for (int kk = 0; kk < 8; kk++) {
        float x = hn[kk];
        const float* wr = &w2s[(k0+kk)*NCc];
        #pragma unroll
        for (int c = 0; c < NCc; c++) acc[c] += x * wr[c];
    }
    #pragma unroll
    for (int c = 0; c < NCc; c++) {
        #pragma unroll
        for (int o = 16; o; o >>= 1) acc[c] += __shfl_down_sync(0xffffffffu, acc[c], o);
    }
    if (lane == 0) {
        #pragma unroll
        for (int c = 0; c < NCc; c++) out[row*NCc + c] = acc[c] + __ldg(bh2 + c);
    }
}

// ---------------- launch ----------------
extern "C" void kernel_launch(void* const* d_in, const int* in_sizes, int n_in,
                              void* d_out, int out_size)
{
    const float* feat  = (const float*)d_in[0];
    const float* W1    = (const float*)d_in[1];
    const float* b1    = (const float*)d_in[2];
    const float* W2    = (const float*)d_in[3];
    const float* b2    = (const float*)d_in[4];
    const float* gs    = (const float*)d_in[5];
    const float* go    = (const float*)d_in[6];
    const float* P     = (const float*)d_in[7];
    const float* Wh1   = (const float*)d_in[8];
    const float* bh1   = (const float*)d_in[9];
    const float* gamma = (const float*)d_in[10];
    const float* beta  = (const float*)d_in[11];
    const float* Wh2   = (const float*)d_in[12];
    const float* bh2   = (const float*)d_in[13];
    float* out = (float*)d_out;

    cudaFuncSetAttribute(flow_kernel,  cudaFuncAttributeMaxDynamicSharedMemorySize, SMEM_BYTES);
    cudaFuncSetAttribute(head1_kernel, cudaFuncAttributeMaxDynamicSharedMemorySize, SMEM_BYTES);

    float *bufA = nullptr, *bufB = nullptr;
    cudaGetSymbolAddress((void**)&bufA, g_bufA);
    cudaGetSymbolAddress((void**)&bufB, g_bufB);

    prep_kernel<<<Lc, 256>>>(gs);
    ptrans_kernel<<<dim3(8, 8, Lc), dim3(32, 8)>>>(P);

    const float* cin = feat;
    for (int l = 0; l < Lc; l++) {
        float* cout = (l & 1) ? bufB : bufA;
        flow_kernel<<<NBLK, NTHR, SMEM_BYTES>>>(cin, cout, W1, b1, W2, b2, go, l);
        cin = cout;
    }
    // z lives in bufB after layer 7
    head1_kernel<<<NBLK, NTHR, SMEM_BYTES>>>(bufB, bufA, Wh1, bh1);
    stats_kernel<<<1, 256>>>(gamma, beta);
    logpx_kernel<<<Bsz/8, 256>>>(bufB, out);
    logits_kernel<<<Bsz/8, 256>>>(bufA, Wh2, bh2, out + Bsz);
}

// round 4
// speedup vs baseline: 2.5823x; 1.8364x over previous
#include <cuda_runtime.h>
#include <cuda_bf16.h>
#include <math.h>
#include <stdint.h>

// ---------------- problem constants ----------------
#define Bsz   131072
#define Dd    256
#define Lc    8
#define NCc   10
#define BN_EPS 1e-5f
#define DGCONST -235.24826450039622f   // D * GCONST

#define MROW  64
#define NTHR  256
#define NBLK  (Bsz/MROW)      // 2048 CTAs
#define APAD  264             // bf16 elems per A row (padded)
#define BPAD  40              // bf16 elems per B row (padded, 80B = 16B-multiple)

// smem byte offsets
#define OFF_XHI 0
#define OFF_XLO 33792         // 64*264*2
#define OFF_HB  67584
#define OFF_BW  101376        // 2 buffers x 40960 (each: [hi 20480][lo 20480])
#define SMEMSZ  183296

// ---------------- static device scratch ----------------
__device__ float g_bufA[(size_t)Bsz*Dd];
__device__ float g_bufB[(size_t)Bsz*Dd];
__device__ float g_ld[Bsz];
__device__ float g_scale[Lc*Dd];
__device__ float g_sumlog[Lc];
__device__ float g_part[(size_t)NBLK*2*Dd];
__device__ float g_stats[2*Dd];
// bf16 weight images, [n][k] row-major (k contiguous)
__device__ __nv_bfloat16 g_w1t[(size_t)Lc*256*128];
__device__ __nv_bfloat16 g_w2t[(size_t)Lc*256*256];
__device__ __nv_bfloat16 g_ph [(size_t)Lc*256*256];
__device__ __nv_bfloat16 g_pl [(size_t)Lc*256*256];
__device__ __nv_bfloat16 g_whh[(size_t)256*256];
__device__ __nv_bfloat16 g_whl[(size_t)256*256];

// ---------------- helpers ----------------
__device__ __forceinline__ uint32_t packbf2(float a, float b) {
    __nv_bfloat162 t = __floats2bfloat162_rn(a, b);
    return *(uint32_t*)&t;
}
__device__ __forceinline__ float2 unpackbf2(uint32_t w) {
    __nv_bfloat162 t = *(__nv_bfloat162*)&w;
    return __bfloat1622float2(t);
}
__device__ __forceinline__ void split2(float a, float b, uint32_t& hw, uint32_t& lw) {
    __nv_bfloat16 ha = __float2bfloat16(a), hb = __float2bfloat16(b);
    float la = a - __bfloat162float(ha), lb = b - __bfloat162float(hb);
    __nv_bfloat162 h; h.x = ha; h.y = hb;
    hw = *(uint32_t*)&h;
    lw = packbf2(la, lb);
}
__device__ __forceinline__ void cpab(void* dst_smem, const void* src) {
    unsigned s = (unsigned)__cvta_generic_to_shared(dst_smem);
    asm volatile("cp.async.cg.shared.global [%0], [%1], 16;" :: "r"(s), "l"(src));
}
#define CP_COMMIT asm volatile("cp.async.commit_group;")
#define CP_WAIT1  asm volatile("cp.async.wait_group 1;")
#define CP_WAIT0  asm volatile("cp.async.wait_group 0;")

#define MMA(cd, a0, a1, a2, a3, b0, b1) \
    asm volatile("mma.sync.aligned.m16n8k16.row.col.f32.bf16.bf16.f32 " \
        "{%0,%1,%2,%3}, {%4,%5,%6,%7}, {%8,%9}, {%0,%1,%2,%3};" \
        : "+f"((cd)[0]), "+f"((cd)[1]), "+f"((cd)[2]), "+f"((cd)[3]) \
        : "r"(a0), "r"(a1), "r"(a2), "r"(a3), "r"(b0), "r"(b1))

// stage one k-chunk (32 k's, 64B per row) of a [256][K] bf16 image into smem [256][BPAD]
__device__ __forceinline__ void stage_chunk(char* dst, const __nv_bfloat16* img,
                                            int K, int k0, int tid) {
    #pragma unroll
    for (int i = tid; i < 1024; i += NTHR) {
        int n = i >> 2, p = i & 3;
        cpab(dst + n*80 + p*16, (const char*)(img + (size_t)n*K + k0) + p*16);
    }
}
// load A frags (2 m-tiles) from bf16 image with APAD stride
__device__ __forceinline__ void loadA(uint32_t A[2][4], const __nv_bfloat16* base,
                                      int mrow0, int kb, int g, int t) {
    #pragma unroll
    for (int mt = 0; mt < 2; mt++) {
        const __nv_bfloat16* ar = base + (size_t)(mrow0 + mt*16 + g)*APAD + kb + 2*t;
        A[mt][0] = *(const uint32_t*)ar;
        A[mt][1] = *(const uint32_t*)(ar + 8*APAD);
        A[mt][2] = *(const uint32_t*)(ar + 8);
        A[mt][3] = *(const uint32_t*)(ar + 8*APAD + 8);
    }
}

// ---------------- preprocessing ----------------
__global__ void prep_scale(const float* __restrict__ gs) {
    __shared__ float red[256];
    int l = blockIdx.x, d = threadIdx.x;
    float x  = 0.5f * gs[l*Dd + d];
    float sp = (x > 20.f) ? x : log1pf(expf(x));
    float s  = 0.2f * sp;
    g_scale[l*Dd + d] = s;
    red[d] = logf(s);
    __syncthreads();
    #pragma unroll
    for (int o = 128; o; o >>= 1) { if (d < o) red[d] += red[d + o]; __syncthreads(); }
    if (d == 0) g_sumlog[l] = red[0];
}
__global__ void prep_w1t(const float* __restrict__ W1) {
    int idx = blockIdx.x * 256 + threadIdx.x;      // Lc*256*128
    int k = idx & 127, n = (idx >> 7) & 255, l = idx >> 15;
    g_w1t[((size_t)l*256 + n)*128 + k] = __float2bfloat16(W1[((size_t)l*128 + k)*256 + n]);
}
__global__ void prep_w2t(const float* __restrict__ W2) {
    int idx = blockIdx.x * 256 + threadIdx.x;      // Lc*256*256
    int k = idx & 255, n = (idx >> 8) & 255, l = idx >> 16;
    g_w2t[((size_t)l*256 + n)*256 + k] = __float2bfloat16(W2[((size_t)l*256 + k)*256 + n]);
}
__global__ void prep_pt(const float* __restrict__ P) {
    int idx = blockIdx.x * 256 + threadIdx.x;      // Lc*256*256
    int k = idx & 255, n = (idx >> 8) & 255, l = idx >> 16;
    float v = P[((size_t)l*256 + n)*256 + k];      // B^T[n][k] = P[n][k]
    __nv_bfloat16 hi = __float2bfloat16(v);
    size_t o = ((size_t)l*256 + n)*256 + k;
    g_ph[o] = hi;
    g_pl[o] = __float2bfloat16(v - __bfloat162float(hi));
}
__global__ void prep_wht(const float* __restrict__ Wh1) {
    int idx = blockIdx.x * 256 + threadIdx.x;      // 256*256
    int k = idx & 255, n = idx >> 8;
    float v = Wh1[(size_t)k*256 + n];
    __nv_bfloat16 hi = __float2bfloat16(v);
    size_t o = (size_t)n*256 + k;
    g_whh[o] = hi;
    g_whl[o] = __float2bfloat16(v - __bfloat162float(hi));
}

// ---------------- fused flow layer (mma.sync bf16) ----------------
__global__ void __launch_bounds__(NTHR, 1) flow_hmma(
    const float* __restrict__ xin, float* __restrict__ xout, int layer,
    const float* __restrict__ b1, const float* __restrict__ b2,
    const float* __restrict__ go)
{
    extern __shared__ char smem[];
    __nv_bfloat16* xhi = (__nv_bfloat16*)(smem + OFF_XHI);
    __nv_bfloat16* xlo = (__nv_bfloat16*)(smem + OFF_XLO);
    __nv_bfloat16* hb  = (__nv_bfloat16*)(smem + OFF_HB);
    char* bw = smem + OFF_BW;

    const int tid = threadIdx.x, lane = tid & 31, wid = tid >> 5;
    const int warpM = wid >> 2, warpN = wid & 3;
    const int g = lane >> 2, t = lane & 3;
    const int mrow0 = warpM * 32;

    const float* bb1 = b1 + layer*Dd;
    const float* bb2 = b2 + layer*Dd;
    const float* sc  = g_scale + layer*Dd;
    const float* oo  = go + layer*Dd;

    // ---- load + split input into xhi/xlo images ----
    {
        const float4* src = (const float4*)(xin + (size_t)blockIdx.x * MROW * Dd);
        for (int i = tid; i < MROW * Dd / 4; i += NTHR) {
            int r = i >> 6, c = (i & 63) * 4;
            float4 v = src[i];
            uint32_t h0, l0, h1, l1;
            split2(v.x, v.y, h0, l0);
            split2(v.z, v.w, h1, l1);
            *(uint32_t*)(xhi + (size_t)r*APAD + c)     = h0;
            *(uint32_t*)(xhi + (size_t)r*APAD + c + 2) = h1;
            *(uint32_t*)(xlo + (size_t)r*APAD + c)     = l0;
            *(uint32_t*)(xlo + (size_t)r*APAD + c + 2) = l1;
        }
    }
    __syncthreads();

    float cacc[2][8][4];

    // ================= GEMM1: H = relu(x1_hi @ W1 + b1), K=128 =================
    {
        #pragma unroll
        for (int mt = 0; mt < 2; mt++)
            #pragma unroll
            for (int nt = 0; nt < 8; nt++)
                #pragma unroll
                for (int q = 0; q < 4; q++) cacc[mt][nt][q] = 0.f;

        const __nv_bfloat16* img = g_w1t + (size_t)layer*256*128;
        stage_chunk(bw, img, 128, 0, tid); CP_COMMIT;
        for (int ch = 0; ch < 4; ch++) {
            char* cur = bw + (ch & 1) * 40960;
            if (ch + 1 < 4) {
                stage_chunk(bw + ((ch + 1) & 1) * 40960, img, 128, (ch + 1) * 32, tid);
                CP_COMMIT; CP_WAIT1;
            } else CP_WAIT0;
            __syncthreads();
            #pragma unroll
            for (int ks = 0; ks < 32; ks += 16) {
                uint32_t A[2][4];
                loadA(A, xhi, mrow0, ch*32 + ks, g, t);
                #pragma unroll
                for (int nt = 0; nt < 8; nt++) {
                    int n = warpN*64 + nt*8 + g;
                    const char* br = cur + n*80 + (ks + 2*t)*2;
                    uint32_t b0v = *(const uint32_t*)br;
                    uint32_t b1v = *(const uint32_t*)(br + 16);
                    MMA(cacc[0][nt], A[0][0], A[0][1], A[0][2], A[0][3], b0v, b1v);
                    MMA(cacc[1][nt], A[1][0], A[1][1], A[1][2], A[1][3], b0v, b1v);
                }
            }
            __syncthreads();
        }
        // epilogue: relu + bias -> hb bf16
        #pragma unroll
        for (int mt = 0; mt < 2; mt++) {
            int r = mrow0 + mt*16 + g;
            #pragma unroll
            for (int nt = 0; nt < 8; nt++) {
                int c = warpN*64 + nt*8 + 2*t;
                float* cf = cacc[mt][nt];
                float w0 = fmaxf(cf[0] + __ldg(bb1 + c),     0.f);
                float w1 = fmaxf(cf[1] + __ldg(bb1 + c + 1), 0.f);
                float w2 = fmaxf(cf[2] + __ldg(bb1 + c),     0.f);
                float w3 = fmaxf(cf[3] + __ldg(bb1 + c + 1), 0.f);
                *(uint32_t*)(hb + (size_t)r*APAD + c)       = packbf2(w0, w1);
                *(uint32_t*)(hb + (size_t)(r+8)*APAD + c)   = packbf2(w2, w3);
            }
        }
        __syncthreads();
    }

    // ================= GEMM2: A2 = H @ W2, K=256 =================
    {
        #pragma unroll
        for (int mt = 0; mt < 2; mt++)
            #pragma unroll
            for (int nt = 0; nt < 8; nt++)
                #pragma unroll
                for (int q = 0; q < 4; q++) cacc[mt][nt][q] = 0.f;

        const __nv_bfloat16* img = g_w2t + (size_t)layer*256*256;
        stage_chunk(bw, img, 256, 0, tid); CP_COMMIT;
        for (int ch = 0; ch < 8; ch++) {
            char* cur = bw + (ch & 1) * 40960;
            if (ch + 1 < 8) {
                stage_chunk(bw + ((ch + 1) & 1) * 40960, img, 256, (ch + 1) * 32, tid);
                CP_COMMIT; CP_WAIT1;
            } else CP_WAIT0;
            __syncthreads();
            #pragma unroll
            for (int ks = 0; ks < 32; ks += 16) {
                uint32_t A[2][4];
                loadA(A, hb, mrow0, ch*32 + ks, g, t);
                #pragma unroll
                for (int nt = 0; nt < 8; nt++) {
                    int n = warpN*64 + nt*8 + g;
                    const char* br = cur + n*80 + (ks + 2*t)*2;
                    uint32_t b0v = *(const uint32_t*)br;
                    uint32_t b1v = *(const uint32_t*)(br + 16);
                    MMA(cacc[0][nt], A[0][0], A[0][1], A[0][2], A[0][3], b0v, b1v);
                    MMA(cacc[1][nt], A[1][0], A[1][1], A[1][2], A[1][3], b0v, b1v);
                }
            }
            __syncthreads();
        }
    }

    // ================= coupling epilogue =================
    if (warpN < 2) {
        // cols 0..127: s = 1.9*tanh(0.1*(a1)) -> hb; x1 actnorm in place
        #pragma unroll
        for (int mt = 0; mt < 2; mt++) {
            #pragma unroll
            for (int half = 0; half < 2; half++) {
                int r = mrow0 + mt*16 + g + half*8;
                #pragma unroll
                for (int nt = 0; nt < 8; nt++) {
                    int c = warpN*64 + nt*8 + 2*t;
                    float* cf = cacc[mt][nt];
                    float a0 = cf[half*2 + 0] + __ldg(bb2 + c);
                    float a1 = cf[half*2 + 1] + __ldg(bb2 + c + 1);
                    float s0 = 1.9f * tanhf(0.1f * a0);
                    float s1 = 1.9f * tanhf(0.1f * a1);
                    *(uint32_t*)(hb + (size_t)r*APAD + c) = packbf2(s0, s1);
                    // x1 actnorm
                    size_t ao = (size_t)r*APAD + c;
                    float2 hv = unpackbf2(*(uint32_t*)(xhi + ao));
                    float2 lv = unpackbf2(*(uint32_t*)(xlo + ao));
                    float n0 = (hv.x + lv.x) * __ldg(sc + c)     + __ldg(oo + c);
                    float n1 = (hv.y + lv.y) * __ldg(sc + c + 1) + __ldg(oo + c + 1);
                    uint32_t hw, lw; split2(n0, n1, hw, lw);
                    *(uint32_t*)(xhi + ao) = hw;
                    *(uint32_t*)(xlo + ao) = lw;
                }
            }
        }
    }
    __syncthreads();
    if (warpN >= 2) {
        // cols 128..255: x2' = x2*exp(s) + a2, then actnorm
        #pragma unroll
        for (int mt = 0; mt < 2; mt++) {
            #pragma unroll
            for (int half = 0; half < 2; half++) {
                int r = mrow0 + mt*16 + g + half*8;
                #pragma unroll
                for (int nt = 0; nt < 8; nt++) {
                    int c = warpN*64 + nt*8 + 2*t;
                    float* cf = cacc[mt][nt];
                    float a20 = 0.1f * (cf[half*2 + 0] + __ldg(bb2 + c));
                    float a21 = 0.1f * (cf[half*2 + 1] + __ldg(bb2 + c + 1));
                    float2 sv = unpackbf2(*(uint32_t*)(hb + (size_t)r*APAD + (c - 128)));
                    size_t ao = (size_t)r*APAD + c;
                    float2 hv = unpackbf2(*(uint32_t*)(xhi + ao));
                    float2 lv = unpackbf2(*(uint32_t*)(xlo + ao));
                    float v0 = (hv.x + lv.x) * expf(sv.x) + a20;
                    float v1 = (hv.y + lv.y) * expf(sv.y) + a21;
                    float n0 = v0 * __ldg(sc + c)     + __ldg(oo + c);
                    float n1 = v1 * __ldg(sc + c + 1) + __ldg(oo + c + 1);
                    uint32_t hw, lw; split2(n0, n1, hw, lw);
                    *(uint32_t*)(xhi + ao) = hw;
                    *(uint32_t*)(xlo + ao) = lw;
                }
            }
        }
    } else if (tid < MROW) {
        // logdet row sums from s (bf16) in hb cols 0..127
        float rs = 0.f;
        #pragma unroll 8
        for (int k2 = 0; k2 < 64; k2++) {
            float2 p = unpackbf2(*(uint32_t*)(hb + (size_t)tid*APAD + 2*k2));
            rs += p.x + p.y;
        }
        int grow = blockIdx.x * MROW + tid;
        float prev = layer ? g_ld[grow] : 0.f;
        g_ld[grow] = prev + rs + g_sumlog[layer];
    }

    // ================= GEMM3: XO = Xc @ P^T, 3-term split, K=256 =================
    {
        #pragma unroll
        for (int mt = 0; mt < 2; mt++)
            #pragma unroll
            for (int nt = 0; nt < 8; nt++)
                #pragma unroll
                for (int q = 0; q < 4; q++) cacc[mt][nt][q] = 0.f;

        const __nv_bfloat16* ih = g_ph + (size_t)layer*256*256;
        const __nv_bfloat16* il = g_pl + (size_t)layer*256*256;
        stage_chunk(bw,         ih, 256, 0, tid);
        stage_chunk(bw + 20480, il, 256, 0, tid); CP_COMMIT;
        for (int ch = 0; ch < 8; ch++) {
            char* cur = bw + (ch & 1) * 40960;
            if (ch + 1 < 8) {
                char* nxt = bw + ((ch + 1) & 1) * 40960;
                stage_chunk(nxt,         ih, 256, (ch + 1) * 32, tid);
                stage_chunk(nxt + 20480, il, 256, (ch + 1) * 32, tid);
                CP_COMMIT; CP_WAIT1;
            } else CP_WAIT0;
            __syncthreads();
            #pragma unroll
            for (int ks = 0; ks < 32; ks += 16) {
                uint32_t Ah[2][4], Al[2][4];
                loadA(Ah, xhi, mrow0, ch*32 + ks, g, t);
                loadA(Al, xlo, mrow0, ch*32 + ks, g, t);
                #pragma unroll
                for (int nt = 0; nt < 8; nt++) {
                    int n = warpN*64 + nt*8 + g;
                    const char* brh = cur + n*80 + (ks + 2*t)*2;
                    const char* brl = brh + 20480;
                    uint32_t bh0 = *(const uint32_t*)brh;
                    uint32_t bh1 = *(const uint32_t*)(brh + 16);
                    uint32_t bl0 = *(const uint32_t*)brl;
                    uint32_t bl1 = *(const uint32_t*)(brl + 16);
                    #pragma unroll
                    for (int mt = 0; mt < 2; mt++) {
                        MMA(cacc[mt][nt], Ah[mt][0], Ah[mt][1], Ah[mt][2], Ah[mt][3], bh0, bh1);
                        MMA(cacc[mt][nt], Al[mt][0], Al[mt][1], Al[mt][2], Al[mt][3], bh0, bh1);
                        MMA(cacc[mt][nt], Ah[mt][0], Ah[mt][1], Ah[mt][2], Ah[mt][3], bl0, bl1);
                    }
                }
            }
            __syncthreads();
        }
        // write fp32 output
        #pragma unroll
        for (int mt = 0; mt < 2; mt++) {
            #pragma unroll
            for (int half = 0; half < 2; half++) {
                int r = blockIdx.x * MROW + mrow0 + mt*16 + g + half*8;
                #pragma unroll
                for (int nt = 0; nt < 8; nt++) {
                    int c = warpN*64 + nt*8 + 2*t;
                    float* cf = cacc[mt][nt];
                    *(float2*)(xout + (size_t)r*Dd + c) =
                        make_float2(cf[half*2 + 0], cf[half*2 + 1]);
                }
            }
        }
    }
}

// ---------------- head: h = z@Wh1 + bh1 (3-term) + BN partials ----------------
__global__ void __launch_bounds__(NTHR, 1) head_hmma(
    const float* __restrict__ z, float* __restrict__ h,
    const float* __restrict__ bh1)
{
    extern __shared__ char smem[];
    __nv_bfloat16* xhi = (__nv_bfloat16*)(smem + OFF_XHI);
    __nv_bfloat16* xlo = (__nv_bfloat16*)(smem + OFF_XLO);
    char* bw = smem + OFF_BW;

    const int tid = threadIdx.x, lane = tid & 31, wid = tid >> 5;
    const int warpM = wid >> 2, warpN = wid & 3;
    const int g = lane >> 2, t = lane & 3;
    const int mrow0 = warpM * 32;

    {
        const float4* src = (const float4*)(z + (size_t)blockIdx.x * MROW * Dd);
        for (int i = tid; i < MROW * Dd / 4; i += NTHR) {
            int r = i >> 6, c = (i & 63) * 4;
            float4 v = src[i];
            uint32_t h0, l0, h1, l1;
            split2(v.x, v.y, h0, l0);
            split2(v.z, v.w, h1, l1);
            *(uint32_t*)(xhi + (size_t)r*APAD + c)     = h0;
            *(uint32_t*)(xhi + (size_t)r*APAD + c + 2) = h1;
            *(uint32_t*)(xlo + (size_t)r*APAD + c)     = l0;
            *(uint32_t*)(xlo + (size_t)r*APAD + c + 2) = l1;
        }
    }
    __syncthreads();

    float cacc[2][8][4];
    #pragma unroll
    for (int mt = 0; mt < 2; mt++)
        #pragma unroll
        for (int nt = 0; nt < 8; nt++)
            #pragma unroll
            for (int q = 0; q < 4; q++) cacc[mt][nt][q] = 0.f;

    stage_chunk(bw,         g_whh, 256, 0, tid);
    stage_chunk(bw + 20480, g_whl, 256, 0, tid); CP_COMMIT;
    for (int ch = 0; ch < 8; ch++) {
        char* cur = bw + (ch & 1) * 40960;
        if (ch + 1 < 8) {
            char* nxt = bw + ((ch + 1) & 1) * 40960;
            stage_chunk(nxt,         g_whh, 256, (ch + 1) * 32, tid);
            stage_chunk(nxt + 20480, g_whl, 256, (ch + 1) * 32, tid);
            CP_COMMIT; CP_WAIT1;
        } else CP_WAIT0;
        __syncthreads();
        #pragma unroll
        for (int ks = 0; ks < 32; ks += 16) {
            uint32_t Ah[2][4], Al[2][4];
            loadA(Ah, xhi, mrow0, ch*32 + ks, g, t);
            loadA(Al, xlo, mrow0, ch*32 + ks, g, t);
            #pragma unroll
            for (int nt = 0; nt < 8; nt++) {
                int n = warpN*64 + nt*8 + g;
                const char* brh = cur + n*80 + (ks + 2*t)*2;
                const char* brl = brh + 20480;
                uint32_t bh0 = *(const uint32_t*)brh;
                uint32_t bh1 = *(const uint32_t*)(brh + 16);
                uint32_t bl0 = *(const uint32_t*)brl;
                uint32_t bl1 = *(const uint32_t*)(brl + 16);
                #pragma unroll
                for (int mt = 0; mt < 2; mt++) {
                    MMA(cacc[mt][nt], Ah[mt][0], Ah[mt][1], Ah[mt][2], Ah[mt][3], bh0, bh1);
                    MMA(cacc[mt][nt], Al[mt][0], Al[mt][1], Al[mt][2], Al[mt][3], bh0, bh1);
                    MMA(cacc[mt][nt], Ah[mt][0], Ah[mt][1], Ah[mt][2], Ah[mt][3], bl0, bl1);
                }
            }
        }
        __syncthreads();
    }

    // epilogue: +bias, gmem write, stage fp32 for BN partials
    float* stg = (float*)smem;    // [64][APAD] fp32 overlay (xhi/xlo regions, now free)
    __syncthreads();
    #pragma unroll
    for (int mt = 0; mt < 2; mt++) {
        #pragma unroll
        for (int half = 0; half < 2; half++) {
            int rl = mrow0 + mt*16 + g + half*8;
            int r  = blockIdx.x * MROW + rl;
            #pragma unroll
            for (int nt = 0; nt < 8; nt++) {
                int c = warpN*64 + nt*8 + 2*t;
                float* cf = cacc[mt][nt];
                float v0 = cf[half*2 + 0] + __ldg(bh1 + c);
                float v1 = cf[half*2 + 1] + __ldg(bh1 + c + 1);
                *(float2*)(h + (size_t)r*Dd + c) = make_float2(v0, v1);
                stg[(size_t)rl*APAD + c]     = v0;
                stg[(size_t)rl*APAD + c + 1] = v1;
            }
        }
    }
    __syncthreads();
    // column partial sums (256 threads = 256 cols)
    {
        float s = 0.f, q = 0.f;
        #pragma unroll 4
        for (int r = 0; r < MROW; r++) {
            float v = stg[(size_t)r*APAD + tid];
            s += v; q += v * v;
        }
        g_part[(size_t)blockIdx.x*2*Dd + tid]      = s;
        g_part[(size_t)blockIdx.x*2*Dd + Dd + tid] = q;
    }
}

// ---------------- BN stats fold ----------------
__global__ void stats_kernel(const float* __restrict__ gamma, const float* __restrict__ beta) {
    int c = threadIdx.x;
    float s0=0.f,s1=0.f,s2=0.f,s3=0.f, q0=0.f,q1=0.f,q2=0.f,q3=0.f;
    for (int i = 0; i < NBLK; i += 4) {
        s0 += g_part[(size_t)(i+0)*2*Dd + c];   q0 += g_part[(size_t)(i+0)*2*Dd + Dd + c];
        s1 += g_part[(size_t)(i+1)*2*Dd + c];   q1 += g_part[(size_t)(i+1)*2*Dd + Dd + c];
        s2 += g_part[(size_t)(i+2)*2*Dd + c];   q2 += g_part[(size_t)(i+2)*2*Dd + Dd + c];
        s3 += g_part[(size_t)(i+3)*2*Dd + c];   q3 += g_part[(size_t)(i+3)*2*Dd + Dd + c];
    }
    float s = (s0+s1)+(s2+s3), q = (q0+q1)+(q2+q3);
    float mu  = s * (1.f/Bsz);
    float var = q * (1.f/Bsz) - mu*mu;
    float a = gamma[c] * rsqrtf(var + BN_EPS);
    g_stats[c]      = a;
    g_stats[Dd + c] = beta[c] - mu * a;
}

// ---------------- log_px ----------------
__global__ void logpx_kernel(const float* __restrict__ z, float* __restrict__ out) {
    int warp = threadIdx.x >> 5, lane = threadIdx.x & 31;
    size_t row = (size_t)blockIdx.x * 8 + warp;
    const float4* zr = (const float4*)(z + row*Dd);
    float4 v0 = zr[lane*2], v1 = zr[lane*2 + 1];
    float ss = v0.x*v0.x + v0.y*v0.y + v0.z*v0.z + v0.w*v0.w
             + v1.x*v1.x + v1.y*v1.y + v1.z*v1.z + v1.w*v1.w;
    #pragma unroll
    for (int o = 16; o; o >>= 1) ss += __shfl_down_sync(0xffffffffu, ss, o);
    if (lane == 0)
        out[row] = (DGCONST - 0.5f*ss + g_ld[row]) * (1.0f/Dd);
}

// ---------------- logits ----------------
__global__ void __launch_bounds__(256) logits_kernel(
    const float* __restrict__ h, const float* __restrict__ Wh2,
    const float* __restrict__ bh2, float* __restrict__ out)
{
    __shared__ float w2s[Dd*NCc];
    __shared__ float As[Dd], Bs[Dd];
    int tid = threadIdx.x;
    for (int i = tid; i < Dd*NCc; i += 256) w2s[i] = Wh2[i];
    if (tid < Dd) { As[tid] = g_stats[tid]; Bs[tid] = g_stats[Dd + tid]; }
    __syncthreads();

    int warp = tid >> 5, lane = tid & 31;
    size_t row = (size_t)blockIdx.x * 8 + warp;
    const float4* hr = (const float4*)(h + row*Dd);
    float4 v0 = hr[lane*2], v1 = hr[lane*2 + 1];
    int k0 = lane * 8;
    float hn[8];
    hn[0] = fmaxf(v0.x*As[k0+0] + Bs[k0+0], 0.f);
    hn[1] = fmaxf(v0.y*As[k0+1] + Bs[k0+1], 0.f);
    hn[2] = fmaxf(v0.z*As[k0+2] + Bs[k0+2], 0.f);
    hn[3] = fmaxf(v0.w*As[k0+3] + Bs[k0+3], 0.f);
    hn[4] = fmaxf(v1.x*As[k0+4] + Bs[k0+4], 0.f);
    hn[5] = fmaxf(v1.y*As[k0+5] + Bs[k0+5], 0.f);
    hn[6] = fmaxf(v1.z*As[k0+6] + Bs[k0+6], 0.f);
    hn[7] = fmaxf(v1.w*As[k0+7] + Bs[k0+7], 0.f);

    float acc[NCc];
    #pragma unroll
    for (int c = 0; c < NCc; c++) acc[c] = 0.f;
    #pragma unroll
    for (int kk = 0; kk < 8; kk++) {
        float x = hn[kk];
        const float* wr = &w2s[(k0+kk)*NCc];
        #pragma unroll
        for (int c = 0; c < NCc; c++) acc[c] += x * wr[c];
    }
    #pragma unroll
    for (int c = 0; c < NCc; c++) {
        #pragma unroll
        for (int o = 16; o; o >>= 1) acc[c] += __shfl_down_sync(0xffffffffu, acc[c], o);
    }
    if (lane == 0) {
        #pragma unroll
        for (int c = 0; c < NCc; c++) out[row*NCc + c] = acc[c] + __ldg(bh2 + c);
    }
}

// ---------------- launch ----------------
extern "C" void kernel_launch(void* const* d_in, const int* in_sizes, int n_in,
                              void* d_out, int out_size)
{
    const float* feat  = (const float*)d_in[0];
    const float* W1    = (const float*)d_in[1];
    const float* b1    = (const float*)d_in[2];
    const float* W2    = (const float*)d_in[3];
    const float* b2    = (const float*)d_in[4];
    const float* gs    = (const float*)d_in[5];
    const float* go    = (const float*)d_in[6];
    const float* P     = (const float*)d_in[7];
    const float* Wh1   = (const float*)d_in[8];
    const float* bh1   = (const float*)d_in[9];
    const float* gamma = (const float*)d_in[10];
    const float* beta  = (const float*)d_in[11];
    const float* Wh2   = (const float*)d_in[12];
    const float* bh2   = (const float*)d_in[13];
    float* out = (float*)d_out;

    cudaFuncSetAttribute(flow_hmma, cudaFuncAttributeMaxDynamicSharedMemorySize, SMEMSZ);
    cudaFuncSetAttribute(head_hmma, cudaFuncAttributeMaxDynamicSharedMemorySize, SMEMSZ);

    float *bufA = nullptr, *bufB = nullptr;
    cudaGetSymbolAddress((void**)&bufA, g_bufA);
    cudaGetSymbolAddress((void**)&bufB, g_bufB);

    prep_scale<<<Lc, 256>>>(gs);
    prep_w1t<<<(Lc*256*128)/256, 256>>>(W1);
    prep_w2t<<<(Lc*256*256)/256, 256>>>(W2);
    prep_pt <<<(Lc*256*256)/256, 256>>>(P);
    prep_wht<<<(256*256)/256, 256>>>(Wh1);

    const float* cin = feat;
    for (int l = 0; l < Lc; l++) {
        float* cout = (l & 1) ? bufB : bufA;
        flow_hmma<<<NBLK, NTHR, SMEMSZ>>>(cin, cout, l, b1, b2, go);
        cin = cout;
    }
    // z in bufB after layer 7
    head_hmma<<<NBLK, NTHR, SMEMSZ>>>(bufB, bufA, bh1);
    stats_kernel<<<1, 256>>>(gamma, beta);
    logpx_kernel<<<Bsz/8, 256>>>(bufB, out);
    logits_kernel<<<Bsz/8, 256>>>(bufA, Wh2, bh2, out + Bsz);
}

// round 5
// speedup vs baseline: 3.3817x; 1.3096x over previous
#include <cuda_runtime.h>
#include <cuda_bf16.h>
#include <math.h>
#include <stdint.h>

// ---------------- problem constants ----------------
#define Bsz   131072
#define Dd    256
#define Lc    8
#define NCc   10
#define BN_EPS 1e-5f
#define DGCONST -235.24826450039622f   // D * GCONST

#define MROW  64
#define NTHR  512
#define NBLK  (Bsz/MROW)      // 2048 CTAs
#define APAD  264             // bf16 elems per A row (stride 528B)
#define BPAD  40              // bf16 elems per B row (stride 80B)

// smem byte offsets
#define OFF_XHI 0
#define OFF_XLO 33792
#define OFF_HB  67584
#define OFF_BW  101376        // 2 buffers x 40960 (each: [hi 20480][lo 20480])
#define SMEMSZ  183296

// ---------------- static device scratch ----------------
__device__ float g_bufA[(size_t)Bsz*Dd];
__device__ float g_bufB[(size_t)Bsz*Dd];
__device__ float g_ld[Bsz];
__device__ float g_scale[Lc*Dd];
__device__ float g_sumlog[Lc];
__device__ float g_part[(size_t)NBLK*2*Dd];
__device__ float g_stats[2*Dd];
// bf16 weight images, [n][k] row-major (k contiguous)
__device__ __nv_bfloat16 g_w1t[(size_t)Lc*256*128];
__device__ __nv_bfloat16 g_w2t[(size_t)Lc*256*256];
__device__ __nv_bfloat16 g_ph [(size_t)Lc*256*256];
__device__ __nv_bfloat16 g_pl [(size_t)Lc*256*256];
__device__ __nv_bfloat16 g_whh[(size_t)256*256];
__device__ __nv_bfloat16 g_whl[(size_t)256*256];

// ---------------- helpers ----------------
__device__ __forceinline__ uint32_t packbf2(float a, float b) {
    __nv_bfloat162 t = __floats2bfloat162_rn(a, b);
    return *(uint32_t*)&t;
}
__device__ __forceinline__ float2 unpackbf2(uint32_t w) {
    __nv_bfloat162 t = *(__nv_bfloat162*)&w;
    return __bfloat1622float2(t);
}
__device__ __forceinline__ void split2(float a, float b, uint32_t& hw, uint32_t& lw) {
    __nv_bfloat16 ha = __float2bfloat16(a), hb = __float2bfloat16(b);
    float la = a - __bfloat162float(ha), lb = b - __bfloat162float(hb);
    __nv_bfloat162 h; h.x = ha; h.y = hb;
    hw = *(uint32_t*)&h;
    lw = packbf2(la, lb);
}
__device__ __forceinline__ float fast_tanh_scaled(float a) {
    // 1.9 * tanh(0.1*a)
    float e = __expf(-0.2f * a);
    return 1.9f * __fdividef(1.f - e, 1.f + e);
}
__device__ __forceinline__ void cpab(void* dst_smem, const void* src) {
    unsigned s = (unsigned)__cvta_generic_to_shared(dst_smem);
    asm volatile("cp.async.cg.shared.global [%0], [%1], 16;" :: "r"(s), "l"(src));
}
#define CP_COMMIT asm volatile("cp.async.commit_group;")
#define CP_WAIT1  asm volatile("cp.async.wait_group 1;")
#define CP_WAIT0  asm volatile("cp.async.wait_group 0;")

#define MMA(cd, a0, a1, a2, a3, b0, b1) \
    asm volatile("mma.sync.aligned.m16n8k16.row.col.f32.bf16.bf16.f32 " \
        "{%0,%1,%2,%3}, {%4,%5,%6,%7}, {%8,%9}, {%0,%1,%2,%3};" \
        : "+f"((cd)[0]), "+f"((cd)[1]), "+f"((cd)[2]), "+f"((cd)[3]) \
        : "r"(a0), "r"(a1), "r"(a2), "r"(a3), "r"(b0), "r"(b1))

#define LDSM4(r0, r1, r2, r3, addr) \
    asm volatile("ldmatrix.sync.aligned.m8n8.x4.shared.b16 {%0,%1,%2,%3}, [%4];" \
        : "=r"(r0), "=r"(r1), "=r"(r2), "=r"(r3) : "r"(addr))

// stage one k-chunk (32 k's, 64B/row) of a [256][K] bf16 image into smem [256][BPAD]
__device__ __forceinline__ void stage_chunk(char* dst, const __nv_bfloat16* img,
                                            int K, int k0, int tid) {
    #pragma unroll
    for (int i = tid; i < 1024; i += NTHR) {
        int n = i >> 2, p = i & 3;
        cpab(dst + n*80 + p*16, (const char*)(img + (size_t)n*K + k0) + p*16);
    }
}

// ---------------- preprocessing ----------------
__global__ void prep_scale(const float* __restrict__ gs) {
    __shared__ float red[256];
    int l = blockIdx.x, d = threadIdx.x;
    float x  = 0.5f * gs[l*Dd + d];
    float sp = (x > 20.f) ? x : log1pf(expf(x));
    float s  = 0.2f * sp;
    g_scale[l*Dd + d] = s;
    red[d] = logf(s);
    __syncthreads();
    #pragma unroll
    for (int o = 128; o; o >>= 1) { if (d < o) red[d] += red[d + o]; __syncthreads(); }
    if (d == 0) g_sumlog[l] = red[0];
}
__global__ void prep_w1t(const float* __restrict__ W1) {
    int idx = blockIdx.x * 256 + threadIdx.x;
    int k = idx & 127, n = (idx >> 7) & 255, l = idx >> 15;
    g_w1t[((size_t)l*256 + n)*128 + k] = __float2bfloat16(W1[((size_t)l*128 + k)*256 + n]);
}
__global__ void prep_w2t(const float* __restrict__ W2) {
    int idx = blockIdx.x * 256 + threadIdx.x;
    int k = idx & 255, n = (idx >> 8) & 255, l = idx >> 16;
    g_w2t[((size_t)l*256 + n)*256 + k] = __float2bfloat16(W2[((size_t)l*256 + k)*256 + n]);
}
__global__ void prep_pt(const float* __restrict__ P) {
    int idx = blockIdx.x * 256 + threadIdx.x;
    int k = idx & 255, n = (idx >> 8) & 255, l = idx >> 16;
    float v = P[((size_t)l*256 + n)*256 + k];
    __nv_bfloat16 hi = __float2bfloat16(v);
    size_t o = ((size_t)l*256 + n)*256 + k;
    g_ph[o] = hi;
    g_pl[o] = __float2bfloat16(v - __bfloat162float(hi));
}
__global__ void prep_wht(const float* __restrict__ Wh1) {
    int idx = blockIdx.x * 256 + threadIdx.x;
    int k = idx & 255, n = idx >> 8;
    float v = Wh1[(size_t)k*256 + n];
    __nv_bfloat16 hi = __float2bfloat16(v);
    size_t o = (size_t)n*256 + k;
    g_whh[o] = hi;
    g_whl[o] = __float2bfloat16(v - __bfloat162float(hi));
}

// ---------------- fused flow layer ----------------
__global__ void __launch_bounds__(NTHR, 1) flow_hmma(
    const float* __restrict__ xin, float* __restrict__ xout, int layer,
    const float* __restrict__ b1, const float* __restrict__ b2,
    const float* __restrict__ go)
{
    extern __shared__ char smem[];
    __nv_bfloat16* xhi = (__nv_bfloat16*)(smem + OFF_XHI);
    __nv_bfloat16* xlo = (__nv_bfloat16*)(smem + OFF_XLO);
    __nv_bfloat16* hb  = (__nv_bfloat16*)(smem + OFF_HB);
    char* bw = smem + OFF_BW;
    const uint32_t smem_u = (uint32_t)__cvta_generic_to_shared(smem);
    const uint32_t XHI = smem_u + OFF_XHI, XLO = smem_u + OFF_XLO,
                   HBs = smem_u + OFF_HB,  BWs = smem_u + OFF_BW;

    const int tid = threadIdx.x, lane = tid & 31, wid = tid >> 5;
    const int warpM = wid >> 3, warpN = wid & 7;
    const int g = lane >> 2, t = lane & 3;
    const int mrow0 = warpM * 32;
    const int n0 = warpN * 32;
    // ldmatrix per-lane row offsets
    const uint32_t aoff = (uint32_t)((lane & 15) * 528 + ((lane >> 4) << 4));           // A: row lane&15, k +8 if lane>=16
    const uint32_t boff = (uint32_t)((((lane >> 4) << 3) + (lane & 7)) * 80 + (((lane >> 3) & 1) << 4));

    const float* bb1 = b1 + layer*Dd;
    const float* bb2 = b2 + layer*Dd;
    const float* sc  = g_scale + layer*Dd;
    const float* oo  = go + layer*Dd;

    // ---- load + split input ----
    {
        const float4* src = (const float4*)(xin + (size_t)blockIdx.x * MROW * Dd);
        #pragma unroll
        for (int i = tid; i < MROW * Dd / 4; i += NTHR) {
            int r = i >> 6, c = (i & 63) * 4;
            float4 v = src[i];
            uint32_t h0, l0, h1, l1;
            split2(v.x, v.y, h0, l0);
            split2(v.z, v.w, h1, l1);
            *(uint32_t*)(xhi + (size_t)r*APAD + c)     = h0;
            *(uint32_t*)(xhi + (size_t)r*APAD + c + 2) = h1;
            *(uint32_t*)(xlo + (size_t)r*APAD + c)     = l0;
            *(uint32_t*)(xlo + (size_t)r*APAD + c + 2) = l1;
        }
    }
    __syncthreads();

    float cacc[2][4][4];

    // ================= GEMM1: H = relu(x1_hi @ W1 + b1), K=128 =================
    {
        #pragma unroll
        for (int mt = 0; mt < 2; mt++)
            #pragma unroll
            for (int nt = 0; nt < 4; nt++)
                #pragma unroll
                for (int q = 0; q < 4; q++) cacc[mt][nt][q] = 0.f;

        const __nv_bfloat16* img = g_w1t + (size_t)layer*256*128;
        stage_chunk(bw, img, 128, 0, tid); CP_COMMIT;
        for (int ch = 0; ch < 4; ch++) {
            uint32_t cur = BWs + (uint32_t)((ch & 1) * 40960);
            if (ch + 1 < 4) {
                stage_chunk(bw + ((ch + 1) & 1) * 40960, img, 128, (ch + 1) * 32, tid);
                CP_COMMIT; CP_WAIT1;
            } else CP_WAIT0;
            __syncthreads();
            #pragma unroll
            for (int ks = 0; ks < 32; ks += 16) {
                uint32_t A[2][4], B[2][4];
                #pragma unroll
                for (int mt = 0; mt < 2; mt++)
                    LDSM4(A[mt][0], A[mt][1], A[mt][2], A[mt][3],
                          XHI + (uint32_t)((mrow0 + mt*16)*528 + (ch*32 + ks)*2) + aoff);
                #pragma unroll
                for (int p = 0; p < 2; p++)
                    LDSM4(B[p][0], B[p][1], B[p][2], B[p][3],
                          cur + (uint32_t)((n0 + p*16)*80 + ks*2) + boff);
                #pragma unroll
                for (int p = 0; p < 2; p++)
                    #pragma unroll
                    for (int q = 0; q < 2; q++) {
                        int nt = p*2 + q;
                        MMA(cacc[0][nt], A[0][0], A[0][1], A[0][2], A[0][3], B[p][q*2], B[p][q*2+1]);
                        MMA(cacc[1][nt], A[1][0], A[1][1], A[1][2], A[1][3], B[p][q*2], B[p][q*2+1]);
                    }
            }
            __syncthreads();
        }
        // epilogue: relu + bias -> hb
        #pragma unroll
        for (int nt = 0; nt < 4; nt++) {
            int c = n0 + nt*8 + 2*t;
            float be0 = __ldg(bb1 + c), be1 = __ldg(bb1 + c + 1);
            #pragma unroll
            for (int mt = 0; mt < 2; mt++) {
                int r = mrow0 + mt*16 + g;
                float* cf = cacc[mt][nt];
                *(uint32_t*)(hb + (size_t)r*APAD + c) =
                    packbf2(fmaxf(cf[0] + be0, 0.f), fmaxf(cf[1] + be1, 0.f));
                *(uint32_t*)(hb + (size_t)(r+8)*APAD + c) =
                    packbf2(fmaxf(cf[2] + be0, 0.f), fmaxf(cf[3] + be1, 0.f));
            }
        }
        __syncthreads();
    }

    // ================= GEMM2: A2 = H @ W2, K=256 =================
    {
        #pragma unroll
        for (int mt = 0; mt < 2; mt++)
            #pragma unroll
            for (int nt = 0; nt < 4; nt++)
                #pragma unroll
                for (int q = 0; q < 4; q++) cacc[mt][nt][q] = 0.f;

        const __nv_bfloat16* img = g_w2t + (size_t)layer*256*256;
        stage_chunk(bw, img, 256, 0, tid); CP_COMMIT;
        for (int ch = 0; ch < 8; ch++) {
            uint32_t cur = BWs + (uint32_t)((ch & 1) * 40960);
            if (ch + 1 < 8) {
                stage_chunk(bw + ((ch + 1) & 1) * 40960, img, 256, (ch + 1) * 32, tid);
                CP_COMMIT; CP_WAIT1;
            } else CP_WAIT0;
            __syncthreads();
            #pragma unroll
            for (int ks = 0; ks < 32; ks += 16) {
                uint32_t A[2][4], B[2][4];
                #pragma unroll
                for (int mt = 0; mt < 2; mt++)
                    LDSM4(A[mt][0], A[mt][1], A[mt][2], A[mt][3],
                          HBs + (uint32_t)((mrow0 + mt*16)*528 + (ch*32 + ks)*2) + aoff);
                #pragma unroll
                for (int p = 0; p < 2; p++)
                    LDSM4(B[p][0], B[p][1], B[p][2], B[p][3],
                          cur + (uint32_t)((n0 + p*16)*80 + ks*2) + boff);
                #pragma unroll
                for (int p = 0; p < 2; p++)
                    #pragma unroll
                    for (int q = 0; q < 2; q++) {
                        int nt = p*2 + q;
                        MMA(cacc[0][nt], A[0][0], A[0][1], A[0][2], A[0][3], B[p][q*2], B[p][q*2+1]);
                        MMA(cacc[1][nt], A[1][0], A[1][1], A[1][2], A[1][3], B[p][q*2], B[p][q*2+1]);
                    }
            }
            __syncthreads();
        }
    }

    // ================= coupling epilogue =================
    if (warpN < 4) {
        // cols 0..127: s -> hb; x1 actnorm in place
        #pragma unroll
        for (int nt = 0; nt < 4; nt++) {
            int c = n0 + nt*8 + 2*t;
            float be0 = __ldg(bb2 + c), be1 = __ldg(bb2 + c + 1);
            float sc0 = __ldg(sc + c),  sc1 = __ldg(sc + c + 1);
            float oo0 = __ldg(oo + c),  oo1 = __ldg(oo + c + 1);
            #pragma unroll
            for (int mt = 0; mt < 2; mt++) {
                float* cf = cacc[mt][nt];
                #pragma unroll
                for (int half = 0; half < 2; half++) {
                    int r = mrow0 + mt*16 + g + half*8;
                    float s0 = fast_tanh_scaled(cf[half*2 + 0] + be0);
                    float s1 = fast_tanh_scaled(cf[half*2 + 1] + be1);
                    *(uint32_t*)(hb + (size_t)r*APAD + c) = packbf2(s0, s1);
                    size_t ao = (size_t)r*APAD + c;
                    float2 hv = unpackbf2(*(uint32_t*)(xhi + ao));
                    float2 lv = unpackbf2(*(uint32_t*)(xlo + ao));
                    float nn0 = (hv.x + lv.x) * sc0 + oo0;
                    float nn1 = (hv.y + lv.y) * sc1 + oo1;
                    uint32_t hw, lw; split2(nn0, nn1, hw, lw);
                    *(uint32_t*)(xhi + ao) = hw;
                    *(uint32_t*)(xlo + ao) = lw;
                }
            }
        }
    }
    __syncthreads();
    if (warpN >= 4) {
        // cols 128..255: x2' = x2*exp(s) + a2, then actnorm
        #pragma unroll
        for (int nt = 0; nt < 4; nt++) {
            int c = n0 + nt*8 + 2*t;
            float be0 = __ldg(bb2 + c), be1 = __ldg(bb2 + c + 1);
            float sc0 = __ldg(sc + c),  sc1 = __ldg(sc + c + 1);
            float oo0 = __ldg(oo + c),  oo1 = __ldg(oo + c + 1);
            #pragma unroll
            for (int mt = 0; mt < 2; mt++) {
                float* cf = cacc[mt][nt];
                #pragma unroll
                for (int half = 0; half < 2; half++) {
                    int r = mrow0 + mt*16 + g + half*8;
                    float a20 = 0.1f * (cf[half*2 + 0] + be0);
                    float a21 = 0.1f * (cf[half*2 + 1] + be1);
                    float2 sv = unpackbf2(*(uint32_t*)(hb + (size_t)r*APAD + (c - 128)));
                    size_t ao = (size_t)r*APAD + c;
                    float2 hv = unpackbf2(*(uint32_t*)(xhi + ao));
                    float2 lv = unpackbf2(*(uint32_t*)(xlo + ao));
                    float v0 = (hv.x + lv.x) * __expf(sv.x) + a20;
                    float v1 = (hv.y + lv.y) * __expf(sv.y) + a21;
                    float nn0 = v0 * sc0 + oo0;
                    float nn1 = v1 * sc1 + oo1;
                    uint32_t hw, lw; split2(nn0, nn1, hw, lw);
                    *(uint32_t*)(xhi + ao) = hw;
                    *(uint32_t*)(xlo + ao) = lw;
                }
            }
        }
    } else if (tid < MROW) {
        float rs = 0.f;
        #pragma unroll 8
        for (int k2 = 0; k2 < 64; k2++) {
            float2 p = unpackbf2(*(uint32_t*)(hb + (size_t)tid*APAD + 2*k2));
            rs += p.x + p.y;
        }
        int grow = blockIdx.x * MROW + tid;
        float prev = layer ? g_ld[grow] : 0.f;
        g_ld[grow] = prev + rs + g_sumlog[layer];
    }

    // ================= GEMM3: XO = Xc @ P^T, 3-term split, K=256 =================
    {
        #pragma unroll
        for (int mt = 0; mt < 2; mt++)
            #pragma unroll
            for (int nt = 0; nt < 4; nt++)
                #pragma unroll
                for (int q = 0; q < 4; q++) cacc[mt][nt][q] = 0.f;

        const __nv_bfloat16* ih = g_ph + (size_t)layer*256*256;
        const __nv_bfloat16* il = g_pl + (size_t)layer*256*256;
        stage_chunk(bw,         ih, 256, 0, tid);
        stage_chunk(bw + 20480, il, 256, 0, tid); CP_COMMIT;
        for (int ch = 0; ch < 8; ch++) {
            uint32_t cur = BWs + (uint32_t)((ch & 1) * 40960);
            if (ch + 1 < 8) {
                char* nxt = bw + ((ch + 1) & 1) * 40960;
                stage_chunk(nxt,         ih, 256, (ch + 1) * 32, tid);
                stage_chunk(nxt + 20480, il, 256, (ch + 1) * 32, tid);
                CP_COMMIT; CP_WAIT1;
            } else CP_WAIT0;
            __syncthreads();
            #pragma unroll
            for (int ks = 0; ks < 32; ks += 16) {
                uint32_t Ah[2][4], Al[2][4], Bh[2][4], Bl[2][4];
                #pragma unroll
                for (int mt = 0; mt < 2; mt++) {
                    uint32_t abase = (uint32_t)((mrow0 + mt*16)*528 + (ch*32 + ks)*2) + aoff;
                    LDSM4(Ah[mt][0], Ah[mt][1], Ah[mt][2], Ah[mt][3], XHI + abase);
                    LDSM4(Al[mt][0], Al[mt][1], Al[mt][2], Al[mt][3], XLO + abase);
                }
                #pragma unroll
                for (int p = 0; p < 2; p++) {
                    uint32_t bbase = cur + (uint32_t)((n0 + p*16)*80 + ks*2) + boff;
                    LDSM4(Bh[p][0], Bh[p][1], Bh[p][2], Bh[p][3], bbase);
                    LDSM4(Bl[p][0], Bl[p][1], Bl[p][2], Bl[p][3], bbase + 20480);
                }
                #pragma unroll
                for (int p = 0; p < 2; p++)
                    #pragma unroll
                    for (int q = 0; q < 2; q++) {
                        int nt = p*2 + q;
                        #pragma unroll
                        for (int mt = 0; mt < 2; mt++) {
                            MMA(cacc[mt][nt], Ah[mt][0], Ah[mt][1], Ah[mt][2], Ah[mt][3], Bh[p][q*2], Bh[p][q*2+1]);
                            MMA(cacc[mt][nt], Al[mt][0], Al[mt][1], Al[mt][2], Al[mt][3], Bh[p][q*2], Bh[p][q*2+1]);
                            MMA(cacc[mt][nt], Ah[mt][0], Ah[mt][1], Ah[mt][2], Ah[mt][3], Bl[p][q*2], Bl[p][q*2+1]);
                        }
                    }
            }
            __syncthreads();
        }
        // write fp32 output
        #pragma unroll
        for (int mt = 0; mt < 2; mt++)
            #pragma unroll
            for (int half = 0; half < 2; half++) {
                int r = blockIdx.x * MROW + mrow0 + mt*16 + g + half*8;
                #pragma unroll
                for (int nt = 0; nt < 4; nt++) {
                    int c = n0 + nt*8 + 2*t;
                    float* cf = cacc[mt][nt];
                    *(float2*)(xout + (size_t)r*Dd + c) =
                        make_float2(cf[half*2 + 0], cf[half*2 + 1]);
                }
            }
    }
}

// ---------------- head: h = z@Wh1 + bh1 (3-term) + BN partials ----------------
__global__ void __launch_bounds__(NTHR, 1) head_hmma(
    const float* __restrict__ z, float* __restrict__ h,
    const float* __restrict__ bh1)
{
    extern __shared__ char smem[];
    __nv_bfloat16* xhi = (__nv_bfloat16*)(smem + OFF_XHI);
    __nv_bfloat16* xlo = (__nv_bfloat16*)(smem + OFF_XLO);
    char* bw = smem + OFF_BW;
    const uint32_t smem_u = (uint32_t)__cvta_generic_to_shared(smem);
    const uint32_t XHI = smem_u + OFF_XHI, XLO = smem_u + OFF_XLO,
                   BWs = smem_u + OFF_BW;

    const int tid = threadIdx.x, lane = tid & 31, wid = tid >> 5;
    const int warpM = wid >> 3, warpN = wid & 7;
    const int g = lane >> 2, t = lane & 3;
    const int mrow0 = warpM * 32;
    const int n0 = warpN * 32;
    const uint32_t aoff = (uint32_t)((lane & 15) * 528 + ((lane >> 4) << 4));
    const uint32_t boff = (uint32_t)((((lane >> 4) << 3) + (lane & 7)) * 80 + (((lane >> 3) & 1) << 4));

    {
        const float4* src = (const float4*)(z + (size_t)blockIdx.x * MROW * Dd);
        #pragma unroll
        for (int i = tid; i < MROW * Dd / 4; i += NTHR) {
            int r = i >> 6, c = (i & 63) * 4;
            float4 v = src[i];
            uint32_t h0, l0, h1, l1;
            split2(v.x, v.y, h0, l0);
            split2(v.z, v.w, h1, l1);
            *(uint32_t*)(xhi + (size_t)r*APAD + c)     = h0;
            *(uint32_t*)(xhi + (size_t)r*APAD + c + 2) = h1;
            *(uint32_t*)(xlo + (size_t)r*APAD + c)     = l0;
            *(uint32_t*)(xlo + (size_t)r*APAD + c + 2) = l1;
        }
    }
    __syncthreads();

    float cacc[2][4][4];
    #pragma unroll
    for (int mt = 0; mt < 2; mt++)
        #pragma unroll
        for (int nt = 0; nt < 4; nt++)
            #pragma unroll
            for (int q = 0; q < 4; q++) cacc[mt][nt][q] = 0.f;

    stage_chunk(bw,         g_whh, 256, 0, tid);
    stage_chunk(bw + 20480, g_whl, 256, 0, tid); CP_COMMIT;
    for (int ch = 0; ch < 8; ch++) {
        uint32_t cur = BWs + (uint32_t)((ch & 1) * 40960);
        if (ch + 1 < 8) {
            char* nxt = bw + ((ch + 1) & 1) * 40960;
            stage_chunk(nxt,         g_whh, 256, (ch + 1) * 32, tid);
            stage_chunk(nxt + 20480, g_whl, 256, (ch + 1) * 32, tid);
            CP_COMMIT; CP_WAIT1;
        } else CP_WAIT0;
        __syncthreads();
        #pragma unroll
        for (int ks = 0; ks < 32; ks += 16) {
            uint32_t Ah[2][4], Al[2][4], Bh[2][4], Bl[2][4];
            #pragma unroll
            for (int mt = 0; mt < 2; mt++) {
                uint32_t abase = (uint32_t)((mrow0 + mt*16)*528 + (ch*32 + ks)*2) + aoff;
                LDSM4(Ah[mt][0], Ah[mt][1], Ah[mt][2], Ah[mt][3], XHI + abase);
                LDSM4(Al[mt][0], Al[mt][1], Al[mt][2], Al[mt][3], XLO + abase);
            }
            #pragma unroll
            for (int p = 0; p < 2; p++) {
                uint32_t bbase = cur + (uint32_t)((n0 + p*16)*80 + ks*2) + boff;
                LDSM4(Bh[p][0], Bh[p][1], Bh[p][2], Bh[p][3], bbase);
                LDSM4(Bl[p][0], Bl[p][1], Bl[p][2], Bl[p][3], bbase + 20480);
            }
            #pragma unroll
            for (int p = 0; p < 2; p++)
                #pragma unroll
                for (int q = 0; q < 2; q++) {
                    int nt = p*2 + q;
                    #pragma unroll
                    for (int mt = 0; mt < 2; mt++) {
                        MMA(cacc[mt][nt], Ah[mt][0], Ah[mt][1], Ah[mt][2], Ah[mt][3], Bh[p][q*2], Bh[p][q*2+1]);
                        MMA(cacc[mt][nt], Al[mt][0], Al[mt][1], Al[mt][2], Al[mt][3], Bh[p][q*2], Bh[p][q*2+1]);
                        MMA(cacc[mt][nt], Ah[mt][0], Ah[mt][1], Ah[mt][2], Ah[mt][3], Bl[p][q*2], Bl[p][q*2+1]);
                    }
                }
        }
        __syncthreads();
    }

    // epilogue: +bias, gmem write, stage fp32 for BN partials
    float* stg = (float*)smem;    // overlay xhi/xlo: [64][APAD] fp32
    __syncthreads();
    #pragma unroll
    for (int mt = 0; mt < 2; mt++)
        #pragma unroll
        for (int half = 0; half < 2; half++) {
            int rl = mrow0 + mt*16 + g + half*8;
            int r  = blockIdx.x * MROW + rl;
            #pragma unroll
            for (int nt = 0; nt < 4; nt++) {
                int c = n0 + nt*8 + 2*t;
                float* cf = cacc[mt][nt];
                float v0 = cf[half*2 + 0] + __ldg(bh1 + c);
                float v1 = cf[half*2 + 1] + __ldg(bh1 + c + 1);
                *(float2*)(h + (size_t)r*Dd + c) = make_float2(v0, v1);
                stg[(size_t)rl*APAD + c]     = v0;
                stg[(size_t)rl*APAD + c + 1] = v1;
            }
        }
    __syncthreads();
    if (tid < Dd) {
        float s = 0.f, q = 0.f;
        #pragma unroll 4
        for (int r = 0; r < MROW; r++) {
            float v = stg[(size_t)r*APAD + tid];
            s += v; q += v * v;
        }
        g_part[(size_t)blockIdx.x*2*Dd + tid]      = s;
        g_part[(size_t)blockIdx.x*2*Dd + Dd + tid] = q;
    }
}

// ---------------- BN stats fold ----------------
__global__ void stats_kernel(const float* __restrict__ gamma, const float* __restrict__ beta) {
    int c = threadIdx.x;
    float s0=0.f,s1=0.f,s2=0.f,s3=0.f, q0=0.f,q1=0.f,q2=0.f,q3=0.f;
    for (int i = 0; i < NBLK; i += 4) {
        s0 += g_part[(size_t)(i+0)*2*Dd + c];   q0 += g_part[(size_t)(i+0)*2*Dd + Dd + c];
        s1 += g_part[(size_t)(i+1)*2*Dd + c];   q1 += g_part[(size_t)(i+1)*2*Dd + Dd + c];
        s2 += g_part[(size_t)(i+2)*2*Dd + c];   q2 += g_part[(size_t)(i+2)*2*Dd + Dd + c];
        s3 += g_part[(size_t)(i+3)*2*Dd + c];   q3 += g_part[(size_t)(i+3)*2*Dd + Dd + c];
    }
    float s = (s0+s1)+(s2+s3), q = (q0+q1)+(q2+q3);
    float mu  = s * (1.f/Bsz);
    float var = q * (1.f/Bsz) - mu*mu;
    float a = gamma[c] * rsqrtf(var + BN_EPS);
    g_stats[c]      = a;
    g_stats[Dd + c] = beta[c] - mu * a;
}

// ---------------- log_px ----------------
__global__ void logpx_kernel(const float* __restrict__ z, float* __restrict__ out) {
    int warp = threadIdx.x >> 5, lane = threadIdx.x & 31;
    size_t row = (size_t)blockIdx.x * 8 + warp;
    const float4* zr = (const float4*)(z + row*Dd);
    float4 v0 = zr[lane*2], v1 = zr[lane*2 + 1];
    float ss = v0.x*v0.x + v0.y*v0.y + v0.z*v0.z + v0.w*v0.w
             + v1.x*v1.x + v1.y*v1.y + v1.z*v1.z + v1.w*v1.w;
    #pragma unroll
    for (int o = 16; o; o >>= 1) ss += __shfl_down_sync(0xffffffffu, ss, o);
    if (lane == 0)
        out[row] = (DGCONST - 0.5f*ss + g_ld[row]) * (1.0f/Dd);
}

// ---------------- logits ----------------
__global__ void __launch_bounds__(256) logits_kernel(
    const float* __restrict__ h, const float* __restrict__ Wh2,
    const float* __restrict__ bh2, float* __restrict__ out)
{
    __shared__ float w2s[Dd*NCc];
    __shared__ float As[Dd], Bs[Dd];
    int tid = threadIdx.x;
    for (int i = tid; i < Dd*NCc; i += 256) w2s[i] = Wh2[i];
    if (tid < Dd) { As[tid] = g_stats[tid]; Bs[tid] = g_stats[Dd + tid]; }
    __syncthreads();

    int warp = tid >> 5, lane = tid & 31;
    size_t row = (size_t)blockIdx.x * 8 + warp;
    const float4* hr = (const float4*)(h + row*Dd);
    float4 v0 = hr[lane*2], v1 = hr[lane*2 + 1];
    int k0 = lane * 8;
    float hn[8];
    hn[0] = fmaxf(v0.x*As[k0+0] + Bs[k0+0], 0.f);
    hn[1] = fmaxf(v0.y*As[k0+1] + Bs[k0+1], 0.f);
    hn[2] = fmaxf(v0.z*As[k0+2] + Bs[k0+2], 0.f);
    hn[3] = fmaxf(v0.w*As[k0+3] + Bs[k0+3], 0.f);
    hn[4] = fmaxf(v1.x*As[k0+4] + Bs[k0+4], 0.f);
    hn[5] = fmaxf(v1.y*As[k0+5] + Bs[k0+5], 0.f);
    hn[6] = fmaxf(v1.z*As[k0+6] + Bs[k0+6], 0.f);
    hn[7] = fmaxf(v1.w*As[k0+7] + Bs[k0+7], 0.f);

    float acc[NCc];
    #pragma unroll
    for (int c = 0; c < NCc; c++) acc[c] = 0.f;
    #pragma unroll
    for (int kk = 0; kk < 8; kk++) {
        float x = hn[kk];
        const float* wr = &w2s[(k0+kk)*NCc];
        #pragma unroll
        for (int c = 0; c < NCc; c++) acc[c] += x * wr[c];
    }
    #pragma unroll
    for (int c = 0; c < NCc; c++) {
        #pragma unroll
        for (int o = 16; o; o >>= 1) acc[c] += __shfl_down_sync(0xffffffffu, acc[c], o);
    }
    if (lane == 0) {
        #pragma unroll
        for (int c = 0; c < NCc; c++) out[row*NCc + c] = acc[c] + __ldg(bh2 + c);
    }
}

// ---------------- launch ----------------
extern "C" void kernel_launch(void* const* d_in, const int* in_sizes, int n_in,
                              void* d_out, int out_size)
{
    const float* feat  = (const float*)d_in[0];
    const float* W1    = (const float*)d_in[1];
    const float* b1    = (const float*)d_in[2];
    const float* W2    = (const float*)d_in[3];
    const float* b2    = (const float*)d_in[4];
    const float* gs    = (const float*)d_in[5];
    const float* go    = (const float*)d_in[6];
    const float* P     = (const float*)d_in[7];
    const float* Wh1   = (const float*)d_in[8];
    const float* bh1   = (const float*)d_in[9];
    const float* gamma = (const float*)d_in[10];
    const float* beta  = (const float*)d_in[11];
    const float* Wh2   = (const float*)d_in[12];
    const float* bh2   = (const float*)d_in[13];
    float* out = (float*)d_out;

    cudaFuncSetAttribute(flow_hmma, cudaFuncAttributeMaxDynamicSharedMemorySize, SMEMSZ);
    cudaFuncSetAttribute(head_hmma, cudaFuncAttributeMaxDynamicSharedMemorySize, SMEMSZ);

    float *bufA = nullptr, *bufB = nullptr;
    cudaGetSymbolAddress((void**)&bufA, g_bufA);
    cudaGetSymbolAddress((void**)&bufB, g_bufB);

    prep_scale<<<Lc, 256>>>(gs);
    prep_w1t<<<(Lc*256*128)/256, 256>>>(W1);
    prep_w2t<<<(Lc*256*256)/256, 256>>>(W2);
    prep_pt <<<(Lc*256*256)/256, 256>>>(P);
    prep_wht<<<(256*256)/256, 256>>>(Wh1);

    const float* cin = feat;
    for (int l = 0; l < Lc; l++) {
        float* cout = (l & 1) ? bufB : bufA;
        flow_hmma<<<NBLK, NTHR, SMEMSZ>>>(cin, cout, l, b1, b2, go);
        cin = cout;
    }
    // z in bufB after layer 7
    head_hmma<<<NBLK, NTHR, SMEMSZ>>>(bufB, bufA, bh1);
    stats_kernel<<<1, 256>>>(gamma, beta);
    logpx_kernel<<<Bsz/8, 256>>>(bufB, out);
    logits_kernel<<<Bsz/8, 256>>>(bufA, Wh2, bh2, out + Bsz);
}

// round 6
// speedup vs baseline: 4.2724x; 1.2634x over previous
#include <cuda_runtime.h>
#include <cuda_bf16.h>
#include <math.h>
#include <stdint.h>

// ---------------- problem constants ----------------
#define Bsz   131072
#define Dd    256
#define Lc    8
#define NCc   10
#define BN_EPS 1e-5f
#define DGCONST -235.24826450039622f   // D * GCONST

#define MROW  64
#define NTHR  512
#define NBLK  (Bsz/MROW)      // 2048 CTAs

// smem byte offsets (all swizzled images, no padding)
#define XHIo 0
#define XLOo 32768
#define HBo  65536
#define BWo  98304            // 2 x 65536 (each stage: [hi 32768][lo 32768])
#define SMEMSZ 229376

// ---------------- static device scratch ----------------
__device__ float g_bufA[(size_t)Bsz*Dd];
__device__ float g_bufB[(size_t)Bsz*Dd];
__device__ float g_ld[Bsz];
__device__ float g_scale[Lc*Dd];
__device__ float g_sumlog[Lc];
__device__ float g_po[Lc*Dd];
__device__ float g_part[(size_t)NBLK*2*Dd];
__device__ float g_stats[2*Dd];
// pre-swizzled bf16 weight images (chunked K=64 smem layout)
__device__ __nv_bfloat16 g_w1t[(size_t)Lc*32768];   // [n=256][k=128], 2 chunks
__device__ __nv_bfloat16 g_w2t[(size_t)Lc*65536];   // [256][256], 4 chunks
__device__ __nv_bfloat16 g_ph [(size_t)Lc*65536];   // P' = P*diag(scale), hi
__device__ __nv_bfloat16 g_pl [(size_t)Lc*65536];   //                     lo
__device__ __nv_bfloat16 g_whh[65536];
__device__ __nv_bfloat16 g_whl[65536];

// ---------------- helpers ----------------
__device__ __forceinline__ uint32_t packbf2(float a, float b) {
    __nv_bfloat162 t = __floats2bfloat162_rn(a, b);
    return *(uint32_t*)&t;
}
__device__ __forceinline__ float2 unpackbf2(uint32_t w) {
    __nv_bfloat162 t = *(__nv_bfloat162*)&w;
    return __bfloat1622float2(t);
}
__device__ __forceinline__ void split2(float a, float b, uint32_t& hw, uint32_t& lw) {
    __nv_bfloat16 ha = __float2bfloat16(a), hb = __float2bfloat16(b);
    float la = a - __bfloat162float(ha), lb = b - __bfloat162float(hb);
    __nv_bfloat162 h; h.x = ha; h.y = hb;
    hw = *(uint32_t*)&h;
    lw = packbf2(la, lb);
}
__device__ __forceinline__ float fast_tanh_scaled(float a) {
    float e = __expf(-0.2f * a);
    return 1.9f * __fdividef(1.f - e, 1.f + e);
}
__device__ __forceinline__ void cpab(void* dst_smem, const void* src) {
    unsigned s = (unsigned)__cvta_generic_to_shared(dst_smem);
    asm volatile("cp.async.cg.shared.global [%0], [%1], 16;" :: "r"(s), "l"(src));
}
#define CP_COMMIT asm volatile("cp.async.commit_group;")
#define CP_WAIT0  asm volatile("cp.async.wait_group 0;")

#define MMA(cd, a0, a1, a2, a3, b0, b1) \
    asm volatile("mma.sync.aligned.m16n8k16.row.col.f32.bf16.bf16.f32 " \
        "{%0,%1,%2,%3}, {%4,%5,%6,%7}, {%8,%9}, {%0,%1,%2,%3};" \
        : "+f"((cd)[0]), "+f"((cd)[1]), "+f"((cd)[2]), "+f"((cd)[3]) \
        : "r"(a0), "r"(a1), "r"(a2), "r"(a3), "r"(b0), "r"(b1))

#define LDSM4(r0, r1, r2, r3, addr) \
    asm volatile("ldmatrix.sync.aligned.m8n8.x4.shared.b16 {%0,%1,%2,%3}, [%4];" \
        : "=r"(r0), "=r"(r1), "=r"(r2), "=r"(r3) : "r"(addr))

// flat 32KB stage (pre-swizzled image)
__device__ __forceinline__ void stage32(char* dst, const __nv_bfloat16* src, int tid) {
    const char* s = (const char*)src;
    #pragma unroll
    for (int i = 0; i < 4; i++) cpab(dst + tid*16 + i*8192, s + tid*16 + i*8192);
}

// element offset within one 64-k chunk image (row n, k in 0..63)
__device__ __forceinline__ int imgoff(int n, int k) {
    return n*64 + (((k >> 3) ^ (n & 7)) << 3) + (k & 7);
}

// ---------------- preprocessing ----------------
__global__ void prep_scale(const float* __restrict__ gs) {
    __shared__ float red[256];
    int l = blockIdx.x, d = threadIdx.x;
    float x  = 0.5f * gs[l*Dd + d];
    float sp = (x > 20.f) ? x : log1pf(expf(x));
    float s  = 0.2f * sp;
    g_scale[l*Dd + d] = s;
    red[d] = logf(s);
    __syncthreads();
    #pragma unroll
    for (int o = 128; o; o >>= 1) { if (d < o) red[d] += red[d + o]; __syncthreads(); }
    if (d == 0) g_sumlog[l] = red[0];
}
__global__ void prep_w1t(const float* __restrict__ W1) {
    int idx = blockIdx.x * 256 + threadIdx.x;      // Lc*256*128
    int k = idx & 127, n = (idx >> 7) & 255, l = idx >> 15;
    g_w1t[(size_t)l*32768 + (k>>6)*16384 + imgoff(n, k & 63)] =
        __float2bfloat16(W1[((size_t)l*128 + k)*256 + n]);
}
__global__ void prep_w2t(const float* __restrict__ W2) {
    int idx = blockIdx.x * 256 + threadIdx.x;      // Lc*256*256
    int k = idx & 255, n = (idx >> 8) & 255, l = idx >> 16;
    g_w2t[(size_t)l*65536 + (k>>6)*16384 + imgoff(n, k & 63)] =
        __float2bfloat16(W2[((size_t)l*256 + k)*256 + n]);
}
__global__ void prep_pt(const float* __restrict__ P) {
    int idx = blockIdx.x * 256 + threadIdx.x;      // Lc*256*256
    int k = idx & 255, n = (idx >> 8) & 255, l = idx >> 16;
    float v = P[((size_t)l*256 + n)*256 + k] * g_scale[l*Dd + k];  // fold actnorm scale
    __nv_bfloat16 hi = __float2bfloat16(v);
    size_t o = (size_t)l*65536 + (k>>6)*16384 + imgoff(n, k & 63);
    g_ph[o] = hi;
    g_pl[o] = __float2bfloat16(v - __bfloat162float(hi));
}
__global__ void prep_po(const float* __restrict__ P, const float* __restrict__ go) {
    int l = blockIdx.x, n = threadIdx.x;
    const float* pr = P + ((size_t)l*256 + n)*256;
    const float* o  = go + l*Dd;
    float acc = 0.f;
    for (int k = 0; k < 256; k++) acc += o[k] * pr[k];
    g_po[l*Dd + n] = acc;
}
__global__ void prep_wht(const float* __restrict__ Wh1) {
    int idx = blockIdx.x * 256 + threadIdx.x;      // 256*256
    int k = idx & 255, n = idx >> 8;
    float v = Wh1[(size_t)k*256 + n];
    __nv_bfloat16 hi = __float2bfloat16(v);
    size_t o = (size_t)(k>>6)*16384 + imgoff(n, k & 63);
    g_whh[o] = hi;
    g_whl[o] = __float2bfloat16(v - __bfloat162float(hi));
}

// ---------------- fused flow layer ----------------
__global__ void __launch_bounds__(NTHR, 1) flow_hmma(
    const float* __restrict__ xin, float* __restrict__ xout, int layer,
    const float* __restrict__ b1, const float* __restrict__ b2)
{
    extern __shared__ char smem[];
    const uint32_t su = (uint32_t)__cvta_generic_to_shared(smem);
    const uint32_t XHI = su + XHIo, XLO = su + XLOo, HBu = su + HBo, BWu = su + BWo;
    char* bw = smem + BWo;

    const int tid = threadIdx.x, lane = tid & 31, wid = tid >> 5;
    const int warpM = wid >> 3, warpN = wid & 7;
    const int g = lane >> 2, t = lane & 3;
    const int mrow0 = warpM * 32;
    const int n0 = warpN * 32;
    const int laneHi = lane >> 4;
    const int key = lane & 7;
    const int aRowB = (lane & 15) * 512;
    const int nloc = ((lane >> 4) << 3) + (lane & 7);
    const int bRow0 = (n0 + nloc) * 128, bRow1 = (n0 + 16 + nloc) * 128;
    const int bsel = (lane >> 3) & 1;

    const float* bb1 = b1 + layer*Dd;
    const float* bb2 = b2 + layer*Dd;
    const __nv_bfloat16* w1img = g_w1t + (size_t)layer*32768;
    const __nv_bfloat16* w2img = g_w2t + (size_t)layer*65536;
    const __nv_bfloat16* phimg = g_ph  + (size_t)layer*65536;
    const __nv_bfloat16* plimg = g_pl  + (size_t)layer*65536;

    // prologue: stage GEMM1 chunk0 first (overlaps x split)
    stage32(bw, w1img, tid); CP_COMMIT;

    // ---- load + split input into swizzled hi/lo images ----
    {
        const float4* src = (const float4*)(xin + (size_t)blockIdx.x * MROW * Dd);
        #pragma unroll
        for (int i = tid; i < MROW * Dd / 4; i += NTHR) {
            int r = i >> 6, c = (i & 63) * 4;
            float4 v = src[i];
            uint32_t h0, l0, h1, l1;
            split2(v.x, v.y, h0, l0);
            split2(v.z, v.w, h1, l1);
            int off = r*512 + (((c >> 3) ^ (r & 7)) << 4) + (c & 7)*2;
            *(uint2*)(smem + XHIo + off) = make_uint2(h0, h1);
            *(uint2*)(smem + XLOo + off) = make_uint2(l0, l1);
        }
    }

    float cacc[2][4][4];
    const int c_base = n0 + 2*t;

    // ================= GEMM1: H = relu(x1_hi @ W1 + b1), K=128 =================
    {
        #pragma unroll
        for (int nt = 0; nt < 4; nt++) {
            int c = c_base + nt*8;
            float f0 = __ldg(bb1 + c), f1 = __ldg(bb1 + c + 1);
            #pragma unroll
            for (int mt = 0; mt < 2; mt++) {
                cacc[mt][nt][0] = f0; cacc[mt][nt][1] = f1;
                cacc[mt][nt][2] = f0; cacc[mt][nt][3] = f1;
            }
        }
        for (int ch = 0; ch < 2; ch++) {
            CP_WAIT0; __syncthreads();
            if (ch + 1 < 2) { stage32(bw + 65536, w1img + 16384, tid); CP_COMMIT; }
            uint32_t cur = BWu + (uint32_t)((ch & 1) * 65536);
            #pragma unroll
            for (int ks = 0; ks < 64; ks += 16) {
                int gA = (ch << 3) + (ks >> 3) + laneHi;
                uint32_t A[2][4], B[2][4];
                #pragma unroll
                for (int mt = 0; mt < 2; mt++)
                    LDSM4(A[mt][0], A[mt][1], A[mt][2], A[mt][3],
                          XHI + (uint32_t)((mrow0 + mt*16)*512 + aRowB + ((gA ^ key) << 4)));
                uint32_t bsw = (uint32_t)(((((ks >> 3) + bsel) ^ key) << 4));
                LDSM4(B[0][0], B[0][1], B[0][2], B[0][3], cur + (uint32_t)bRow0 + bsw);
                LDSM4(B[1][0], B[1][1], B[1][2], B[1][3], cur + (uint32_t)bRow1 + bsw);
                #pragma unroll
                for (int p = 0; p < 2; p++)
                    #pragma unroll
                    for (int q = 0; q < 2; q++) {
                        int nt = p*2 + q;
                        MMA(cacc[0][nt], A[0][0], A[0][1], A[0][2], A[0][3], B[p][q*2], B[p][q*2+1]);
                        MMA(cacc[1][nt], A[1][0], A[1][1], A[1][2], A[1][3], B[p][q*2], B[p][q*2+1]);
                    }
            }
        }
        // pre-stage GEMM2 chunk0
        stage32(bw, w2img, tid); CP_COMMIT;
        // epilogue: relu -> HB (swizzled)
        #pragma unroll
        for (int nt = 0; nt < 4; nt++) {
            int c = c_base + nt*8;
            int csw = ((c >> 3) ^ g) << 4;
            #pragma unroll
            for (int mt = 0; mt < 2; mt++) {
                int r = mrow0 + mt*16 + g;
                float* cf = cacc[mt][nt];
                *(uint32_t*)(smem + HBo + r*512     + csw + 4*t) =
                    packbf2(fmaxf(cf[0], 0.f), fmaxf(cf[1], 0.f));
                *(uint32_t*)(smem + HBo + (r+8)*512 + csw + 4*t) =
                    packbf2(fmaxf(cf[2], 0.f), fmaxf(cf[3], 0.f));
            }
        }
    }

    // ================= GEMM2: A2 = H @ W2 + b2, K=256 =================
    {
        #pragma unroll
        for (int nt = 0; nt < 4; nt++) {
            int c = c_base + nt*8;
            float f0 = __ldg(bb2 + c), f1 = __ldg(bb2 + c + 1);
            #pragma unroll
            for (int mt = 0; mt < 2; mt++) {
                cacc[mt][nt][0] = f0; cacc[mt][nt][1] = f1;
                cacc[mt][nt][2] = f0; cacc[mt][nt][3] = f1;
            }
        }
        for (int ch = 0; ch < 4; ch++) {
            CP_WAIT0; __syncthreads();
            if (ch + 1 < 4) {
                stage32(bw + ((ch+1)&1)*65536, w2img + (ch+1)*16384, tid); CP_COMMIT;
            }
            uint32_t cur = BWu + (uint32_t)((ch & 1) * 65536);
            #pragma unroll
            for (int ks = 0; ks < 64; ks += 16) {
                int gA = (ch << 3) + (ks >> 3) + laneHi;
                uint32_t A[2][4], B[2][4];
                #pragma unroll
                for (int mt = 0; mt < 2; mt++)
                    LDSM4(A[mt][0], A[mt][1], A[mt][2], A[mt][3],
                          HBu + (uint32_t)((mrow0 + mt*16)*512 + aRowB + ((gA ^ key) << 4)));
                uint32_t bsw = (uint32_t)(((((ks >> 3) + bsel) ^ key) << 4));
                LDSM4(B[0][0], B[0][1], B[0][2], B[0][3], cur + (uint32_t)bRow0 + bsw);
                LDSM4(B[1][0], B[1][1], B[1][2], B[1][3], cur + (uint32_t)bRow1 + bsw);
                #pragma unroll
                for (int p = 0; p < 2; p++)
                    #pragma unroll
                    for (int q = 0; q < 2; q++) {
                        int nt = p*2 + q;
                        MMA(cacc[0][nt], A[0][0], A[0][1], A[0][2], A[0][3], B[p][q*2], B[p][q*2+1]);
                        MMA(cacc[1][nt], A[1][0], A[1][1], A[1][2], A[1][3], B[p][q*2], B[p][q*2+1]);
                    }
            }
        }
    }
    // pre-stage GEMM3 chunk0 (hi+lo)
    stage32(bw,         phimg, tid);
    stage32(bw + 32768, plimg, tid); CP_COMMIT;

    // ================= coupling epilogue (actnorm folded into P) =================
    if (warpN < 4) {
        // cols 0..127: s = 1.9*tanh(0.1*a1) -> HB
        #pragma unroll
        for (int nt = 0; nt < 4; nt++) {
            int c = c_base + nt*8;
            int csw = ((c >> 3) ^ g) << 4;
            #pragma unroll
            for (int mt = 0; mt < 2; mt++) {
                float* cf = cacc[mt][nt];
                #pragma unroll
                for (int half = 0; half < 2; half++) {
                    int r = mrow0 + mt*16 + g + half*8;
                    float s0 = fast_tanh_scaled(cf[half*2 + 0]);
                    float s1 = fast_tanh_scaled(cf[half*2 + 1]);
                    *(uint32_t*)(smem + HBo + r*512 + csw + 4*t) = packbf2(s0, s1);
                }
            }
        }
    }
    __syncthreads();
    if (warpN >= 4) {
        // cols 128..255: x2' = x2*exp(s) + a2 (no actnorm here)
        #pragma unroll
        for (int nt = 0; nt < 4; nt++) {
            int c = c_base + nt*8;
            int csw  = ((c >> 3) ^ g) << 4;
            int ssw  = (((c - 128) >> 3) ^ g) << 4;
            #pragma unroll
            for (int mt = 0; mt < 2; mt++) {
                float* cf = cacc[mt][nt];
                #pragma unroll
                for (int half = 0; half < 2; half++) {
                    int r = mrow0 + mt*16 + g + half*8;
                    float a20 = 0.1f * cf[half*2 + 0];
                    float a21 = 0.1f * cf[half*2 + 1];
                    float2 sv = unpackbf2(*(uint32_t*)(smem + HBo + r*512 + ssw + 4*t));
                    int xo = r*512 + csw + 4*t;
                    float2 hv = unpackbf2(*(uint32_t*)(smem + XHIo + xo));
                    float2 lv = unpackbf2(*(uint32_t*)(smem + XLOo + xo));
                    float v0 = (hv.x + lv.x) * __expf(sv.x) + a20;
                    float v1 = (hv.y + lv.y) * __expf(sv.y) + a21;
                    uint32_t hw, lw; split2(v0, v1, hw, lw);
                    *(uint32_t*)(smem + XHIo + xo) = hw;
                    *(uint32_t*)(smem + XLOo + xo) = lw;
                }
            }
        }
    } else if (tid < MROW) {
        float rs = 0.f;
        int rk = tid & 7;
        #pragma unroll
        for (int gi = 0; gi < 16; gi++) {
            int gg = (gi + tid) & 15;
            uint4 w = *(uint4*)(smem + HBo + tid*512 + ((gg ^ rk) << 4));
            float2 p0 = unpackbf2(w.x), p1 = unpackbf2(w.y),
                   p2 = unpackbf2(w.z), p3 = unpackbf2(w.w);
            rs += (p0.x + p0.y) + (p1.x + p1.y) + (p2.x + p2.y) + (p3.x + p3.y);
        }
        int grow = blockIdx.x * MROW + tid;
        float prev = layer ? g_ld[grow] : 0.f;
        g_ld[grow] = prev + rs + g_sumlog[layer];
    }

    // ================= GEMM3: XO = Xc @ P'^T + po, 3-term split, K=256 =================
    {
        const float* po = g_po + layer*Dd;
        #pragma unroll
        for (int nt = 0; nt < 4; nt++) {
            int c = c_base + nt*8;
            float f0 = __ldg(po + c), f1 = __ldg(po + c + 1);
            #pragma unroll
            for (int mt = 0; mt < 2; mt++) {
                cacc[mt][nt][0] = f0; cacc[mt][nt][1] = f1;
                cacc[mt][nt][2] = f0; cacc[mt][nt][3] = f1;
            }
        }
        for (int ch = 0; ch < 4; ch++) {
            CP_WAIT0; __syncthreads();
            if (ch + 1 < 4) {
                char* nxt = bw + ((ch+1)&1)*65536;
                stage32(nxt,         phimg + (ch+1)*16384, tid);
                stage32(nxt + 32768, plimg + (ch+1)*16384, tid); CP_COMMIT;
            }
            uint32_t cur = BWu + (uint32_t)((ch & 1) * 65536);
            #pragma unroll
            for (int ks = 0; ks < 64; ks += 16) {
                int gA = (ch << 3) + (ks >> 3) + laneHi;
                uint32_t Ah[2][4], Al[2][4], Bh[2][4], Bl[2][4];
                #pragma unroll
                for (int mt = 0; mt < 2; mt++) {
                    uint32_t abase = (uint32_t)((mrow0 + mt*16)*512 + aRowB + ((gA ^ key) << 4));
                    LDSM4(Ah[mt][0], Ah[mt][1], Ah[mt][2], Ah[mt][3], XHI + abase);
                    LDSM4(Al[mt][0], Al[mt][1], Al[mt][2], Al[mt][3], XLO + abase);
                }
                uint32_t bsw = (uint32_t)(((((ks >> 3) + bsel) ^ key) << 4));
                LDSM4(Bh[0][0], Bh[0][1], Bh[0][2], Bh[0][3], cur + (uint32_t)bRow0 + bsw);
                LDSM4(Bh[1][0], Bh[1][1], Bh[1][2], Bh[1][3], cur + (uint32_t)bRow1 + bsw);
                LDSM4(Bl[0][0], Bl[0][1], Bl[0][2], Bl[0][3], cur + 32768u + (uint32_t)bRow0 + bsw);
                LDSM4(Bl[1][0], Bl[1][1], Bl[1][2], Bl[1][3], cur + 32768u + (uint32_t)bRow1 + bsw);
                #pragma unroll
                for (int p = 0; p < 2; p++)
                    #pragma unroll
                    for (int q = 0; q < 2; q++) {
                        int nt = p*2 + q;
                        #pragma unroll
                        for (int mt = 0; mt < 2; mt++) {
                            MMA(cacc[mt][nt], Ah[mt][0], Ah[mt][1], Ah[mt][2], Ah[mt][3], Bh[p][q*2], Bh[p][q*2+1]);
                            MMA(cacc[mt][nt], Al[mt][0], Al[mt][1], Al[mt][2], Al[mt][3], Bh[p][q*2], Bh[p][q*2+1]);
                            MMA(cacc[mt][nt], Ah[mt][0], Ah[mt][1], Ah[mt][2], Ah[mt][3], Bl[p][q*2], Bl[p][q*2+1]);
                        }
                    }
            }
        }
        // write fp32 output
        #pragma unroll
        for (int mt = 0; mt < 2; mt++)
            #pragma unroll
            for (int half = 0; half < 2; half++) {
                int r = blockIdx.x * MROW + mrow0 + mt*16 + g + half*8;
                #pragma unroll
                for (int nt = 0; nt < 4; nt++) {
                    int c = c_base + nt*8;
                    float* cf = cacc[mt][nt];
                    *(float2*)(xout + (size_t)r*Dd + c) =
                        make_float2(cf[half*2 + 0], cf[half*2 + 1]);
                }
            }
    }
}

// ---------------- head: h = z@Wh1 + bh1 (3-term) + BN partials ----------------
__global__ void __launch_bounds__(NTHR, 1) head_hmma(
    const float* __restrict__ z, float* __restrict__ h,
    const float* __restrict__ bh1)
{
    extern __shared__ char smem[];
    const uint32_t su = (uint32_t)__cvta_generic_to_shared(smem);
    const uint32_t XHI = su + XHIo, XLO = su + XLOo, BWu = su + BWo;
    char* bw = smem + BWo;

    const int tid = threadIdx.x, lane = tid & 31, wid = tid >> 5;
    const int warpM = wid >> 3, warpN = wid & 7;
    const int g = lane >> 2, t = lane & 3;
    const int mrow0 = warpM * 32;
    const int n0 = warpN * 32;
    const int laneHi = lane >> 4;
    const int key = lane & 7;
    const int aRowB = (lane & 15) * 512;
    const int nloc = ((lane >> 4) << 3) + (lane & 7);
    const int bRow0 = (n0 + nloc) * 128, bRow1 = (n0 + 16 + nloc) * 128;
    const int bsel = (lane >> 3) & 1;
    const int c_base = n0 + 2*t;

    stage32(bw,         g_whh, tid);
    stage32(bw + 32768, g_whl, tid); CP_COMMIT;

    {
        const float4* src = (const float4*)(z + (size_t)blockIdx.x * MROW * Dd);
        #pragma unroll
        for (int i = tid; i < MROW * Dd / 4; i += NTHR) {
            int r = i >> 6, c = (i & 63) * 4;
            float4 v = src[i];
            uint32_t h0, l0, h1, l1;
            split2(v.x, v.y, h0, l0);
            split2(v.z, v.w, h1, l1);
            int off = r*512 + (((c >> 3) ^ (r & 7)) << 4) + (c & 7)*2;
            *(uint2*)(smem + XHIo + off) = make_uint2(h0, h1);
            *(uint2*)(smem + XLOo + off) = make_uint2(l0, l1);
        }
    }

    float cacc[2][4][4];
    #pragma unroll
    for (int nt = 0; nt < 4; nt++) {
        int c = c_base + nt*8;
        float f0 = __ldg(bh1 + c), f1 = __ldg(bh1 + c + 1);
        #pragma unroll
        for (int mt = 0; mt < 2; mt++) {
            cacc[mt][nt][0] = f0; cacc[mt][nt][1] = f1;
            cacc[mt][nt][2] = f0; cacc[mt][nt][3] = f1;
        }
    }

    for (int ch = 0; ch < 4; ch++) {
        CP_WAIT0; __syncthreads();
        if (ch + 1 < 4) {
            char* nxt = bw + ((ch+1)&1)*65536;
            stage32(nxt,         g_whh + (ch+1)*16384, tid);
            stage32(nxt + 32768, g_whl + (ch+1)*16384, tid); CP_COMMIT;
        }
        uint32_t cur = BWu + (uint32_t)((ch & 1) * 65536);
        #pragma unroll
        for (int ks = 0; ks < 64; ks += 16) {
            int gA = (ch << 3) + (ks >> 3) + laneHi;
            uint32_t Ah[2][4], Al[2][4], Bh[2][4], Bl[2][4];
            #pragma unroll
            for (int mt = 0; mt < 2; mt++) {
                uint32_t abase = (uint32_t)((mrow0 + mt*16)*512 + aRowB + ((gA ^ key) << 4));
                LDSM4(Ah[mt][0], Ah[mt][1], Ah[mt][2], Ah[mt][3], XHI + abase);
                LDSM4(Al[mt][0], Al[mt][1], Al[mt][2], Al[mt][3], XLO + abase);
            }
            uint32_t bsw = (uint32_t)(((((ks >> 3) + bsel) ^ key) << 4));
            LDSM4(Bh[0][0], Bh[0][1], Bh[0][2], Bh[0][3], cur + (uint32_t)bRow0 + bsw);
            LDSM4(Bh[1][0], Bh[1][1], Bh[1][2], Bh[1][3], cur + (uint32_t)bRow1 + bsw);
            LDSM4(Bl[0][0], Bl[0][1], Bl[0][2], Bl[0][3], cur + 32768u + (uint32_t)bRow0 + bsw);
            LDSM4(Bl[1][0], Bl[1][1], Bl[1][2], Bl[1][3], cur + 32768u + (uint32_t)bRow1 + bsw);
            #pragma unroll
            for (int p = 0; p < 2; p++)
                #pragma unroll
                for (int q = 0; q < 2; q++) {
                    int nt = p*2 + q;
                    #pragma unroll
                    for (int mt = 0; mt < 2; mt++) {
                        MMA(cacc[mt][nt], Ah[mt][0], Ah[mt][1], Ah[mt][2], Ah[mt][3], Bh[p][q*2], Bh[p][q*2+1]);
                        MMA(cacc[mt][nt], Al[mt][0], Al[mt][1], Al[mt][2], Al[mt][3], Bh[p][q*2], Bh[p][q*2+1]);
                        MMA(cacc[mt][nt], Ah[mt][0], Ah[mt][1], Ah[mt][2], Ah[mt][3], Bl[p][q*2], Bl[p][q*2+1]);
                    }
                }
        }
    }

    // epilogue: gmem write + BN partials via fp32 overlay
    float* stg = (float*)smem;   // [64][264] fp32 overlay (xhi/xlo dead now)
    __syncthreads();
    #pragma unroll
    for (int mt = 0; mt < 2; mt++)
        #pragma unroll
        for (int half = 0; half < 2; half++) {
            int rl = mrow0 + mt*16 + g + half*8;
            int r  = blockIdx.x * MROW + rl;
            #pragma unroll
            for (int nt = 0; nt < 4; nt++) {
                int c = c_base + nt*8;
                float* cf = cacc[mt][nt];
                float v0 = cf[half*2 + 0];
                float v1 = cf[half*2 + 1];
                *(float2*)(h + (size_t)r*Dd + c) = make_float2(v0, v1);
                stg[(size_t)rl*264 + c]     = v0;
                stg[(size_t)rl*264 + c + 1] = v1;
            }
        }
    __syncthreads();
    if (tid < Dd) {
        float s = 0.f, q = 0.f;
        #pragma unroll 4
        for (int r = 0; r < MROW; r++) {
            float v = stg[(size_t)r*264 + tid];
            s += v; q += v * v;
        }
        g_part[(size_t)blockIdx.x*2*Dd + tid]      = s;
        g_part[(size_t)blockIdx.x*2*Dd + Dd + tid] = q;
    }
}

// ---------------- BN stats fold ----------------
__global__ void stats_kernel(const float* __restrict__ gamma, const float* __restrict__ beta) {
    int c = threadIdx.x;
    float s0=0.f,s1=0.f,s2=0.f,s3=0.f, q0=0.f,q1=0.f,q2=0.f,q3=0.f;
    for (int i = 0; i < NBLK; i += 4) {
        s0 += g_part[(size_t)(i+0)*2*Dd + c];   q0 += g_part[(size_t)(i+0)*2*Dd + Dd + c];
        s1 += g_part[(size_t)(i+1)*2*Dd + c];   q1 += g_part[(size_t)(i+1)*2*Dd + Dd + c];
        s2 += g_part[(size_t)(i+2)*2*Dd + c];   q2 += g_part[(size_t)(i+2)*2*Dd + Dd + c];
        s3 += g_part[(size_t)(i+3)*2*Dd + c];   q3 += g_part[(size_t)(i+3)*2*Dd + Dd + c];
    }
    float s = (s0+s1)+(s2+s3), q = (q0+q1)+(q2+q3);
    float mu  = s * (1.f/Bsz);
    float var = q * (1.f/Bsz) - mu*mu;
    float a = gamma[c] * rsqrtf(var + BN_EPS);
    g_stats[c]      = a;
    g_stats[Dd + c] = beta[c] - mu * a;
}

// ---------------- log_px ----------------
__global__ void logpx_kernel(const float* __restrict__ z, float* __restrict__ out) {
    int warp = threadIdx.x >> 5, lane = threadIdx.x & 31;
    size_t row = (size_t)blockIdx.x * 8 + warp;
    const float4* zr = (const float4*)(z + row*Dd);
    float4 v0 = zr[lane*2], v1 = zr[lane*2 + 1];
    float ss = v0.x*v0.x + v0.y*v0.y + v0.z*v0.z + v0.w*v0.w
             + v1.x*v1.x + v1.y*v1.y + v1.z*v1.z + v1.w*v1.w;
    #pragma unroll
    for (int o = 16; o; o >>= 1) ss += __shfl_down_sync(0xffffffffu, ss, o);
    if (lane == 0)
        out[row] = (DGCONST - 0.5f*ss + g_ld[row]) * (1.0f/Dd);
}

// ---------------- logits ----------------
__global__ void __launch_bounds__(256) logits_kernel(
    const float* __restrict__ h, const float* __restrict__ Wh2,
    const float* __restrict__ bh2, float* __restrict__ out)
{
    __shared__ float w2s[Dd*NCc];
    __shared__ float As[Dd], Bs[Dd];
    int tid = threadIdx.x;
    for (int i = tid; i < Dd*NCc; i += 256) w2s[i] = Wh2[i];
    if (tid < Dd) { As[tid] = g_stats[tid]; Bs[tid] = g_stats[Dd + tid]; }
    __syncthreads();

    int warp = tid >> 5, lane = tid & 31;
    size_t row = (size_t)blockIdx.x * 8 + warp;
    const float4* hr = (const float4*)(h + row*Dd);
    float4 v0 = hr[lane*2], v1 = hr[lane*2 + 1];
    int k0 = lane * 8;
    float hn[8];
    hn[0] = fmaxf(v0.x*As[k0+0] + Bs[k0+0], 0.f);
    hn[1] = fmaxf(v0.y*As[k0+1] + Bs[k0+1], 0.f);
    hn[2] = fmaxf(v0.z*As[k0+2] + Bs[k0+2], 0.f);
    hn[3] = fmaxf(v0.w*As[k0+3] + Bs[k0+3], 0.f);
    hn[4] = fmaxf(v1.x*As[k0+4] + Bs[k0+4], 0.f);
    hn[5] = fmaxf(v1.y*As[k0+5] + Bs[k0+5], 0.f);
    hn[6] = fmaxf(v1.z*As[k0+6] + Bs[k0+6], 0.f);
    hn[7] = fmaxf(v1.w*As[k0+7] + Bs[k0+7], 0.f);

    float acc[NCc];
    #pragma unroll
    for (int c = 0; c < NCc; c++) acc[c] = 0.f;
    #pragma unroll
    for (int kk = 0; kk < 8; kk++) {
        float x = hn[kk];
        const float* wr = &w2s[(k0+kk)*NCc];
        #pragma unroll
        for (int c = 0; c < NCc; c++) acc[c] += x * wr[c];
    }
    #pragma unroll
    for (int c = 0; c < NCc; c++) {
        #pragma unroll
        for (int o = 16; o; o >>= 1) acc[c] += __shfl_down_sync(0xffffffffu, acc[c], o);
    }
    if (lane == 0) {
        #pragma unroll
        for (int c = 0; c < NCc; c++) out[row*NCc + c] = acc[c] + __ldg(bh2 + c);
    }
}

// ---------------- launch ----------------
extern "C" void kernel_launch(void* const* d_in, const int* in_sizes, int n_in,
                              void* d_out, int out_size)
{
    const float* feat  = (const float*)d_in[0];
    const float* W1    = (const float*)d_in[1];
    const float* b1    = (const float*)d_in[2];
    const float* W2    = (const float*)d_in[3];
    const float* b2    = (const float*)d_in[4];
    const float* gs    = (const float*)d_in[5];
    const float* go    = (const float*)d_in[6];
    const float* P     = (const float*)d_in[7];
    const float* Wh1   = (const float*)d_in[8];
    const float* bh1   = (const float*)d_in[9];
    const float* gamma = (const float*)d_in[10];
    const float* beta  = (const float*)d_in[11];
    const float* Wh2   = (const float*)d_in[12];
    const float* bh2   = (const float*)d_in[13];
    float* out = (float*)d_out;

    cudaFuncSetAttribute(flow_hmma, cudaFuncAttributeMaxDynamicSharedMemorySize, SMEMSZ);
    cudaFuncSetAttribute(head_hmma, cudaFuncAttributeMaxDynamicSharedMemorySize, SMEMSZ);

    float *bufA = nullptr, *bufB = nullptr;
    cudaGetSymbolAddress((void**)&bufA, g_bufA);
    cudaGetSymbolAddress((void**)&bufB, g_bufB);

    prep_scale<<<Lc, 256>>>(gs);
    prep_w1t<<<(Lc*256*128)/256, 256>>>(W1);
    prep_w2t<<<(Lc*256*256)/256, 256>>>(W2);
    prep_pt <<<(Lc*256*256)/256, 256>>>(P);
    prep_po <<<Lc, 256>>>(P, go);
    prep_wht<<<(256*256)/256, 256>>>(Wh1);

    const float* cin = feat;
    for (int l = 0; l < Lc; l++) {
        float* cout = (l & 1) ? bufB : bufA;
        flow_hmma<<<NBLK, NTHR, SMEMSZ>>>(cin, cout, l, b1, b2);
        cin = cout;
    }
    // z in bufB after layer 7
    head_hmma<<<NBLK, NTHR, SMEMSZ>>>(bufB, bufA, bh1);
    stats_kernel<<<1, 256>>>(gamma, beta);
    logpx_kernel<<<Bsz/8, 256>>>(bufB, out);
    logits_kernel<<<Bsz/8, 256>>>(bufA, Wh2, bh2, out + Bsz);
}

// round 7
// speedup vs baseline: 4.7219x; 1.1052x over previous
#include <cuda_runtime.h>
#include <cuda_bf16.h>
#include <math.h>
#include <stdint.h>

// ---------------- problem constants ----------------
#define Bsz   131072
#define Dd    256
#define Lc    8
#define NCc   10
#define BN_EPS 1e-5f
#define DGCONST -235.24826450039622f   // D * GCONST

#define MROW  64
#define NTHR  512
#define NBLK  (Bsz/MROW)      // 2048 CTAs

// smem byte offsets (all swizzled images, no padding)
#define XHIo 0
#define XLOo 32768
#define HBo  65536
#define BWo  98304            // 2 x 65536 (each stage: [hi 32768][lo 32768])
#define SMEMSZ 229376

// ---------------- static device scratch ----------------
__device__ float g_bufA[(size_t)Bsz*Dd];
__device__ float g_bufB[(size_t)Bsz*Dd];
__device__ float g_ld[Bsz];
__device__ float g_scale[Lc*Dd];
__device__ float g_sumlog[Lc];
__device__ float g_po[Lc*Dd];
__device__ float g_part[(size_t)NBLK*2*Dd];
__device__ float g_stats[2*Dd];
// pre-swizzled bf16 weight images (chunked K=64 smem layout)
__device__ __nv_bfloat16 g_w1t[(size_t)Lc*32768];
__device__ __nv_bfloat16 g_w2t[(size_t)Lc*65536];
__device__ __nv_bfloat16 g_ph [(size_t)Lc*65536];   // P' = P*diag(scale), hi
__device__ __nv_bfloat16 g_pl [(size_t)Lc*65536];
__device__ __nv_bfloat16 g_whh[65536];
__device__ __nv_bfloat16 g_whl[65536];

// ---------------- helpers ----------------
__device__ __forceinline__ uint32_t packbf2(float a, float b) {
    __nv_bfloat162 t = __floats2bfloat162_rn(a, b);
    return *(uint32_t*)&t;
}
__device__ __forceinline__ float2 unpackbf2(uint32_t w) {
    __nv_bfloat162 t = *(__nv_bfloat162*)&w;
    return __bfloat1622float2(t);
}
__device__ __forceinline__ void split2(float a, float b, uint32_t& hw, uint32_t& lw) {
    __nv_bfloat16 ha = __float2bfloat16(a), hb = __float2bfloat16(b);
    float la = a - __bfloat162float(ha), lb = b - __bfloat162float(hb);
    __nv_bfloat162 h; h.x = ha; h.y = hb;
    hw = *(uint32_t*)&h;
    lw = packbf2(la, lb);
}
__device__ __forceinline__ float fast_tanh_scaled(float a) {
    float e = __expf(-0.2f * a);
    return 1.9f * __fdividef(1.f - e, 1.f + e);
}
__device__ __forceinline__ void cpab(void* dst_smem, const void* src) {
    unsigned s = (unsigned)__cvta_generic_to_shared(dst_smem);
    asm volatile("cp.async.cg.shared.global [%0], [%1], 16;" :: "r"(s), "l"(src));
}
#define CP_COMMIT asm volatile("cp.async.commit_group;")
#define CP_WAIT0  asm volatile("cp.async.wait_group 0;")

#define MMA(cd, a0, a1, a2, a3, b0, b1) \
    asm volatile("mma.sync.aligned.m16n8k16.row.col.f32.bf16.bf16.f32 " \
        "{%0,%1,%2,%3}, {%4,%5,%6,%7}, {%8,%9}, {%0,%1,%2,%3};" \
        : "+f"((cd)[0]), "+f"((cd)[1]), "+f"((cd)[2]), "+f"((cd)[3]) \
        : "r"(a0), "r"(a1), "r"(a2), "r"(a3), "r"(b0), "r"(b1))

#define LDSM4(r0, r1, r2, r3, addr) \
    asm volatile("ldmatrix.sync.aligned.m8n8.x4.shared.b16 {%0,%1,%2,%3}, [%4];" \
        : "=r"(r0), "=r"(r1), "=r"(r2), "=r"(r3) : "r"(addr))

__device__ __forceinline__ void stage32(char* dst, const __nv_bfloat16* src, int tid) {
    const char* s = (const char*)src;
    #pragma unroll
    for (int i = 0; i < 4; i++) cpab(dst + tid*16 + i*8192, s + tid*16 + i*8192);
}
__device__ __forceinline__ int imgoff(int n, int k) {
    return n*64 + (((k >> 3) ^ (n & 7)) << 3) + (k & 7);
}

// ---------------- preprocessing ----------------
__global__ void prep_scale(const float* __restrict__ gs) {
    __shared__ float red[256];
    int l = blockIdx.x, d = threadIdx.x;
    float x  = 0.5f * gs[l*Dd + d];
    float sp = (x > 20.f) ? x : log1pf(expf(x));
    float s  = 0.2f * sp;
    g_scale[l*Dd + d] = s;
    red[d] = logf(s);
    __syncthreads();
    #pragma unroll
    for (int o = 128; o; o >>= 1) { if (d < o) red[d] += red[d + o]; __syncthreads(); }
    if (d == 0) g_sumlog[l] = red[0];
}
__global__ void prep_w1t(const float* __restrict__ W1) {
    int idx = blockIdx.x * 256 + threadIdx.x;
    int k = idx & 127, n = (idx >> 7) & 255, l = idx >> 15;
    g_w1t[(size_t)l*32768 + (k>>6)*16384 + imgoff(n, k & 63)] =
        __float2bfloat16(W1[((size_t)l*128 + k)*256 + n]);
}
__global__ void prep_w2t(const float* __restrict__ W2) {
    int idx = blockIdx.x * 256 + threadIdx.x;
    int k = idx & 255, n = (idx >> 8) & 255, l = idx >> 16;
    g_w2t[(size_t)l*65536 + (k>>6)*16384 + imgoff(n, k & 63)] =
        __float2bfloat16(W2[((size_t)l*256 + k)*256 + n]);
}
__global__ void prep_pt(const float* __restrict__ P) {
    int idx = blockIdx.x * 256 + threadIdx.x;
    int k = idx & 255, n = (idx >> 8) & 255, l = idx >> 16;
    float v = P[((size_t)l*256 + n)*256 + k] * g_scale[l*Dd + k];
    __nv_bfloat16 hi = __float2bfloat16(v);
    size_t o = (size_t)l*65536 + (k>>6)*16384 + imgoff(n, k & 63);
    g_ph[o] = hi;
    g_pl[o] = __float2bfloat16(v - __bfloat162float(hi));
}
__global__ void prep_po(const float* __restrict__ P, const float* __restrict__ go) {
    int l = blockIdx.x, n = threadIdx.x;
    const float* pr = P + ((size_t)l*256 + n)*256;
    const float* o  = go + l*Dd;
    float acc = 0.f;
    for (int k = 0; k < 256; k++) acc += o[k] * pr[k];
    g_po[l*Dd + n] = acc;
}
__global__ void prep_wht(const float* __restrict__ Wh1) {
    int idx = blockIdx.x * 256 + threadIdx.x;
    int k = idx & 255, n = idx >> 8;
    float v = Wh1[(size_t)k*256 + n];
    __nv_bfloat16 hi = __float2bfloat16(v);
    size_t o = (size_t)(k>>6)*16384 + imgoff(n, k & 63);
    g_whh[o] = hi;
    g_whl[o] = __float2bfloat16(v - __bfloat162float(hi));
}

// ---------------- fully fused flow (all 8 layers, x resident in smem) ----------------
__global__ void __launch_bounds__(NTHR, 1) flow_fused(
    const float* __restrict__ xin, float* __restrict__ zout,
    const float* __restrict__ b1, const float* __restrict__ b2)
{
    extern __shared__ char smem[];
    const uint32_t su = (uint32_t)__cvta_generic_to_shared(smem);
    const uint32_t XHI = su + XHIo, XLO = su + XLOo, HBu = su + HBo, BWu = su + BWo;
    char* bw = smem + BWo;

    const int tid = threadIdx.x, lane = tid & 31, wid = tid >> 5;
    const int warpM = wid >> 3, warpN = wid & 7;
    const int g = lane >> 2, t = lane & 3;
    const int mrow0 = warpM * 32;
    const int n0 = warpN * 32;
    const int laneHi = lane >> 4;
    const int key = lane & 7;
    const int aRowB = (lane & 15) * 512;
    const int nloc = ((lane >> 4) << 3) + (lane & 7);
    const int bRow0 = (n0 + nloc) * 128, bRow1 = (n0 + 16 + nloc) * 128;
    const int bsel = (lane >> 3) & 1;
    const int c_base = n0 + 2*t;

    // prologue: stage layer-0 GEMM1 chunk0
    stage32(bw, g_w1t, tid); CP_COMMIT;

    // load + split input x once
    {
        const float4* src = (const float4*)(xin + (size_t)blockIdx.x * MROW * Dd);
        #pragma unroll
        for (int i = tid; i < MROW * Dd / 4; i += NTHR) {
            int r = i >> 6, c = (i & 63) * 4;
            float4 v = src[i];
            uint32_t h0, l0, h1, l1;
            split2(v.x, v.y, h0, l0);
            split2(v.z, v.w, h1, l1);
            int off = r*512 + (((c >> 3) ^ (r & 7)) << 4) + (c & 7)*2;
            *(uint2*)(smem + XHIo + off) = make_uint2(h0, h1);
            *(uint2*)(smem + XLOo + off) = make_uint2(l0, l1);
        }
    }

    float cacc[2][4][4];
    float ldacc = 0.f;     // per-row logdet (valid for tid < MROW)

    #pragma unroll 1
    for (int layer = 0; layer < Lc; layer++) {
        const float* bb1 = b1 + layer*Dd;
        const float* bb2 = b2 + layer*Dd;
        const __nv_bfloat16* w1img = g_w1t + (size_t)layer*32768;
        const __nv_bfloat16* w2img = g_w2t + (size_t)layer*65536;
        const __nv_bfloat16* phimg = g_ph  + (size_t)layer*65536;
        const __nv_bfloat16* plimg = g_pl  + (size_t)layer*65536;

        // ===== GEMM1: H = relu(x1_hi @ W1 + b1), K=128 =====
        #pragma unroll
        for (int nt = 0; nt < 4; nt++) {
            int c = c_base + nt*8;
            float f0 = __ldg(bb1 + c), f1 = __ldg(bb1 + c + 1);
            #pragma unroll
            for (int mt = 0; mt < 2; mt++) {
                cacc[mt][nt][0] = f0; cacc[mt][nt][1] = f1;
                cacc[mt][nt][2] = f0; cacc[mt][nt][3] = f1;
            }
        }
        #pragma unroll 1
        for (int ch = 0; ch < 2; ch++) {
            CP_WAIT0; __syncthreads();
            if (ch + 1 < 2) { stage32(bw + 65536, w1img + 16384, tid); CP_COMMIT; }
            uint32_t cur = BWu + (uint32_t)((ch & 1) * 65536);
            #pragma unroll
            for (int ks = 0; ks < 64; ks += 16) {
                int gA = (ch << 3) + (ks >> 3) + laneHi;
                uint32_t A[2][4], B[2][4];
                #pragma unroll
                for (int mt = 0; mt < 2; mt++)
                    LDSM4(A[mt][0], A[mt][1], A[mt][2], A[mt][3],
                          XHI + (uint32_t)((mrow0 + mt*16)*512 + aRowB + ((gA ^ key) << 4)));
                uint32_t bsw = (uint32_t)(((((ks >> 3) + bsel) ^ key) << 4));
                LDSM4(B[0][0], B[0][1], B[0][2], B[0][3], cur + (uint32_t)bRow0 + bsw);
                LDSM4(B[1][0], B[1][1], B[1][2], B[1][3], cur + (uint32_t)bRow1 + bsw);
                #pragma unroll
                for (int p = 0; p < 2; p++)
                    #pragma unroll
                    for (int q = 0; q < 2; q++) {
                        int nt = p*2 + q;
                        MMA(cacc[0][nt], A[0][0], A[0][1], A[0][2], A[0][3], B[p][q*2], B[p][q*2+1]);
                        MMA(cacc[1][nt], A[1][0], A[1][1], A[1][2], A[1][3], B[p][q*2], B[p][q*2+1]);
                    }
            }
        }
        stage32(bw, w2img, tid); CP_COMMIT;        // pre-stage GEMM2 chunk0
        // relu -> HB
        #pragma unroll
        for (int nt = 0; nt < 4; nt++) {
            int c = c_base + nt*8;
            int csw = ((c >> 3) ^ g) << 4;
            #pragma unroll
            for (int mt = 0; mt < 2; mt++) {
                int r = mrow0 + mt*16 + g;
                float* cf = cacc[mt][nt];
                *(uint32_t*)(smem + HBo + r*512     + csw + 4*t) =
                    packbf2(fmaxf(cf[0], 0.f), fmaxf(cf[1], 0.f));
                *(uint32_t*)(smem + HBo + (r+8)*512 + csw + 4*t) =
                    packbf2(fmaxf(cf[2], 0.f), fmaxf(cf[3], 0.f));
            }
        }

        // ===== GEMM2: A2 = H @ W2 + b2, K=256 =====
        #pragma unroll
        for (int nt = 0; nt < 4; nt++) {
            int c = c_base + nt*8;
            float f0 = __ldg(bb2 + c), f1 = __ldg(bb2 + c + 1);
            #pragma unroll
            for (int mt = 0; mt < 2; mt++) {
                cacc[mt][nt][0] = f0; cacc[mt][nt][1] = f1;
                cacc[mt][nt][2] = f0; cacc[mt][nt][3] = f1;
            }
        }
        #pragma unroll 1
        for (int ch = 0; ch < 4; ch++) {
            CP_WAIT0; __syncthreads();
            if (ch + 1 < 4) {
                stage32(bw + ((ch+1)&1)*65536, w2img + (ch+1)*16384, tid); CP_COMMIT;
            }
            uint32_t cur = BWu + (uint32_t)((ch & 1) * 65536);
            #pragma unroll
            for (int ks = 0; ks < 64; ks += 16) {
                int gA = (ch << 3) + (ks >> 3) + laneHi;
                uint32_t A[2][4], B[2][4];
                #pragma unroll
                for (int mt = 0; mt < 2; mt++)
                    LDSM4(A[mt][0], A[mt][1], A[mt][2], A[mt][3],
                          HBu + (uint32_t)((mrow0 + mt*16)*512 + aRowB + ((gA ^ key) << 4)));
                uint32_t bsw = (uint32_t)(((((ks >> 3) + bsel) ^ key) << 4));
                LDSM4(B[0][0], B[0][1], B[0][2], B[0][3], cur + (uint32_t)bRow0 + bsw);
                LDSM4(B[1][0], B[1][1], B[1][2], B[1][3], cur + (uint32_t)bRow1 + bsw);
                #pragma unroll
                for (int p = 0; p < 2; p++)
                    #pragma unroll
                    for (int q = 0; q < 2; q++) {
                        int nt = p*2 + q;
                        MMA(cacc[0][nt], A[0][0], A[0][1], A[0][2], A[0][3], B[p][q*2], B[p][q*2+1]);
                        MMA(cacc[1][nt], A[1][0], A[1][1], A[1][2], A[1][3], B[p][q*2], B[p][q*2+1]);
                    }
            }
        }
        // pre-stage GEMM3 chunk0 (hi+lo)
        stage32(bw,         phimg, tid);
        stage32(bw + 32768, plimg, tid); CP_COMMIT;
        __syncthreads();   // all warps done READING HB (GEMM2 A) before s overwrites it

        // ===== coupling epilogue (actnorm folded into P) =====
        if (warpN < 4) {
            #pragma unroll
            for (int nt = 0; nt < 4; nt++) {
                int c = c_base + nt*8;
                int csw = ((c >> 3) ^ g) << 4;
                #pragma unroll
                for (int mt = 0; mt < 2; mt++) {
                    float* cf = cacc[mt][nt];
                    #pragma unroll
                    for (int half = 0; half < 2; half++) {
                        int r = mrow0 + mt*16 + g + half*8;
                        float s0 = fast_tanh_scaled(cf[half*2 + 0]);
                        float s1 = fast_tanh_scaled(cf[half*2 + 1]);
                        *(uint32_t*)(smem + HBo + r*512 + csw + 4*t) = packbf2(s0, s1);
                    }
                }
            }
        }
        __syncthreads();
        if (warpN >= 4) {
            #pragma unroll
            for (int nt = 0; nt < 4; nt++) {
                int c = c_base + nt*8;
                int csw  = ((c >> 3) ^ g) << 4;
                int ssw  = (((c - 128) >> 3) ^ g) << 4;
                #pragma unroll
                for (int mt = 0; mt < 2; mt++) {
                    float* cf = cacc[mt][nt];
                    #pragma unroll
                    for (int half = 0; half < 2; half++) {
                        int r = mrow0 + mt*16 + g + half*8;
                        float a20 = 0.1f * cf[half*2 + 0];
                        float a21 = 0.1f * cf[half*2 + 1];
                        float2 sv = unpackbf2(*(uint32_t*)(smem + HBo + r*512 + ssw + 4*t));
                        int xo = r*512 + csw + 4*t;
                        float2 hv = unpackbf2(*(uint32_t*)(smem + XHIo + xo));
                        float2 lv = unpackbf2(*(uint32_t*)(smem + XLOo + xo));
                        float v0 = (hv.x + lv.x) * __expf(sv.x) + a20;
                        float v1 = (hv.y + lv.y) * __expf(sv.y) + a21;
                        uint32_t hw, lw; split2(v0, v1, hw, lw);
                        *(uint32_t*)(smem + XHIo + xo) = hw;
                        *(uint32_t*)(smem + XLOo + xo) = lw;
                    }
                }
            }
        } else if (tid < MROW) {
            float rs = 0.f;
            int rk = tid & 7;
            #pragma unroll
            for (int gi = 0; gi < 16; gi++) {
                int gg = (gi + tid) & 15;
                uint4 w = *(uint4*)(smem + HBo + tid*512 + ((gg ^ rk) << 4));
                float2 p0 = unpackbf2(w.x), p1 = unpackbf2(w.y),
                       p2 = unpackbf2(w.z), p3 = unpackbf2(w.w);
                rs += (p0.x + p0.y) + (p1.x + p1.y) + (p2.x + p2.y) + (p3.x + p3.y);
            }
            ldacc += rs + g_sumlog[layer];
        }

        // ===== GEMM3: Xnew = Xc @ P'^T + po, 3-term split, K=256 =====
        {
            const float* po = g_po + layer*Dd;
            #pragma unroll
            for (int nt = 0; nt < 4; nt++) {
                int c = c_base + nt*8;
                float f0 = __ldg(po + c), f1 = __ldg(po + c + 1);
                #pragma unroll
                for (int mt = 0; mt < 2; mt++) {
                    cacc[mt][nt][0] = f0; cacc[mt][nt][1] = f1;
                    cacc[mt][nt][2] = f0; cacc[mt][nt][3] = f1;
                }
            }
            #pragma unroll 1
            for (int ch = 0; ch < 4; ch++) {
                CP_WAIT0; __syncthreads();
                if (ch + 1 < 4) {
                    char* nxt = bw + ((ch+1)&1)*65536;
                    stage32(nxt,         phimg + (ch+1)*16384, tid);
                    stage32(nxt + 32768, plimg + (ch+1)*16384, tid); CP_COMMIT;
                } else if (layer + 1 < Lc) {
                    // prefetch next layer's GEMM1 chunk0 into buf0
                    stage32(bw, g_w1t + (size_t)(layer+1)*32768, tid); CP_COMMIT;
                }
                uint32_t cur = BWu + (uint32_t)((ch & 1) * 65536);
                #pragma unroll
                for (int ks = 0; ks < 64; ks += 16) {
                    int gA = (ch << 3) + (ks >> 3) + laneHi;
                    uint32_t Ah[2][4], Al[2][4], Bh[2][4], Bl[2][4];
                    #pragma unroll
                    for (int mt = 0; mt < 2; mt++) {
                        uint32_t abase = (uint32_t)((mrow0 + mt*16)*512 + aRowB + ((gA ^ key) << 4));
                        LDSM4(Ah[mt][0], Ah[mt][1], Ah[mt][2], Ah[mt][3], XHI + abase);
                        LDSM4(Al[mt][0], Al[mt][1], Al[mt][2], Al[mt][3], XLO + abase);
                    }
                    uint32_t bsw = (uint32_t)(((((ks >> 3) + bsel) ^ key) << 4));
                    LDSM4(Bh[0][0], Bh[0][1], Bh[0][2], Bh[0][3], cur + (uint32_t)bRow0 + bsw);
                    LDSM4(Bh[1][0], Bh[1][1], Bh[1][2], Bh[1][3], cur + (uint32_t)bRow1 + bsw);
                    LDSM4(Bl[0][0], Bl[0][1], Bl[0][2], Bl[0][3], cur + 32768u + (uint32_t)bRow0 + bsw);
                    LDSM4(Bl[1][0], Bl[1][1], Bl[1][2], Bl[1][3], cur + 32768u + (uint32_t)bRow1 + bsw);
                    #pragma unroll
                    for (int p = 0; p < 2; p++)
                        #pragma unroll
                        for (int q = 0; q < 2; q++) {
                            int nt = p*2 + q;
                            #pragma unroll
                            for (int mt = 0; mt < 2; mt++) {
                                MMA(cacc[mt][nt], Ah[mt][0], Ah[mt][1], Ah[mt][2], Ah[mt][3], Bh[p][q*2], Bh[p][q*2+1]);
                                MMA(cacc[mt][nt], Al[mt][0], Al[mt][1], Al[mt][2], Al[mt][3], Bh[p][q*2], Bh[p][q*2+1]);
                                MMA(cacc[mt][nt], Ah[mt][0], Ah[mt][1], Ah[mt][2], Ah[mt][3], Bl[p][q*2], Bl[p][q*2+1]);
                            }
                        }
                }
            }
            __syncthreads();   // all warps done reading XHI/XLO before overwrite

            if (layer + 1 < Lc) {
                // split accumulators straight back into XHI/XLO (stay resident)
                #pragma unroll
                for (int nt = 0; nt < 4; nt++) {
                    int c = c_base + nt*8;
                    int csw = ((c >> 3) ^ g) << 4;
                    #pragma unroll
                    for (int mt = 0; mt < 2; mt++) {
                        float* cf = cacc[mt][nt];
                        #pragma unroll
                        for (int half = 0; half < 2; half++) {
                            int r = mrow0 + mt*16 + g + half*8;
                            uint32_t hw, lw;
                            split2(cf[half*2 + 0], cf[half*2 + 1], hw, lw);
                            *(uint32_t*)(smem + XHIo + r*512 + csw + 4*t) = hw;
                            *(uint32_t*)(smem + XLOo + r*512 + csw + 4*t) = lw;
                        }
                    }
                }
            } else {
                // final layer: write z fp32 to gmem
                #pragma unroll
                for (int mt = 0; mt < 2; mt++)
                    #pragma unroll
                    for (int half = 0; half < 2; half++) {
                        int r = blockIdx.x * MROW + mrow0 + mt*16 + g + half*8;
                        #pragma unroll
                        for (int nt = 0; nt < 4; nt++) {
                            int c = c_base + nt*8;
                            float* cf = cacc[mt][nt];
                            *(float2*)(zout + (size_t)r*Dd + c) =
                                make_float2(cf[half*2 + 0], cf[half*2 + 1]);
                        }
                    }
            }
        }
    }

    if (tid < MROW) g_ld[blockIdx.x * MROW + tid] = ldacc;
}

// ---------------- head: h = z@Wh1 + bh1 (3-term) + BN partials ----------------
__global__ void __launch_bounds__(NTHR, 1) head_hmma(
    const float* __restrict__ z, float* __restrict__ h,
    const float* __restrict__ bh1)
{
    extern __shared__ char smem[];
    const uint32_t su = (uint32_t)__cvta_generic_to_shared(smem);
    const uint32_t XHI = su + XHIo, XLO = su + XLOo, BWu = su + BWo;
    char* bw = smem + BWo;

    const int tid = threadIdx.x, lane = tid & 31, wid = tid >> 5;
    const int warpM = wid >> 3, warpN = wid & 7;
    const int g = lane >> 2, t = lane & 3;
    const int mrow0 = warpM * 32;
    const int n0 = warpN * 32;
    const int laneHi = lane >> 4;
    const int key = lane & 7;
    const int aRowB = (lane & 15) * 512;
    const int nloc = ((lane >> 4) << 3) + (lane & 7);
    const int bRow0 = (n0 + nloc) * 128, bRow1 = (n0 + 16 + nloc) * 128;
    const int bsel = (lane >> 3) & 1;
    const int c_base = n0 + 2*t;

    stage32(bw,         g_whh, tid);
    stage32(bw + 32768, g_whl, tid); CP_COMMIT;

    {
        const float4* src = (const float4*)(z + (size_t)blockIdx.x * MROW * Dd);
        #pragma unroll
        for (int i = tid; i < MROW * Dd / 4; i += NTHR) {
            int r = i >> 6, c = (i & 63) * 4;
            float4 v = src[i];
            uint32_t h0, l0, h1, l1;
            split2(v.x, v.y, h0, l0);
            split2(v.z, v.w, h1, l1);
            int off = r*512 + (((c >> 3) ^ (r & 7)) << 4) + (c & 7)*2;
            *(uint2*)(smem + XHIo + off) = make_uint2(h0, h1);
            *(uint2*)(smem + XLOo + off) = make_uint2(l0, l1);
        }
    }

    float cacc[2][4][4];
    #pragma unroll
    for (int nt = 0; nt < 4; nt++) {
        int c = c_base + nt*8;
        float f0 = __ldg(bh1 + c), f1 = __ldg(bh1 + c + 1);
        #pragma unroll
        for (int mt = 0; mt < 2; mt++) {
            cacc[mt][nt][0] = f0; cacc[mt][nt][1] = f1;
            cacc[mt][nt][2] = f0; cacc[mt][nt][3] = f1;
        }
    }

    for (int ch = 0; ch < 4; ch++) {
        CP_WAIT0; __syncthreads();
        if (ch + 1 < 4) {
            char* nxt = bw + ((ch+1)&1)*65536;
            stage32(nxt,         g_whh + (ch+1)*16384, tid);
            stage32(nxt + 32768, g_whl + (ch+1)*16384, tid); CP_COMMIT;
        }
        uint32_t cur = BWu + (uint32_t)((ch & 1) * 65536);
        #pragma unroll
        for (int ks = 0; ks < 64; ks += 16) {
            int gA = (ch << 3) + (ks >> 3) + laneHi;
            uint32_t Ah[2][4], Al[2][4], Bh[2][4], Bl[2][4];
            #pragma unroll
            for (int mt = 0; mt < 2; mt++) {
                uint32_t abase = (uint32_t)((mrow0 + mt*16)*512 + aRowB + ((gA ^ key) << 4));
                LDSM4(Ah[mt][0], Ah[mt][1], Ah[mt][2], Ah[mt][3], XHI + abase);
                LDSM4(Al[mt][0], Al[mt][1], Al[mt][2], Al[mt][3], XLO + abase);
            }
            uint32_t bsw = (uint32_t)(((((ks >> 3) + bsel) ^ key) << 4));
            LDSM4(Bh[0][0], Bh[0][1], Bh[0][2], Bh[0][3], cur + (uint32_t)bRow0 + bsw);
            LDSM4(Bh[1][0], Bh[1][1], Bh[1][2], Bh[1][3], cur + (uint32_t)bRow1 + bsw);
            LDSM4(Bl[0][0], Bl[0][1], Bl[0][2], Bl[0][3], cur + 32768u + (uint32_t)bRow0 + bsw);
            LDSM4(Bl[1][0], Bl[1][1], Bl[1][2], Bl[1][3], cur + 32768u + (uint32_t)bRow1 + bsw);
            #pragma unroll
            for (int p = 0; p < 2; p++)
                #pragma unroll
                for (int q = 0; q < 2; q++) {
                    int nt = p*2 + q;
                    #pragma unroll
                    for (int mt = 0; mt < 2; mt++) {
                        MMA(cacc[mt][nt], Ah[mt][0], Ah[mt][1], Ah[mt][2], Ah[mt][3], Bh[p][q*2], Bh[p][q*2+1]);
                        MMA(cacc[mt][nt], Al[mt][0], Al[mt][1], Al[mt][2], Al[mt][3], Bh[p][q*2], Bh[p][q*2+1]);
                        MMA(cacc[mt][nt], Ah[mt][0], Ah[mt][1], Ah[mt][2], Ah[mt][3], Bl[p][q*2], Bl[p][q*2+1]);
                    }
                }
        }
    }

    float* stg = (float*)smem;   // [64][264] fp32 overlay
    __syncthreads();
    #pragma unroll
    for (int mt = 0; mt < 2; mt++)
        #pragma unroll
        for (int half = 0; half < 2; half++) {
            int rl = mrow0 + mt*16 + g + half*8;
            int r  = blockIdx.x * MROW + rl;
            #pragma unroll
            for (int nt = 0; nt < 4; nt++) {
                int c = c_base + nt*8;
                float* cf = cacc[mt][nt];
                float v0 = cf[half*2 + 0];
                float v1 = cf[half*2 + 1];
                *(float2*)(h + (size_t)r*Dd + c) = make_float2(v0, v1);
                stg[(size_t)rl*264 + c]     = v0;
                stg[(size_t)rl*264 + c + 1] = v1;
            }
        }
    __syncthreads();
    if (tid < Dd) {
        float s = 0.f, q = 0.f;
        #pragma unroll 4
        for (int r = 0; r < MROW; r++) {
            float v = stg[(size_t)r*264 + tid];
            s += v; q += v * v;
        }
        g_part[(size_t)blockIdx.x*2*Dd + tid]      = s;
        g_part[(size_t)blockIdx.x*2*Dd + Dd + tid] = q;
    }
}

// ---------------- BN stats fold ----------------
__global__ void stats_kernel(const float* __restrict__ gamma, const float* __restrict__ beta) {
    int c = threadIdx.x;
    float s0=0.f,s1=0.f,s2=0.f,s3=0.f, q0=0.f,q1=0.f,q2=0.f,q3=0.f;
    for (int i = 0; i < NBLK; i += 4) {
        s0 += g_part[(size_t)(i+0)*2*Dd + c];   q0 += g_part[(size_t)(i+0)*2*Dd + Dd + c];
        s1 += g_part[(size_t)(i+1)*2*Dd + c];   q1 += g_part[(size_t)(i+1)*2*Dd + Dd + c];
        s2 += g_part[(size_t)(i+2)*2*Dd + c];   q2 += g_part[(size_t)(i+2)*2*Dd + Dd + c];
        s3 += g_part[(size_t)(i+3)*2*Dd + c];   q3 += g_part[(size_t)(i+3)*2*Dd + Dd + c];
    }
    float s = (s0+s1)+(s2+s3), q = (q0+q1)+(q2+q3);
    float mu  = s * (1.f/Bsz);
    float var = q * (1.f/Bsz) - mu*mu;
    float a = gamma[c] * rsqrtf(var + BN_EPS);
    g_stats[c]      = a;
    g_stats[Dd + c] = beta[c] - mu * a;
}

// ---------------- log_px ----------------
__global__ void logpx_kernel(const float* __restrict__ z, float* __restrict__ out) {
    int warp = threadIdx.x >> 5, lane = threadIdx.x & 31;
    size_t row = (size_t)blockIdx.x * 8 + warp;
    const float4* zr = (const float4*)(z + row*Dd);
    float4 v0 = zr[lane*2], v1 = zr[lane*2 + 1];
    float ss = v0.x*v0.x + v0.y*v0.y + v0.z*v0.z + v0.w*v0.w
             + v1.x*v1.x + v1.y*v1.y + v1.z*v1.z + v1.w*v1.w;
    #pragma unroll
    for (int o = 16; o; o >>= 1) ss += __shfl_down_sync(0xffffffffu, ss, o);
    if (lane == 0)
        out[row] = (DGCONST - 0.5f*ss + g_ld[row]) * (1.0f/Dd);
}

// ---------------- logits ----------------
__global__ void __launch_bounds__(256) logits_kernel(
    const float* __restrict__ h, const float* __restrict__ Wh2,
    const float* __restrict__ bh2, float* __restrict__ out)
{
    __shared__ float w2s[Dd*NCc];
    __shared__ float As[Dd], Bs[Dd];
    int tid = threadIdx.x;
    for (int i = tid; i < Dd*NCc; i += 256) w2s[i] = Wh2[i];
    if (tid < Dd) { As[tid] = g_stats[tid]; Bs[tid] = g_stats[Dd + tid]; }
    __syncthreads();

    int warp = tid >> 5, lane = tid & 31;
    size_t row = (size_t)blockIdx.x * 8 + warp;
    const float4* hr = (const float4*)(h + row*Dd);
    float4 v0 = hr[lane*2], v1 = hr[lane*2 + 1];
    int k0 = lane * 8;
    float hn[8];
    hn[0] = fmaxf(v0.x*As[k0+0] + Bs[k0+0], 0.f);
    hn[1] = fmaxf(v0.y*As[k0+1] + Bs[k0+1], 0.f);
    hn[2] = fmaxf(v0.z*As[k0+2] + Bs[k0+2], 0.f);
    hn[3] = fmaxf(v0.w*As[k0+3] + Bs[k0+3], 0.f);
    hn[4] = fmaxf(v1.x*As[k0+4] + Bs[k0+4], 0.f);
    hn[5] = fmaxf(v1.y*As[k0+5] + Bs[k0+5], 0.f);
    hn[6] = fmaxf(v1.z*As[k0+6] + Bs[k0+6], 0.f);
    hn[7] = fmaxf(v1.w*As[k0+7] + Bs[k0+7], 0.f);

    float acc[NCc];
    #pragma unroll
    for (int c = 0; c < NCc; c++) acc[c] = 0.f;
    #pragma unroll
    for (int kk = 0; kk < 8; kk++) {
        float x = hn[kk];
        const float* wr = &w2s[(k0+kk)*NCc];
        #pragma unroll
        for (int c = 0; c < NCc; c++) acc[c] += x * wr[c];
    }
    #pragma unroll
    for (int c = 0; c < NCc; c++) {
        #pragma unroll
        for (int o = 16; o; o >>= 1) acc[c] += __shfl_down_sync(0xffffffffu, acc[c], o);
    }
    if (lane == 0) {
        #pragma unroll
        for (int c = 0; c < NCc; c++) out[row*NCc + c] = acc[c] + __ldg(bh2 + c);
    }
}

// ---------------- launch ----------------
extern "C" void kernel_launch(void* const* d_in, const int* in_sizes, int n_in,
                              void* d_out, int out_size)
{
    const float* feat  = (const float*)d_in[0];
    const float* W1    = (const float*)d_in[1];
    const float* b1    = (const float*)d_in[2];
    const float* W2    = (const float*)d_in[3];
    const float* b2    = (const float*)d_in[4];
    const float* gs    = (const float*)d_in[5];
    const float* go    = (const float*)d_in[6];
    const float* P     = (const float*)d_in[7];
    const float* Wh1   = (const float*)d_in[8];
    const float* bh1   = (const float*)d_in[9];
    const float* gamma = (const float*)d_in[10];
    const float* beta  = (const float*)d_in[11];
    const float* Wh2   = (const float*)d_in[12];
    const float* bh2   = (const float*)d_in[13];
    float* out = (float*)d_out;

    cudaFuncSetAttribute(flow_fused, cudaFuncAttributeMaxDynamicSharedMemorySize, SMEMSZ);
    cudaFuncSetAttribute(head_hmma,  cudaFuncAttributeMaxDynamicSharedMemorySize, SMEMSZ);

    float *bufA = nullptr, *bufB = nullptr;
    cudaGetSymbolAddress((void**)&bufA, g_bufA);
    cudaGetSymbolAddress((void**)&bufB, g_bufB);

    prep_scale<<<Lc, 256>>>(gs);
    prep_w1t<<<(Lc*256*128)/256, 256>>>(W1);
    prep_w2t<<<(Lc*256*256)/256, 256>>>(W2);
    prep_pt <<<(Lc*256*256)/256, 256>>>(P);
    prep_po <<<Lc, 256>>>(P, go);
    prep_wht<<<(256*256)/256, 256>>>(Wh1);

    flow_fused<<<NBLK, NTHR, SMEMSZ>>>(feat, bufB, b1, b2);

    head_hmma<<<NBLK, NTHR, SMEMSZ>>>(bufB, bufA, bh1);
    stats_kernel<<<1, 256>>>(gamma, beta);
    logpx_kernel<<<Bsz/8, 256>>>(bufB, out);
    logits_kernel<<<Bsz/8, 256>>>(bufA, Wh2, bh2, out + Bsz);
}

// round 9
// speedup vs baseline: 4.9784x; 1.0543x over previous
#include <cuda_runtime.h>
#include <cuda_bf16.h>
#include <math.h>
#include <stdint.h>

// ---------------- problem constants ----------------
#define Bsz   131072
#define Dd    256
#define Lc    8
#define NCc   10
#define BN_EPS 1e-5f
#define DGCONST -235.24826450039622f   // D * GCONST

#define MROW  64
#define NTHR  512
#define NBLK  (Bsz/MROW)      // 2048 CTAs

// smem byte offsets (all swizzled images, no padding)
#define XHIo 0
#define XLOo 32768
#define HBo  65536
#define BWo  98304            // 2 x 65536
#define SMEMSZ 229376

// ---------------- static device scratch ----------------
__device__ float g_bufA[(size_t)Bsz*Dd];
__device__ float g_bufB[(size_t)Bsz*Dd];
__device__ float g_ld[Bsz];
__device__ float g_scale[Lc*Dd];
__device__ float g_sumlog[Lc];
__device__ float g_po[Lc*Dd];
__device__ float g_part[(size_t)NBLK*2*Dd];
__device__ float g_stats[2*Dd];
// pre-swizzled bf16 weight images (chunked K=64 smem layout)
__device__ __nv_bfloat16 g_w1t[(size_t)Lc*32768];
__device__ __nv_bfloat16 g_w2t[(size_t)Lc*65536];
__device__ __nv_bfloat16 g_ph [(size_t)Lc*65536];   // P' = P*diag(scale), hi
__device__ __nv_bfloat16 g_pl [(size_t)Lc*65536];
__device__ __nv_bfloat16 g_whh[65536];
__device__ __nv_bfloat16 g_whl[65536];

// ---------------- helpers ----------------
__device__ __forceinline__ uint32_t packbf2(float a, float b) {
    __nv_bfloat162 t = __floats2bfloat162_rn(a, b);
    return *(uint32_t*)&t;
}
__device__ __forceinline__ float2 unpackbf2(uint32_t w) {
    __nv_bfloat162 t = *(__nv_bfloat162*)&w;
    return __bfloat1622float2(t);
}
__device__ __forceinline__ void split2(float a, float b, uint32_t& hw, uint32_t& lw) {
    __nv_bfloat16 ha = __float2bfloat16(a), hb = __float2bfloat16(b);
    float la = a - __bfloat162float(ha), lb = b - __bfloat162float(hb);
    __nv_bfloat162 h; h.x = ha; h.y = hb;
    hw = *(uint32_t*)&h;
    lw = packbf2(la, lb);
}
__device__ __forceinline__ float fast_tanh_scaled(float a) {
    float e = __expf(-0.2f * a);
    return 1.9f * __fdividef(1.f - e, 1.f + e);
}
__device__ __forceinline__ void cpab(void* dst_smem, const void* src) {
    unsigned s = (unsigned)__cvta_generic_to_shared(dst_smem);
    asm volatile("cp.async.cg.shared.global [%0], [%1], 16;" :: "r"(s), "l"(src));
}
#define CP_COMMIT asm volatile("cp.async.commit_group;")
#define CP_WAIT0  asm volatile("cp.async.wait_group 0;")

#define MMA(cd, a0, a1, a2, a3, b0, b1) \
    asm volatile("mma.sync.aligned.m16n8k16.row.col.f32.bf16.bf16.f32 " \
        "{%0,%1,%2,%3}, {%4,%5,%6,%7}, {%8,%9}, {%0,%1,%2,%3};" \
        : "+f"((cd)[0]), "+f"((cd)[1]), "+f"((cd)[2]), "+f"((cd)[3]) \
        : "r"(a0), "r"(a1), "r"(a2), "r"(a3), "r"(b0), "r"(b1))

#define LDSM4(r0, r1, r2, r3, addr) \
    asm volatile("ldmatrix.sync.aligned.m8n8.x4.shared.b16 {%0,%1,%2,%3}, [%4];" \
        : "=r"(r0), "=r"(r1), "=r"(r2), "=r"(r3) : "r"(addr))

__device__ __forceinline__ void stage32(char* dst, const __nv_bfloat16* src, int tid) {
    const char* s = (const char*)src;
    #pragma unroll
    for (int i = 0; i < 4; i++) cpab(dst + tid*16 + i*8192, s + tid*16 + i*8192);
}
__device__ __forceinline__ int imgoff(int n, int k) {
    return n*64 + (((k >> 3) ^ (n & 7)) << 3) + (k & 7);
}

// ---------------- preprocessing (3 launches) ----------------
__global__ void prep_scale(const float* __restrict__ gs) {
    __shared__ float red[256];
    int l = blockIdx.x, d = threadIdx.x;
    float x  = 0.5f * gs[l*Dd + d];
    float sp = (x > 20.f) ? x : log1pf(expf(x));
    float s  = 0.2f * sp;
    g_scale[l*Dd + d] = s;
    red[d] = logf(s);
    __syncthreads();
    #pragma unroll
    for (int o = 128; o; o >>= 1) { if (d < o) red[d] += red[d + o]; __syncthreads(); }
    if (d == 0) g_sumlog[l] = red[0];
}
__global__ void prep_wimg(const float* __restrict__ W1, const float* __restrict__ W2,
                          const float* __restrict__ Wh1) {
    int idx = blockIdx.x * 256 + threadIdx.x;
    if (idx < Lc*32768) {
        int k = idx & 127, n = (idx >> 7) & 255, l = idx >> 15;
        g_w1t[(size_t)l*32768 + (k>>6)*16384 + imgoff(n, k & 63)] =
            __float2bfloat16(W1[((size_t)l*128 + k)*256 + n]);
    } else if (idx < Lc*32768 + Lc*65536) {
        int j = idx - Lc*32768;
        int k = j & 255, n = (j >> 8) & 255, l = j >> 16;
        g_w2t[(size_t)l*65536 + (k>>6)*16384 + imgoff(n, k & 63)] =
            __float2bfloat16(W2[((size_t)l*256 + k)*256 + n]);
    } else {
        int j = idx - (Lc*32768 + Lc*65536);
        int k = j & 255, n = j >> 8;
        float v = Wh1[(size_t)k*256 + n];
        __nv_bfloat16 hi = __float2bfloat16(v);
        size_t o = (size_t)(k>>6)*16384 + imgoff(n, k & 63);
        g_whh[o] = hi;
        g_whl[o] = __float2bfloat16(v - __bfloat162float(hi));
    }
}
__global__ void prep_pimg(const float* __restrict__ P, const float* __restrict__ go) {
    int idx = blockIdx.x * 256 + threadIdx.x;
    if (idx < Lc*65536) {
        int k = idx & 255, n = (idx >> 8) & 255, l = idx >> 16;
        float v = P[((size_t)l*256 + n)*256 + k] * g_scale[l*Dd + k];
        __nv_bfloat16 hi = __float2bfloat16(v);
        size_t o = (size_t)l*65536 + (k>>6)*16384 + imgoff(n, k & 63);
        g_ph[o] = hi;
        g_pl[o] = __float2bfloat16(v - __bfloat162float(hi));
    } else {
        int j = idx - Lc*65536;
        int l = j >> 8, n = j & 255;
        const float* pr = P + ((size_t)l*256 + n)*256;
        const float* o  = go + l*Dd;
        float acc = 0.f;
        for (int k = 0; k < 256; k++) acc += o[k] * pr[k];
        g_po[l*Dd + n] = acc;
    }
}

// ---------------- fully fused flow (all 8 layers, x resident in smem) ----------------
__global__ void __launch_bounds__(NTHR, 1) flow_fused(
    const float* __restrict__ xin, float* __restrict__ zout,
    const float* __restrict__ b1, const float* __restrict__ b2)
{
    extern __shared__ char smem[];
    const uint32_t su = (uint32_t)__cvta_generic_to_shared(smem);
    const uint32_t XHI = su + XHIo, XLO = su + XLOo, HBu = su + HBo, BWu = su + BWo;
    char* bw = smem + BWo;

    const int tid = threadIdx.x, lane = tid & 31, wid = tid >> 5;
    const int warpM = wid >> 3, warpN = wid & 7;
    const int g = lane >> 2, t = lane & 3;
    const int mrow0 = warpM * 32;
    const int n0 = warpN * 32;
    const int laneHi = lane >> 4;
    const int key = lane & 7;
    const int aRowB = (lane & 15) * 512;
    const int nloc = ((lane >> 4) << 3) + (lane & 7);
    const int bRow0 = (n0 + nloc) * 128, bRow1 = (n0 + 16 + nloc) * 128;
    const int bsel = (lane >> 3) & 1;
    const int c_base = n0 + 2*t;

    // prologue: stage layer-0 W1 in full (64KB -> buf0 == wb(layer0))
    stage32(bw,         g_w1t,         tid);
    stage32(bw + 32768, g_w1t + 16384, tid); CP_COMMIT;

    // load + split input x once
    {
        const float4* src = (const float4*)(xin + (size_t)blockIdx.x * MROW * Dd);
        #pragma unroll
        for (int i = tid; i < MROW * Dd / 4; i += NTHR) {
            int r = i >> 6, c = (i & 63) * 4;
            float4 v = src[i];
            uint32_t h0, l0, h1, l1;
            split2(v.x, v.y, h0, l0);
            split2(v.z, v.w, h1, l1);
            int off = r*512 + (((c >> 3) ^ (r & 7)) << 4) + (c & 7)*2;
            *(uint2*)(smem + XHIo + off) = make_uint2(h0, h1);
            *(uint2*)(smem + XLOo + off) = make_uint2(l0, l1);
        }
    }

    float cacc[2][4][4];
    float ldacc = 0.f;

    #pragma unroll 1
    for (int layer = 0; layer < Lc; layer++) {
        const float* bb1 = b1 + layer*Dd;
        const float* bb2 = b2 + layer*Dd;
        const __nv_bfloat16* w2img = g_w2t + (size_t)layer*65536;
        const __nv_bfloat16* phimg = g_ph  + (size_t)layer*65536;
        const __nv_bfloat16* plimg = g_pl  + (size_t)layer*65536;
        // W1-resident buffer alternates per layer; ob is the other buffer
        const uint32_t wbo = (uint32_t)((layer & 1) * 65536);
        const uint32_t obo = 65536u - wbo;

        // ===== GEMM1: H = relu(x1_hi @ W1 + b1), K=128, whole W1 in wb =====
        #pragma unroll
        for (int nt = 0; nt < 4; nt++) {
            int c = c_base + nt*8;
            float f0 = __ldg(bb1 + c), f1 = __ldg(bb1 + c + 1);
            #pragma unroll
            for (int mt = 0; mt < 2; mt++) {
                cacc[mt][nt][0] = f0; cacc[mt][nt][1] = f1;
                cacc[mt][nt][2] = f0; cacc[mt][nt][3] = f1;
            }
        }
        CP_WAIT0; __syncthreads();                                   // S1: W1 ready
        // prefetch W2 k[0:128) -> ob during GEMM1 compute
        stage32(bw + obo,         w2img,         tid);
        stage32(bw + obo + 32768, w2img + 16384, tid); CP_COMMIT;
        #pragma unroll
        for (int kk = 0; kk < 8; kk++) {
            int gA = kk*2 + laneHi;
            uint32_t A[2][4], B[2][4];
            #pragma unroll
            for (int mt = 0; mt < 2; mt++)
                LDSM4(A[mt][0], A[mt][1], A[mt][2], A[mt][3],
                      XHI + (uint32_t)((mrow0 + mt*16)*512 + aRowB + ((gA ^ key) << 4)));
            uint32_t bb = BWu + wbo + (uint32_t)((kk >> 2) * 32768);
            uint32_t bsw = (uint32_t)(((((kk & 3)*2) + bsel) ^ key) << 4);
            LDSM4(B[0][0], B[0][1], B[0][2], B[0][3], bb + (uint32_t)bRow0 + bsw);
            LDSM4(B[1][0], B[1][1], B[1][2], B[1][3], bb + (uint32_t)bRow1 + bsw);
            #pragma unroll
            for (int p = 0; p < 2; p++)
                #pragma unroll
                for (int q = 0; q < 2; q++) {
                    int nt = p*2 + q;
                    MMA(cacc[0][nt], A[0][0], A[0][1], A[0][2], A[0][3], B[p][q*2], B[p][q*2+1]);
                    MMA(cacc[1][nt], A[1][0], A[1][1], A[1][2], A[1][3], B[p][q*2], B[p][q*2+1]);
                }
        }
        // relu -> HB
        #pragma unroll
        for (int nt = 0; nt < 4; nt++) {
            int c = c_base + nt*8;
            int csw = ((c >> 3) ^ g) << 4;
            #pragma unroll
            for (int mt = 0; mt < 2; mt++) {
                int r = mrow0 + mt*16 + g;
                float* cf = cacc[mt][nt];
                *(uint32_t*)(smem + HBo + r*512     + csw + 4*t) =
                    packbf2(fmaxf(cf[0], 0.f), fmaxf(cf[1], 0.f));
                *(uint32_t*)(smem + HBo + (r+8)*512 + csw + 4*t) =
                    packbf2(fmaxf(cf[2], 0.f), fmaxf(cf[3], 0.f));
            }
        }

        // ===== GEMM2: A2 = H @ W2 + b2, K=256, 2 chunks of 128k =====
        #pragma unroll
        for (int nt = 0; nt < 4; nt++) {
            int c = c_base + nt*8;
            float f0 = __ldg(bb2 + c), f1 = __ldg(bb2 + c + 1);
            #pragma unroll
            for (int mt = 0; mt < 2; mt++) {
                cacc[mt][nt][0] = f0; cacc[mt][nt][1] = f1;
                cacc[mt][nt][2] = f0; cacc[mt][nt][3] = f1;
            }
        }
        #pragma unroll 1
        for (int half2 = 0; half2 < 2; half2++) {
            CP_WAIT0; __syncthreads();                               // S2 / S3
            if (half2 == 0) {
                // prefetch W2 k[128:256) -> wb (W1 dead)
                stage32(bw + wbo,         w2img + 32768, tid);
                stage32(bw + wbo + 32768, w2img + 49152, tid); CP_COMMIT;
            } else {
                // prefetch P chunk0 (hi+lo) -> ob (W2c0 dead)
                stage32(bw + obo,         phimg, tid);
                stage32(bw + obo + 32768, plimg, tid); CP_COMMIT;
            }
            uint32_t cur = BWu + ((half2 == 0) ? obo : wbo);
            #pragma unroll
            for (int kk = 0; kk < 8; kk++) {
                int gA = half2*16 + kk*2 + laneHi;
                uint32_t A[2][4], B[2][4];
                #pragma unroll
                for (int mt = 0; mt < 2; mt++)
                    LDSM4(A[mt][0], A[mt][1], A[mt][2], A[mt][3],
                          HBu + (uint32_t)((mrow0 + mt*16)*512 + aRowB + ((gA ^ key) << 4)));
                uint32_t bb = cur + (uint32_t)((kk >> 2) * 32768);
                uint32_t bsw = (uint32_t)(((((kk & 3)*2) + bsel) ^ key) << 4);
                LDSM4(B[0][0], B[0][1], B[0][2], B[0][3], bb + (uint32_t)bRow0 + bsw);
                LDSM4(B[1][0], B[1][1], B[1][2], B[1][3], bb + (uint32_t)bRow1 + bsw);
                #pragma unroll
                for (int p = 0; p < 2; p++)
                    #pragma unroll
                    for (int q = 0; q < 2; q++) {
                        int nt = p*2 + q;
                        MMA(cacc[0][nt], A[0][0], A[0][1], A[0][2], A[0][3], B[p][q*2], B[p][q*2+1]);
                        MMA(cacc[1][nt], A[1][0], A[1][1], A[1][2], A[1][3], B[p][q*2], B[p][q*2+1]);
                    }
            }
        }
        CP_WAIT0; __syncthreads();                                   // S4: Pc0 ready; HB/wb reads done
        // prefetch P chunk1 -> wb (W2c1 dead)
        stage32(bw + wbo,         phimg + 16384, tid);
        stage32(bw + wbo + 32768, plimg + 16384, tid); CP_COMMIT;

        // ===== coupling epilogue =====
        if (warpN < 4) {
            #pragma unroll
            for (int nt = 0; nt < 4; nt++) {
                int c = c_base + nt*8;
                int csw = ((c >> 3) ^ g) << 4;
                #pragma unroll
                for (int mt = 0; mt < 2; mt++) {
                    float* cf = cacc[mt][nt];
                    #pragma unroll
                    for (int half = 0; half < 2; half++) {
                        int r = mrow0 + mt*16 + g + half*8;
                        float s0 = fast_tanh_scaled(cf[half*2 + 0]);
                        float s1 = fast_tanh_scaled(cf[half*2 + 1]);
                        *(uint32_t*)(smem + HBo + r*512 + csw + 4*t) = packbf2(s0, s1);
                    }
                }
            }
        }
        __syncthreads();                                             // S5
        if (warpN >= 4) {
            #pragma unroll
            for (int nt = 0; nt < 4; nt++) {
                int c = c_base + nt*8;
                int csw  = ((c >> 3) ^ g) << 4;
                int ssw  = (((c - 128) >> 3) ^ g) << 4;
                #pragma unroll
                for (int mt = 0; mt < 2; mt++) {
                    float* cf = cacc[mt][nt];
                    #pragma unroll
                    for (int half = 0; half < 2; half++) {
                        int r = mrow0 + mt*16 + g + half*8;
                        float a20 = 0.1f * cf[half*2 + 0];
                        float a21 = 0.1f * cf[half*2 + 1];
                        float2 sv = unpackbf2(*(uint32_t*)(smem + HBo + r*512 + ssw + 4*t));
                        int xo = r*512 + csw + 4*t;
                        float2 hv = unpackbf2(*(uint32_t*)(smem + XHIo + xo));
                        float2 lv = unpackbf2(*(uint32_t*)(smem + XLOo + xo));
                        float v0 = (hv.x + lv.x) * __expf(sv.x) + a20;
                        float v1 = (hv.y + lv.y) * __expf(sv.y) + a21;
                        uint32_t hw, lw; split2(v0, v1, hw, lw);
                        *(uint32_t*)(smem + XHIo + xo) = hw;
                        *(uint32_t*)(smem + XLOo + xo) = lw;
                    }
                }
            }
        } else if (tid < MROW) {
            float rs = 0.f;
            int rk = tid & 7;
            #pragma unroll
            for (int gi = 0; gi < 16; gi++) {
                int gg = (gi + tid) & 15;
                uint4 w = *(uint4*)(smem + HBo + tid*512 + ((gg ^ rk) << 4));
                float2 p0 = unpackbf2(w.x), p1 = unpackbf2(w.y),
                       p2 = unpackbf2(w.z), p3 = unpackbf2(w.w);
                rs += (p0.x + p0.y) + (p1.x + p1.y) + (p2.x + p2.y) + (p3.x + p3.y);
            }
            ldacc += rs + g_sumlog[layer];
        }

        // ===== GEMM3: Xnew = Xc @ P'^T + po, 3-term split, K=256 =====
        // chunk buffers: ch0->ob(Pc0), ch1->wb(Pc1), ch2->ob(Pc2), ch3->wb(Pc3)
        {
            const float* po = g_po + layer*Dd;
            #pragma unroll
            for (int nt = 0; nt < 4; nt++) {
                int c = c_base + nt*8;
                float f0 = __ldg(po + c), f1 = __ldg(po + c + 1);
                #pragma unroll
                for (int mt = 0; mt < 2; mt++) {
                    cacc[mt][nt][0] = f0; cacc[mt][nt][1] = f1;
                    cacc[mt][nt][2] = f0; cacc[mt][nt][3] = f1;
                }
            }
            #pragma unroll 1
            for (int ch = 0; ch < 4; ch++) {
                if (ch > 0) {
                    CP_WAIT0; __syncthreads();                       // S6..S8
                    if (ch < 3) {
                        // stage P chunk ch+1 into the buffer ch+1 will read:
                        // ch1: Pc2 -> ob; ch2: Pc3 -> wb
                        uint32_t dsto = (ch == 1) ? obo : wbo;
                        stage32(bw + dsto,         phimg + (ch+1)*16384, tid);
                        stage32(bw + dsto + 32768, plimg + (ch+1)*16384, tid); CP_COMMIT;
                    } else if (layer + 1 < Lc) {
                        // prefetch next layer's W1 (full) -> ob  (= wb of next layer)
                        const __nv_bfloat16* w1n = g_w1t + (size_t)(layer+1)*32768;
                        stage32(bw + obo,         w1n,         tid);
                        stage32(bw + obo + 32768, w1n + 16384, tid); CP_COMMIT;
                    }
                }
                uint32_t cur = BWu + ((ch & 1) ? wbo : obo);
                #pragma unroll
                for (int ks = 0; ks < 64; ks += 16) {
                    int gA = (ch << 3) + (ks >> 3) + laneHi;
                    uint32_t Ah[2][4], Al[2][4], Bh[2][4], Bl[2][4];
                    #pragma unroll
                    for (int mt = 0; mt < 2; mt++) {
                        uint32_t abase = (uint32_t)((mrow0 + mt*16)*512 + aRowB + ((gA ^ key) << 4));
                        LDSM4(Ah[mt][0], Ah[mt][1], Ah[mt][2], Ah[mt][3], XHI + abase);
                        LDSM4(Al[mt][0], Al[mt][1], Al[mt][2], Al[mt][3], XLO + abase);
                    }
                    uint32_t bsw = (uint32_t)(((((ks >> 3) + bsel) ^ key) << 4));
                    LDSM4(Bh[0][0], Bh[0][1], Bh[0][2], Bh[0][3], cur + (uint32_t)bRow0 + bsw);
                    LDSM4(Bh[1][0], Bh[1][1], Bh[1][2], Bh[1][3], cur + (uint32_t)bRow1 + bsw);
                    LDSM4(Bl[0][0], Bl[0][1], Bl[0][2], Bl[0][3], cur + 32768u + (uint32_t)bRow0 + bsw);
                    LDSM4(Bl[1][0], Bl[1][1], Bl[1][2], Bl[1][3], cur + 32768u + (uint32_t)bRow1 + bsw);
                    #pragma unroll
                    for (int p = 0; p < 2; p++)
                        #pragma unroll
                        for (int q = 0; q < 2; q++) {
                            int nt = p*2 + q;
                            #pragma unroll
                            for (int mt = 0; mt < 2; mt++) {
                                MMA(cacc[mt][nt], Ah[mt][0], Ah[mt][1], Ah[mt][2], Ah[mt][3], Bh[p][q*2], Bh[p][q*2+1]);
                                MMA(cacc[mt][nt], Al[mt][0], Al[mt][1], Al[mt][2], Al[mt][3], Bh[p][q*2], Bh[p][q*2+1]);
                                MMA(cacc[mt][nt], Ah[mt][0], Ah[mt][1], Ah[mt][2], Ah[mt][3], Bl[p][q*2], Bl[p][q*2+1]);
                            }
                        }
                }
            }
            __syncthreads();                                         // S9: X reads done

            if (layer + 1 < Lc) {
                #pragma unroll
                for (int nt = 0; nt < 4; nt++) {
                    int c = c_base + nt*8;
                    int csw = ((c >> 3) ^ g) << 4;
                    #pragma unroll
                    for (int mt = 0; mt < 2; mt++) {
                        float* cf = cacc[mt][nt];
                        #pragma unroll
                        for (int half = 0; half < 2; half++) {
                            int r = mrow0 + mt*16 + g + half*8;
                            uint32_t hw, lw;
                            split2(cf[half*2 + 0], cf[half*2 + 1], hw, lw);
                            *(uint32_t*)(smem + XHIo + r*512 + csw + 4*t) = hw;
                            *(uint32_t*)(smem + XLOo + r*512 + csw + 4*t) = lw;
                        }
                    }
                }
            } else {
                #pragma unroll
                for (int mt = 0; mt < 2; mt++)
                    #pragma unroll
                    for (int half = 0; half < 2; half++) {
                        int r = blockIdx.x * MROW + mrow0 + mt*16 + g + half*8;
                        #pragma unroll
                        for (int nt = 0; nt < 4; nt++) {
                            int c = c_base + nt*8;
                            float* cf = cacc[mt][nt];
                            *(float2*)(zout + (size_t)r*Dd + c) =
                                make_float2(cf[half*2 + 0], cf[half*2 + 1]);
                        }
                    }
            }
        }
    }

    if (tid < MROW) g_ld[blockIdx.x * MROW + tid] = ldacc;
}

// ---------------- head: h = z@Wh1 + bh1 (3-term) + BN partials ----------------
__global__ void __launch_bounds__(NTHR, 1) head_hmma(
    const float* __restrict__ z, float* __restrict__ h,
    const float* __restrict__ bh1)
{
    extern __shared__ char smem[];
    const uint32_t su = (uint32_t)__cvta_generic_to_shared(smem);
    const uint32_t XHI = su + XHIo, XLO = su + XLOo, BWu = su + BWo;
    char* bw = smem + BWo;

    const int tid = threadIdx.x, lane = tid & 31, wid = tid >> 5;
    const int warpM = wid >> 3, warpN = wid & 7;
    const int g = lane >> 2, t = lane & 3;
    const int mrow0 = warpM * 32;
    const int n0 = warpN * 32;
    const int laneHi = lane >> 4;
    const int key = lane & 7;
    const int aRowB = (lane & 15) * 512;
    const int nloc = ((lane >> 4) << 3) + (lane & 7);
    const int bRow0 = (n0 + nloc) * 128, bRow1 = (n0 + 16 + nloc) * 128;
    const int bsel = (lane >> 3) & 1;
    const int c_base = n0 + 2*t;

    stage32(bw,         g_whh, tid);
    stage32(bw + 32768, g_whl, tid); CP_COMMIT;

    {
        const float4* src = (const float4*)(z + (size_t)blockIdx.x * MROW * Dd);
        #pragma unroll
        for (int i = tid; i < MROW * Dd / 4; i += NTHR) {
            int r = i >> 6, c = (i & 63) * 4;
            float4 v = src[i];
            uint32_t h0, l0, h1, l1;
            split2(v.x, v.y, h0, l0);
            split2(v.z, v.w, h1, l1);
            int off = r*512 + (((c >> 3) ^ (r & 7)) << 4) + (c & 7)*2;
            *(uint2*)(smem + XHIo + off) = make_uint2(h0, h1);
            *(uint2*)(smem + XLOo + off) = make_uint2(l0, l1);
        }
    }

    float cacc[2][4][4];
    #pragma unroll
    for (int nt = 0; nt < 4; nt++) {
        int c = c_base + nt*8;
        float f0 = __ldg(bh1 + c), f1 = __ldg(bh1 + c + 1);
        #pragma unroll
        for (int mt = 0; mt < 2; mt++) {
            cacc[mt][nt][0] = f0; cacc[mt][nt][1] = f1;
            cacc[mt][nt][2] = f0; cacc[mt][nt][3] = f1;
        }
    }

    for (int ch = 0; ch < 4; ch++) {
        CP_WAIT0; __syncthreads();
        if (ch + 1 < 4) {
            char* nxt = bw + ((ch+1)&1)*65536;
            stage32(nxt,         g_whh + (ch+1)*16384, tid);
            stage32(nxt + 32768, g_whl + (ch+1)*16384, tid); CP_COMMIT;
        }
        uint32_t cur = BWu + (uint32_t)((ch & 1) * 65536);
        #pragma unroll
        for (int ks = 0; ks < 64; ks += 16) {
            int gA = (ch << 3) + (ks >> 3) + laneHi;
            uint32_t Ah[2][4], Al[2][4], Bh[2][4], Bl[2][4];
            #pragma unroll
            for (int mt = 0; mt < 2; mt++) {
                uint32_t abase = (uint32_t)((mrow0 + mt*16)*512 + aRowB + ((gA ^ key) << 4));
                LDSM4(Ah[mt][0], Ah[mt][1], Ah[mt][2], Ah[mt][3], XHI + abase);
                LDSM4(Al[mt][0], Al[mt][1], Al[mt][2], Al[mt][3], XLO + abase);
            }
            uint32_t bsw = (uint32_t)(((((ks >> 3) + bsel) ^ key) << 4));
            LDSM4(Bh[0][0], Bh[0][1], Bh[0][2], Bh[0][3], cur + (uint32_t)bRow0 + bsw);
            LDSM4(Bh[1][0], Bh[1][1], Bh[1][2], Bh[1][3], cur + (uint32_t)bRow1 + bsw);
            LDSM4(Bl[0][0], Bl[0][1], Bl[0][2], Bl[0][3], cur + 32768u + (uint32_t)bRow0 + bsw);
            LDSM4(Bl[1][0], Bl[1][1], Bl[1][2], Bl[1][3], cur + 32768u + (uint32_t)bRow1 + bsw);
            #pragma unroll
            for (int p = 0; p < 2; p++)
                #pragma unroll
                for (int q = 0; q < 2; q++) {
                    int nt = p*2 + q;
                    #pragma unroll
                    for (int mt = 0; mt < 2; mt++) {
                        MMA(cacc[mt][nt], Ah[mt][0], Ah[mt][1], Ah[mt][2], Ah[mt][3], Bh[p][q*2], Bh[p][q*2+1]);
                        MMA(cacc[mt][nt], Al[mt][0], Al[mt][1], Al[mt][2], Al[mt][3], Bh[p][q*2], Bh[p][q*2+1]);
                        MMA(cacc[mt][nt], Ah[mt][0], Ah[mt][1], Ah[mt][2], Ah[mt][3], Bl[p][q*2], Bl[p][q*2+1]);
                    }
                }
        }
    }

    float* stg = (float*)smem;   // [64][264] fp32 overlay
    __syncthreads();
    #pragma unroll
    for (int mt = 0; mt < 2; mt++)
        #pragma unroll
        for (int half = 0; half < 2; half++) {
            int rl = mrow0 + mt*16 + g + half*8;
            int r  = blockIdx.x * MROW + rl;
            #pragma unroll
            for (int nt = 0; nt < 4; nt++) {
                int c = c_base + nt*8;
                float* cf = cacc[mt][nt];
                float v0 = cf[half*2 + 0];
                float v1 = cf[half*2 + 1];
                *(float2*)(h + (size_t)r*Dd + c) = make_float2(v0, v1);
                stg[(size_t)rl*264 + c]     = v0;
                stg[(size_t)rl*264 + c + 1] = v1;
            }
        }
    __syncthreads();
    if (tid < Dd) {
        float s = 0.f, q = 0.f;
        #pragma unroll 4
        for (int r = 0; r < MROW; r++) {
            float v = stg[(size_t)r*264 + tid];
            s += v; q += v * v;
        }
        g_part[(size_t)blockIdx.x*2*Dd + tid]      = s;
        g_part[(size_t)blockIdx.x*2*Dd + Dd + tid] = q;
    }
}

// ---------------- BN stats fold ----------------
__global__ void stats_kernel(const float* __restrict__ gamma, const float* __restrict__ beta) {
    int c = threadIdx.x;
    float s0=0.f,s1=0.f,s2=0.f,s3=0.f, q0=0.f,q1=0.f,q2=0.f,q3=0.f;
    for (int i = 0; i < NBLK; i += 4) {
        s0 += g_part[(size_t)(i+0)*2*Dd + c];   q0 += g_part[(size_t)(i+0)*2*Dd + Dd + c];
        s1 += g_part[(size_t)(i+1)*2*Dd + c];   q1 += g_part[(size_t)(i+1)*2*Dd + Dd + c];
        s2 += g_part[(size_t)(i+2)*2*Dd + c];   q2 += g_part[(size_t)(i+2)*2*Dd + Dd + c];
        s3 += g_part[(size_t)(i+3)*2*Dd + c];   q3 += g_part[(size_t)(i+3)*2*Dd + Dd + c];
    }
    float s = (s0+s1)+(s2+s3), q = (q0+q1)+(q2+q3);
    float mu  = s * (1.f/Bsz);
    float var = q * (1.f/Bsz) - mu*mu;
    float a = gamma[c] * rsqrtf(var + BN_EPS);
    g_stats[c]      = a;
    g_stats[Dd + c] = beta[c] - mu * a;
}

// ---------------- log_px ----------------
__global__ void logpx_kernel(const float* __restrict__ z, float* __restrict__ out) {
    int warp = threadIdx.x >> 5, lane = threadIdx.x & 31;
    size_t row = (size_t)blockIdx.x * 8 + warp;
    const float4* zr = (const float4*)(z + row*Dd);
    float4 v0 = zr[lane*2], v1 = zr[lane*2 + 1];
    float ss = v0.x*v0.x + v0.y*v0.y + v0.z*v0.z + v0.w*v0.w
             + v1.x*v1.x + v1.y*v1.y + v1.z*v1.z + v1.w*v1.w;
    #pragma unroll
    for (int o = 16; o; o >>= 1) ss += __shfl_down_sync(0xffffffffu, ss, o);
    if (lane == 0)
        out[row] = (DGCONST - 0.5f*ss + g_ld[row]) * (1.0f/Dd);
}

// ---------------- logits ----------------
__global__ void __launch_bounds__(256) logits_kernel(
    const float* __restrict__ h, const float* __restrict__ Wh2,
    const float* __restrict__ bh2, float* __restrict__ out)
{
    __shared__ float w2s[Dd*NCc];
    __shared__ float As[Dd], Bs[Dd];
    int tid = threadIdx.x;
    for (int i = tid; i < Dd*NCc; i += 256) w2s[i] = Wh2[i];
    if (tid < Dd) { As[tid] = g_stats[tid]; Bs[tid] = g_stats[Dd + tid]; }
    __syncthreads();

    int warp = tid >> 5, lane = tid & 31;
    size_t row = (size_t)blockIdx.x * 8 + warp;
    const float4* hr = (const float4*)(h + row*Dd);
    float4 v0 = hr[lane*2], v1 = hr[lane*2 + 1];
    int k0 = lane * 8;
    float hn[8];
    hn[0] = fmaxf(v0.x*As[k0+0] + Bs[k0+0], 0.f);
    hn[1] = fmaxf(v0.y*As[k0+1] + Bs[k0+1], 0.f);
    hn[2] = fmaxf(v0.z*As[k0+2] + Bs[k0+2], 0.f);
    hn[3] = fmaxf(v0.w*As[k0+3] + Bs[k0+3], 0.f);
    hn[4] = fmaxf(v1.x*As[k0+4] + Bs[k0+4], 0.f);
    hn[5] = fmaxf(v1.y*As[k0+5] + Bs[k0+5], 0.f);
    hn[6] = fmaxf(v1.z*As[k0+6] + Bs[k0+6], 0.f);
    hn[7] = fmaxf(v1.w*As[k0+7] + Bs[k0+7], 0.f);

    float acc[NCc];
    #pragma unroll
    for (int c = 0; c < NCc; c++) acc[c] = 0.f;
    #pragma unroll
    for (int kk = 0; kk < 8; kk++) {
        float x = hn[kk];
        const float* wr = &w2s[(k0+kk)*NCc];
        #pragma unroll
        for (int c = 0; c < NCc; c++) acc[c] += x * wr[c];
    }
    #pragma unroll
    for (int c = 0; c < NCc; c++) {
        #pragma unroll
        for (int o = 16; o; o >>= 1) acc[c] += __shfl_down_sync(0xffffffffu, acc[c], o);
    }
    if (lane == 0) {
        #pragma unroll
        for (int c = 0; c < NCc; c++) out[row*NCc + c] = acc[c] + __ldg(bh2 + c);
    }
}

// ---------------- launch ----------------
extern "C" void kernel_launch(void* const* d_in, const int* in_sizes, int n_in,
                              void* d_out, int out_size)
{
    const float* feat  = (const float*)d_in[0];
    const float* W1    = (const float*)d_in[1];
    const float* b1    = (const float*)d_in[2];
    const float* W2    = (const float*)d_in[3];
    const float* b2    = (const float*)d_in[4];
    const float* gs    = (const float*)d_in[5];
    const float* go    = (const float*)d_in[6];
    const float* P     = (const float*)d_in[7];
    const float* Wh1   = (const float*)d_in[8];
    const float* bh1   = (const float*)d_in[9];
    const float* gamma = (const float*)d_in[10];
    const float* beta  = (const float*)d_in[11];
    const float* Wh2   = (const float*)d_in[12];
    const float* bh2   = (const float*)d_in[13];
    float* out = (float*)d_out;

    cudaFuncSetAttribute(flow_fused, cudaFuncAttributeMaxDynamicSharedMemorySize, SMEMSZ);
    cudaFuncSetAttribute(head_hmma,  cudaFuncAttributeMaxDynamicSharedMemorySize, SMEMSZ);

    float *bufA = nullptr, *bufB = nullptr;
    cudaGetSymbolAddress((void**)&bufA, g_bufA);
    cudaGetSymbolAddress((void**)&bufB, g_bufB);

    prep_scale<<<Lc, 256>>>(gs);
    prep_wimg<<<(Lc*32768 + Lc*65536 + 65536)/256, 256>>>(W1, W2, Wh1);
    prep_pimg<<<(Lc*65536 + Lc*256)/256, 256>>>(P, go);

    flow_fused<<<NBLK, NTHR, SMEMSZ>>>(feat, bufB, b1, b2);

    head_hmma<<<NBLK, NTHR, SMEMSZ>>>(bufB, bufA, bh1);
    stats_kernel<<<1, 256>>>(gamma, beta);
    logpx_kernel<<<Bsz/8, 256>>>(bufB, out);
    logits_kernel<<<Bsz/8, 256>>>(bufA, Wh2, bh2, out + Bsz);
}

// round 10
// speedup vs baseline: 5.1827x; 1.0410x over previous
#include <cuda_runtime.h>
#include <cuda_bf16.h>
#include <math.h>
#include <stdint.h>

// ---------------- problem constants ----------------
#define Bsz   131072
#define Dd    256
#define Lc    8
#define NCc   10
#define BN_EPS 1e-5f
#define DGCONST -235.24826450039622f   // D * GCONST

#define MROW  64
#define NTHR  512
#define NBLK  (Bsz/MROW)      // 2048 CTAs

// smem byte offsets (all swizzled images, no padding)
#define XHIo 0
#define XLOo 32768
#define HBo  65536
#define BWo  98304            // 2 x 65536
#define SMEMSZ 229376

// ---------------- static device scratch ----------------
__device__ float g_bufA[(size_t)Bsz*Dd];          // h
__device__ float g_scale[Lc*Dd];
__device__ float g_sumlog[Lc];
__device__ float g_po[Lc*Dd];
__device__ float g_part[(size_t)NBLK*2*Dd];
__device__ float g_stats[2*Dd];
// pre-swizzled bf16 weight images (chunked K=64 smem layout)
__device__ __nv_bfloat16 g_w1t[(size_t)Lc*32768];
__device__ __nv_bfloat16 g_w2t[(size_t)Lc*65536];   // column-PERMUTED (see prep)
__device__ __nv_bfloat16 g_ph [(size_t)Lc*65536];   // P' = P*diag(scale), hi
__device__ __nv_bfloat16 g_pl [(size_t)Lc*65536];
__device__ __nv_bfloat16 g_whh[65536];
__device__ __nv_bfloat16 g_whl[65536];

// ---------------- helpers ----------------
__device__ __forceinline__ uint32_t packbf2(float a, float b) {
    __nv_bfloat162 t = __floats2bfloat162_rn(a, b);
    return *(uint32_t*)&t;
}
__device__ __forceinline__ float2 unpackbf2(uint32_t w) {
    __nv_bfloat162 t = *(__nv_bfloat162*)&w;
    return __bfloat1622float2(t);
}
__device__ __forceinline__ void split2(float a, float b, uint32_t& hw, uint32_t& lw) {
    __nv_bfloat16 ha = __float2bfloat16(a), hb = __float2bfloat16(b);
    float la = a - __bfloat162float(ha), lb = b - __bfloat162float(hb);
    __nv_bfloat162 h; h.x = ha; h.y = hb;
    hw = *(uint32_t*)&h;
    lw = packbf2(la, lb);
}
__device__ __forceinline__ float fast_tanh_scaled(float a) {
    float e = __expf(-0.2f * a);
    return 1.9f * __fdividef(1.f - e, 1.f + e);
}
__device__ __forceinline__ void cpab(void* dst_smem, const void* src) {
    unsigned s = (unsigned)__cvta_generic_to_shared(dst_smem);
    asm volatile("cp.async.cg.shared.global [%0], [%1], 16;" :: "r"(s), "l"(src));
}
#define CP_COMMIT asm volatile("cp.async.commit_group;")
#define CP_WAIT0  asm volatile("cp.async.wait_group 0;")

#define MMA(cd, a0, a1, a2, a3, b0, b1) \
    asm volatile("mma.sync.aligned.m16n8k16.row.col.f32.bf16.bf16.f32 " \
        "{%0,%1,%2,%3}, {%4,%5,%6,%7}, {%8,%9}, {%0,%1,%2,%3};" \
        : "+f"((cd)[0]), "+f"((cd)[1]), "+f"((cd)[2]), "+f"((cd)[3]) \
        : "r"(a0), "r"(a1), "r"(a2), "r"(a3), "r"(b0), "r"(b1))

#define LDSM4(r0, r1, r2, r3, addr) \
    asm volatile("ldmatrix.sync.aligned.m8n8.x4.shared.b16 {%0,%1,%2,%3}, [%4];" \
        : "=r"(r0), "=r"(r1), "=r"(r2), "=r"(r3) : "r"(addr))

__device__ __forceinline__ void stage32(char* dst, const __nv_bfloat16* src, int tid) {
    const char* s = (const char*)src;
    #pragma unroll
    for (int i = 0; i < 4; i++) cpab(dst + tid*16 + i*8192, s + tid*16 + i*8192);
}
__device__ __forceinline__ int imgoff(int n, int k) {
    return n*64 + (((k >> 3) ^ (n & 7)) << 3) + (k & 7);
}

// ---------------- preprocessing (3 launches) ----------------
__global__ void prep_scale(const float* __restrict__ gs) {
    __shared__ float red[256];
    int l = blockIdx.x, d = threadIdx.x;
    float x  = 0.5f * gs[l*Dd + d];
    float sp = (x > 20.f) ? x : log1pf(expf(x));
    float s  = 0.2f * sp;
    g_scale[l*Dd + d] = s;
    red[d] = logf(s);
    __syncthreads();
    #pragma unroll
    for (int o = 128; o; o >>= 1) { if (d < o) red[d] += red[d + o]; __syncthreads(); }
    if (d == 0) g_sumlog[l] = red[0];
}
__global__ void prep_wimg(const float* __restrict__ W1, const float* __restrict__ W2,
                          const float* __restrict__ Wh1) {
    int idx = blockIdx.x * 256 + threadIdx.x;
    if (idx < Lc*32768) {
        int k = idx & 127, n = (idx >> 7) & 255, l = idx >> 15;
        g_w1t[(size_t)l*32768 + (k>>6)*16384 + imgoff(n, k & 63)] =
            __float2bfloat16(W1[((size_t)l*128 + k)*256 + n]);
    } else if (idx < Lc*32768 + Lc*65536) {
        int j = idx - Lc*32768;
        int k = j & 255, n = (j >> 8) & 255, l = j >> 16;
        // column permutation: image row jr s.t. warp owning (c, c+128) pairs
        int jr = ((n & 127) >> 4) * 32 + ((n >> 7) << 4) + (n & 15);
        g_w2t[(size_t)l*65536 + (k>>6)*16384 + imgoff(jr, k & 63)] =
            __float2bfloat16(W2[((size_t)l*256 + k)*256 + n]);
    } else {
        int j = idx - (Lc*32768 + Lc*65536);
        int k = j & 255, n = j >> 8;
        float v = Wh1[(size_t)k*256 + n];
        __nv_bfloat16 hi = __float2bfloat16(v);
        size_t o = (size_t)(k>>6)*16384 + imgoff(n, k & 63);
        g_whh[o] = hi;
        g_whl[o] = __float2bfloat16(v - __bfloat162float(hi));
    }
}
__global__ void prep_pimg(const float* __restrict__ P, const float* __restrict__ go) {
    int idx = blockIdx.x * 256 + threadIdx.x;
    if (idx < Lc*65536) {
        int k = idx & 255, n = (idx >> 8) & 255, l = idx >> 16;
        float v = P[((size_t)l*256 + n)*256 + k] * g_scale[l*Dd + k];
        __nv_bfloat16 hi = __float2bfloat16(v);
        size_t o = (size_t)l*65536 + (k>>6)*16384 + imgoff(n, k & 63);
        g_ph[o] = hi;
        g_pl[o] = __float2bfloat16(v - __bfloat162float(hi));
    } else {
        int j = idx - Lc*65536;
        int l = j >> 8, n = j & 255;
        const float* pr = P + ((size_t)l*256 + n)*256;
        const float* o  = go + l*Dd;
        float acc = 0.f;
        for (int k = 0; k < 256; k++) acc += o[k] * pr[k];
        g_po[l*Dd + n] = acc;
    }
}

// ---------------- mega-fused: flow(8 layers) + log_px + head GEMM ----------------
__global__ void __launch_bounds__(NTHR, 1) flow_fused(
    const float* __restrict__ xin, float* __restrict__ hout,
    const float* __restrict__ b1, const float* __restrict__ b2,
    const float* __restrict__ bh1, float* __restrict__ logpx)
{
    extern __shared__ char smem[];
    const uint32_t su = (uint32_t)__cvta_generic_to_shared(smem);
    const uint32_t XHI = su + XHIo, XLO = su + XLOo, HBu = su + HBo, BWu = su + BWo;
    char* bw = smem + BWo;

    const int tid = threadIdx.x, lane = tid & 31, wid = tid >> 5;
    const int warpM = wid >> 3, warpN = wid & 7;
    const int g = lane >> 2, t = lane & 3;
    const int mrow0 = warpM * 32;
    const int n0 = warpN * 32;
    const int laneHi = lane >> 4;
    const int key = lane & 7;
    const int aRowB = (lane & 15) * 512;
    const int nloc = ((lane >> 4) << 3) + (lane & 7);
    const int bRow0 = (n0 + nloc) * 128, bRow1 = (n0 + 16 + nloc) * 128;
    const int bsel = (lane >> 3) & 1;
    const int c_base = n0 + 2*t;

    // prologue: stage layer-0 W1 in full (64KB -> buf0 == wb(layer0))
    stage32(bw,         g_w1t,         tid);
    stage32(bw + 32768, g_w1t + 16384, tid); CP_COMMIT;

    // load + split input x once
    {
        const float4* src = (const float4*)(xin + (size_t)blockIdx.x * MROW * Dd);
        #pragma unroll
        for (int i = tid; i < MROW * Dd / 4; i += NTHR) {
            int r = i >> 6, c = (i & 63) * 4;
            float4 v = src[i];
            uint32_t h0, l0, h1, l1;
            split2(v.x, v.y, h0, l0);
            split2(v.z, v.w, h1, l1);
            int off = r*512 + (((c >> 3) ^ (r & 7)) << 4) + (c & 7)*2;
            *(uint2*)(smem + XHIo + off) = make_uint2(h0, h1);
            *(uint2*)(smem + XLOo + off) = make_uint2(l0, l1);
        }
    }

    float cacc[2][4][4];
    float ldacc = 0.f;

    #pragma unroll 1
    for (int layer = 0; layer < Lc; layer++) {
        const float* bb1 = b1 + layer*Dd;
        const float* bb2 = b2 + layer*Dd;
        const __nv_bfloat16* w2img = g_w2t + (size_t)layer*65536;
        const __nv_bfloat16* phimg = g_ph  + (size_t)layer*65536;
        const __nv_bfloat16* plimg = g_pl  + (size_t)layer*65536;
        const uint32_t wbo = (uint32_t)((layer & 1) * 65536);
        const uint32_t obo = 65536u - wbo;

        // ===== GEMM1: H = relu(x1_hi @ W1 + b1), K=128, whole W1 in wb =====
        #pragma unroll
        for (int nt = 0; nt < 4; nt++) {
            int c = c_base + nt*8;
            float f0 = __ldg(bb1 + c), f1 = __ldg(bb1 + c + 1);
            #pragma unroll
            for (int mt = 0; mt < 2; mt++) {
                cacc[mt][nt][0] = f0; cacc[mt][nt][1] = f1;
                cacc[mt][nt][2] = f0; cacc[mt][nt][3] = f1;
            }
        }
        CP_WAIT0; __syncthreads();                                   // S1
        stage32(bw + obo,         w2img,         tid);
        stage32(bw + obo + 32768, w2img + 16384, tid); CP_COMMIT;
        #pragma unroll
        for (int kk = 0; kk < 8; kk++) {
            int gA = kk*2 + laneHi;
            uint32_t A[2][4], B[2][4];
            #pragma unroll
            for (int mt = 0; mt < 2; mt++)
                LDSM4(A[mt][0], A[mt][1], A[mt][2], A[mt][3],
                      XHI + (uint32_t)((mrow0 + mt*16)*512 + aRowB + ((gA ^ key) << 4)));
            uint32_t bb = BWu + wbo + (uint32_t)((kk >> 2) * 32768);
            uint32_t bsw = (uint32_t)(((((kk & 3)*2) + bsel) ^ key) << 4);
            LDSM4(B[0][0], B[0][1], B[0][2], B[0][3], bb + (uint32_t)bRow0 + bsw);
            LDSM4(B[1][0], B[1][1], B[1][2], B[1][3], bb + (uint32_t)bRow1 + bsw);
            #pragma unroll
            for (int p = 0; p < 2; p++)
                #pragma unroll
                for (int q = 0; q < 2; q++) {
                    int nt = p*2 + q;
                    MMA(cacc[0][nt], A[0][0], A[0][1], A[0][2], A[0][3], B[p][q*2], B[p][q*2+1]);
                    MMA(cacc[1][nt], A[1][0], A[1][1], A[1][2], A[1][3], B[p][q*2], B[p][q*2+1]);
                }
        }
        // relu -> HB (unpermuted)
        #pragma unroll
        for (int nt = 0; nt < 4; nt++) {
            int c = c_base + nt*8;
            int csw = ((c >> 3) ^ g) << 4;
            #pragma unroll
            for (int mt = 0; mt < 2; mt++) {
                int r = mrow0 + mt*16 + g;
                float* cf = cacc[mt][nt];
                *(uint32_t*)(smem + HBo + r*512     + csw + 4*t) =
                    packbf2(fmaxf(cf[0], 0.f), fmaxf(cf[1], 0.f));
                *(uint32_t*)(smem + HBo + (r+8)*512 + csw + 4*t) =
                    packbf2(fmaxf(cf[2], 0.f), fmaxf(cf[3], 0.f));
            }
        }

        // ===== GEMM2: A2 = H @ W2perm + b2, K=256 (output cols permuted) =====
        // accumulator (p,q): actual col = p*128 + warpN*16 + q*8 + 2t
        #pragma unroll
        for (int nt = 0; nt < 4; nt++) {
            int p = nt >> 1, q = nt & 1;
            int c2 = p*128 + warpN*16 + q*8 + 2*t;
            float f0 = __ldg(bb2 + c2), f1 = __ldg(bb2 + c2 + 1);
            #pragma unroll
            for (int mt = 0; mt < 2; mt++) {
                cacc[mt][nt][0] = f0; cacc[mt][nt][1] = f1;
                cacc[mt][nt][2] = f0; cacc[mt][nt][3] = f1;
            }
        }
        #pragma unroll 1
        for (int half2 = 0; half2 < 2; half2++) {
            CP_WAIT0; __syncthreads();                               // S2 / S3
            if (half2 == 0) {
                stage32(bw + wbo,         w2img + 32768, tid);
                stage32(bw + wbo + 32768, w2img + 49152, tid); CP_COMMIT;
            } else {
                stage32(bw + obo,         phimg, tid);
                stage32(bw + obo + 32768, plimg, tid); CP_COMMIT;
            }
            uint32_t cur = BWu + ((half2 == 0) ? obo : wbo);
            #pragma unroll
            for (int kk = 0; kk < 8; kk++) {
                int gA = half2*16 + kk*2 + laneHi;
                uint32_t A[2][4], B[2][4];
                #pragma unroll
                for (int mt = 0; mt < 2; mt++)
                    LDSM4(A[mt][0], A[mt][1], A[mt][2], A[mt][3],
                          HBu + (uint32_t)((mrow0 + mt*16)*512 + aRowB + ((gA ^ key) << 4)));
                uint32_t bb = cur + (uint32_t)((kk >> 2) * 32768);
                uint32_t bsw = (uint32_t)(((((kk & 3)*2) + bsel) ^ key) << 4);
                LDSM4(B[0][0], B[0][1], B[0][2], B[0][3], bb + (uint32_t)bRow0 + bsw);
                LDSM4(B[1][0], B[1][1], B[1][2], B[1][3], bb + (uint32_t)bRow1 + bsw);
                #pragma unroll
                for (int p = 0; p < 2; p++)
                    #pragma unroll
                    for (int q = 0; q < 2; q++) {
                        int nt = p*2 + q;
                        MMA(cacc[0][nt], A[0][0], A[0][1], A[0][2], A[0][3], B[p][q*2], B[p][q*2+1]);
                        MMA(cacc[1][nt], A[1][0], A[1][1], A[1][2], A[1][3], B[p][q*2], B[p][q*2+1]);
                    }
            }
        }
        CP_WAIT0; __syncthreads();                                   // S4
        stage32(bw + wbo,         phimg + 16384, tid);
        stage32(bw + wbo + 32768, plimg + 16384, tid); CP_COMMIT;

        // ===== coupling epilogue (register-local; s -> HB for logdet only) =====
        #pragma unroll
        for (int q = 0; q < 2; q++) {
            int cs = warpN*16 + q*8 + 2*t;
            int cx = 128 + cs;
            #pragma unroll
            for (int mt = 0; mt < 2; mt++) {
                #pragma unroll
                for (int half = 0; half < 2; half++) {
                    int i0 = half*2, r = mrow0 + mt*16 + g + half*8;
                    float s0 = fast_tanh_scaled(cacc[mt][q][i0]);
                    float s1 = fast_tanh_scaled(cacc[mt][q][i0 + 1]);
                    *(uint32_t*)(smem + HBo + r*512 + (((cs >> 3) ^ g) << 4) + 4*t) =
                        packbf2(s0, s1);
                    float a20 = 0.1f * cacc[mt][2 + q][i0];
                    float a21 = 0.1f * cacc[mt][2 + q][i0 + 1];
                    int xo = r*512 + (((cx >> 3) ^ g) << 4) + 4*t;
                    float2 hv = unpackbf2(*(uint32_t*)(smem + XHIo + xo));
                    float2 lv = unpackbf2(*(uint32_t*)(smem + XLOo + xo));
                    float v0 = (hv.x + lv.x) * __expf(s0) + a20;
                    float v1 = (hv.y + lv.y) * __expf(s1) + a21;
                    uint32_t hw, lw; split2(v0, v1, hw, lw);
                    *(uint32_t*)(smem + XHIo + xo) = hw;
                    *(uint32_t*)(smem + XLOo + xo) = lw;
                }
            }
        }

        // ===== GEMM3: Xnew = Xc @ P'^T + po, 3-term split, K=256 =====
        // ch0 reads only k<64 (x1, untouched by epilogue) -> no barrier needed here
        {
            const float* po = g_po + layer*Dd;
            #pragma unroll
            for (int nt = 0; nt < 4; nt++) {
                int c = c_base + nt*8;
                float f0 = __ldg(po + c), f1 = __ldg(po + c + 1);
                #pragma unroll
                for (int mt = 0; mt < 2; mt++) {
                    cacc[mt][nt][0] = f0; cacc[mt][nt][1] = f1;
                    cacc[mt][nt][2] = f0; cacc[mt][nt][3] = f1;
                }
            }
            #pragma unroll 1
            for (int ch = 0; ch < 4; ch++) {
                if (ch > 0) {
                    CP_WAIT0; __syncthreads();                       // S6..S8
                    if (ch < 3) {
                        uint32_t dsto = (ch == 1) ? obo : wbo;
                        stage32(bw + dsto,         phimg + (ch+1)*16384, tid);
                        stage32(bw + dsto + 32768, plimg + (ch+1)*16384, tid); CP_COMMIT;
                    } else if (layer + 1 < Lc) {
                        const __nv_bfloat16* w1n = g_w1t + (size_t)(layer+1)*32768;
                        stage32(bw + obo,         w1n,         tid);
                        stage32(bw + obo + 32768, w1n + 16384, tid); CP_COMMIT;
                    } else {
                        // final layer: prefetch head weight chunk0 -> ob
                        stage32(bw + obo,         g_whh, tid);
                        stage32(bw + obo + 32768, g_whl, tid); CP_COMMIT;
                    }
                }
                uint32_t cur = BWu + ((ch & 1) ? wbo : obo);
                #pragma unroll
                for (int ks = 0; ks < 64; ks += 16) {
                    int gA = (ch << 3) + (ks >> 3) + laneHi;
                    uint32_t Ah[2][4], Al[2][4], Bh[2][4], Bl[2][4];
                    #pragma unroll
                    for (int mt = 0; mt < 2; mt++) {
                        uint32_t abase = (uint32_t)((mrow0 + mt*16)*512 + aRowB + ((gA ^ key) << 4));
                        LDSM4(Ah[mt][0], Ah[mt][1], Ah[mt][2], Ah[mt][3], XHI + abase);
                        LDSM4(Al[mt][0], Al[mt][1], Al[mt][2], Al[mt][3], XLO + abase);
                    }
                    uint32_t bsw = (uint32_t)(((((ks >> 3) + bsel) ^ key) << 4));
                    LDSM4(Bh[0][0], Bh[0][1], Bh[0][2], Bh[0][3], cur + (uint32_t)bRow0 + bsw);
                    LDSM4(Bh[1][0], Bh[1][1], Bh[1][2], Bh[1][3], cur + (uint32_t)bRow1 + bsw);
                    LDSM4(Bl[0][0], Bl[0][1], Bl[0][2], Bl[0][3], cur + 32768u + (uint32_t)bRow0 + bsw);
                    LDSM4(Bl[1][0], Bl[1][1], Bl[1][2], Bl[1][3], cur + 32768u + (uint32_t)bRow1 + bsw);
                    #pragma unroll
                    for (int p = 0; p < 2; p++)
                        #pragma unroll
                        for (int q = 0; q < 2; q++) {
                            int nt = p*2 + q;
                            #pragma unroll
                            for (int mt = 0; mt < 2; mt++) {
                                MMA(cacc[mt][nt], Ah[mt][0], Ah[mt][1], Ah[mt][2], Ah[mt][3], Bh[p][q*2], Bh[p][q*2+1]);
                                MMA(cacc[mt][nt], Al[mt][0], Al[mt][1], Al[mt][2], Al[mt][3], Bh[p][q*2], Bh[p][q*2+1]);
                                MMA(cacc[mt][nt], Ah[mt][0], Ah[mt][1], Ah[mt][2], Ah[mt][3], Bl[p][q*2], Bl[p][q*2+1]);
                            }
                        }
                }
            }
            __syncthreads();                                         // S9: X/HB reads done
        }

        // logdet from s image (HB untouched during GEMM3)
        if (tid < MROW) {
            float rs = 0.f;
            int rk = tid & 7;
            #pragma unroll
            for (int gi = 0; gi < 16; gi++) {
                int gg = (gi + tid) & 15;
                uint4 w = *(uint4*)(smem + HBo + tid*512 + ((gg ^ rk) << 4));
                float2 p0 = unpackbf2(w.x), p1 = unpackbf2(w.y),
                       p2 = unpackbf2(w.z), p3 = unpackbf2(w.w);
                rs += (p0.x + p0.y) + (p1.x + p1.y) + (p2.x + p2.y) + (p3.x + p3.y);
            }
            ldacc += rs + g_sumlog[layer];
        }

        // split accumulators back into XHI/XLO (all layers; final = z)
        #pragma unroll
        for (int nt = 0; nt < 4; nt++) {
            int c = c_base + nt*8;
            int csw = ((c >> 3) ^ g) << 4;
            #pragma unroll
            for (int mt = 0; mt < 2; mt++) {
                float* cf = cacc[mt][nt];
                #pragma unroll
                for (int half = 0; half < 2; half++) {
                    int r = mrow0 + mt*16 + g + half*8;
                    uint32_t hw, lw;
                    split2(cf[half*2 + 0], cf[half*2 + 1], hw, lw);
                    *(uint32_t*)(smem + XHIo + r*512 + csw + 4*t) = hw;
                    *(uint32_t*)(smem + XLOo + r*512 + csw + 4*t) = lw;
                }
            }
        }
    }

    // ===================== fused tail: log_px + head GEMM =====================
    // z^2 partial per thread per row, reduce over t via shfl
    {
        float* HBf = (float*)(smem + HBo);
        float z2[2][2];
        #pragma unroll
        for (int mt = 0; mt < 2; mt++)
            #pragma unroll
            for (int half = 0; half < 2; half++) {
                float s = 0.f;
                #pragma unroll
                for (int nt = 0; nt < 4; nt++) {
                    float a = cacc[mt][nt][half*2 + 0], b = cacc[mt][nt][half*2 + 1];
                    s += a*a + b*b;
                }
                s += __shfl_xor_sync(0xffffffffu, s, 1);
                s += __shfl_xor_sync(0xffffffffu, s, 2);
                z2[mt][half] = s;
            }
        CP_WAIT0;                      // head wh chunk0 arrived
        __syncthreads();               // S10: logdet reads done; z visible
        if (t == 0) {
            #pragma unroll
            for (int mt = 0; mt < 2; mt++)
                #pragma unroll
                for (int half = 0; half < 2; half++) {
                    int r = mrow0 + mt*16 + g + half*8;
                    HBf[r*8 + warpN] = z2[mt][half];
                }
        }
        __syncthreads();               // S11
        if (tid < MROW) {
            float ss = 0.f;
            #pragma unroll
            for (int w = 0; w < 8; w++) ss += HBf[tid*8 + w];
            logpx[(size_t)blockIdx.x * MROW + tid] =
                (DGCONST - 0.5f*ss + ldacc) * (1.0f/Dd);
        }
    }

    // head GEMM: h = z @ Wh1 (3-term) + bh1; buffers: ob=0, wb=65536 (layer7 parity)
    {
        const uint32_t wbo = 65536u, obo = 0u;
        // stage chunk1 -> wb during ch0 compute
        stage32(bw + wbo,         g_whh + 16384, tid);
        stage32(bw + wbo + 32768, g_whl + 16384, tid); CP_COMMIT;

        #pragma unroll
        for (int nt = 0; nt < 4; nt++) {
            int c = c_base + nt*8;
            float f0 = __ldg(bh1 + c), f1 = __ldg(bh1 + c + 1);
            #pragma unroll
            for (int mt = 0; mt < 2; mt++) {
                cacc[mt][nt][0] = f0; cacc[mt][nt][1] = f1;
                cacc[mt][nt][2] = f0; cacc[mt][nt][3] = f1;
            }
        }
        #pragma unroll 1
        for (int ch = 0; ch < 4; ch++) {
            if (ch > 0) {
                CP_WAIT0; __syncthreads();
                if (ch < 3) {
                    uint32_t dsto = (ch == 1) ? obo : wbo;
                    stage32(bw + dsto,         g_whh + (ch+1)*16384, tid);
                    stage32(bw + dsto + 32768, g_whl + (ch+1)*16384, tid); CP_COMMIT;
                }
            }
            uint32_t cur = BWu + ((ch & 1) ? wbo : obo);
            #pragma unroll
            for (int ks = 0; ks < 64; ks += 16) {
                int gA = (ch << 3) + (ks >> 3) + laneHi;
                uint32_t Ah[2][4], Al[2][4], Bh[2][4], Bl[2][4];
                #pragma unroll
                for (int mt = 0; mt < 2; mt++) {
                    uint32_t abase = (uint32_t)((mrow0 + mt*16)*512 + aRowB + ((gA ^ key) << 4));
                    LDSM4(Ah[mt][0], Ah[mt][1], Ah[mt][2], Ah[mt][3], XHI + abase);
                    LDSM4(Al[mt][0], Al[mt][1], Al[mt][2], Al[mt][3], XLO + abase);
                }
                uint32_t bsw = (uint32_t)(((((ks >> 3) + bsel) ^ key) << 4));
                LDSM4(Bh[0][0], Bh[0][1], Bh[0][2], Bh[0][3], cur + (uint32_t)bRow0 + bsw);
                LDSM4(Bh[1][0], Bh[1][1], Bh[1][2], Bh[1][3], cur + (uint32_t)bRow1 + bsw);
                LDSM4(Bl[0][0], Bl[0][1], Bl[0][2], Bl[0][3], cur + 32768u + (uint32_t)bRow0 + bsw);
                LDSM4(Bl[1][0], Bl[1][1], Bl[1][2], Bl[1][3], cur + 32768u + (uint32_t)bRow1 + bsw);
                #pragma unroll
                for (int p = 0; p < 2; p++)
                    #pragma unroll
                    for (int q = 0; q < 2; q++) {
                        int nt = p*2 + q;
                        #pragma unroll
                        for (int mt = 0; mt < 2; mt++) {
                            MMA(cacc[mt][nt], Ah[mt][0], Ah[mt][1], Ah[mt][2], Ah[mt][3], Bh[p][q*2], Bh[p][q*2+1]);
                            MMA(cacc[mt][nt], Al[mt][0], Al[mt][1], Al[mt][2], Al[mt][3], Bh[p][q*2], Bh[p][q*2+1]);
                            MMA(cacc[mt][nt], Ah[mt][0], Ah[mt][1], Ah[mt][2], Ah[mt][3], Bl[p][q*2], Bl[p][q*2+1]);
                        }
                    }
            }
        }
        __syncthreads();               // S12: z reads done, smem free

        // h epilogue: gmem write + fp32 overlay for BN partials
        float* stg = (float*)smem;     // [64][264] over XHI/XLO/HB
        #pragma unroll
        for (int mt = 0; mt < 2; mt++)
            #pragma unroll
            for (int half = 0; half < 2; half++) {
                int rl = mrow0 + mt*16 + g + half*8;
                int r  = blockIdx.x * MROW + rl;
                #pragma unroll
                for (int nt = 0; nt < 4; nt++) {
                    int c = c_base + nt*8;
                    float* cf = cacc[mt][nt];
                    float v0 = cf[half*2 + 0];
                    float v1 = cf[half*2 + 1];
                    *(float2*)(hout + (size_t)r*Dd + c) = make_float2(v0, v1);
                    stg[(size_t)rl*264 + c]     = v0;
                    stg[(size_t)rl*264 + c + 1] = v1;
                }
            }
        __syncthreads();               // S13
        if (tid < Dd) {
            float s = 0.f, q = 0.f;
            #pragma unroll 4
            for (int r = 0; r < MROW; r++) {
                float v = stg[(size_t)r*264 + tid];
                s += v; q += v * v;
            }
            g_part[(size_t)blockIdx.x*2*Dd + tid]      = s;
            g_part[(size_t)blockIdx.x*2*Dd + Dd + tid] = q;
        }
    }
}

// ---------------- BN stats fold ----------------
__global__ void stats_kernel(const float* __restrict__ gamma, const float* __restrict__ beta) {
    int c = threadIdx.x;
    float s0=0.f,s1=0.f,s2=0.f,s3=0.f, q0=0.f,q1=0.f,q2=0.f,q3=0.f;
    for (int i = 0; i < NBLK; i += 4) {
        s0 += g_part[(size_t)(i+0)*2*Dd + c];   q0 += g_part[(size_t)(i+0)*2*Dd + Dd + c];
        s1 += g_part[(size_t)(i+1)*2*Dd + c];   q1 += g_part[(size_t)(i+1)*2*Dd + Dd + c];
        s2 += g_part[(size_t)(i+2)*2*Dd + c];   q2 += g_part[(size_t)(i+2)*2*Dd + Dd + c];
        s3 += g_part[(size_t)(i+3)*2*Dd + c];   q3 += g_part[(size_t)(i+3)*2*Dd + Dd + c];
    }
    float s = (s0+s1)+(s2+s3), q = (q0+q1)+(q2+q3);
    float mu  = s * (1.f/Bsz);
    float var = q * (1.f/Bsz) - mu*mu;
    float a = gamma[c] * rsqrtf(var + BN_EPS);
    g_stats[c]      = a;
    g_stats[Dd + c] = beta[c] - mu * a;
}

// ---------------- logits ----------------
__global__ void __launch_bounds__(256) logits_kernel(
    const float* __restrict__ h, const float* __restrict__ Wh2,
    const float* __restrict__ bh2, float* __restrict__ out)
{
    __shared__ float w2s[Dd*NCc];
    __shared__ float As[Dd], Bs[Dd];
    int tid = threadIdx.x;
    for (int i = tid; i < Dd*NCc; i += 256) w2s[i] = Wh2[i];
    if (tid < Dd) { As[tid] = g_stats[tid]; Bs[tid] = g_stats[Dd + tid]; }
    __syncthreads();

    int warp = tid >> 5, lane = tid & 31;
    size_t row = (size_t)blockIdx.x * 8 + warp;
    const float4* hr = (const float4*)(h + row*Dd);
    float4 v0 = hr[lane*2], v1 = hr[lane*2 + 1];
    int k0 = lane * 8;
    float hn[8];
    hn[0] = fmaxf(v0.x*As[k0+0] + Bs[k0+0], 0.f);
    hn[1] = fmaxf(v0.y*As[k0+1] + Bs[k0+1], 0.f);
    hn[2] = fmaxf(v0.z*As[k0+2] + Bs[k0+2], 0.f);
    hn[3] = fmaxf(v0.w*As[k0+3] + Bs[k0+3], 0.f);
    hn[4] = fmaxf(v1.x*As[k0+4] + Bs[k0+4], 0.f);
    hn[5] = fmaxf(v1.y*As[k0+5] + Bs[k0+5], 0.f);
    hn[6] = fmaxf(v1.z*As[k0+6] + Bs[k0+6], 0.f);
    hn[7] = fmaxf(v1.w*As[k0+7] + Bs[k0+7], 0.f);

    float acc[NCc];
    #pragma unroll
    for (int c = 0; c < NCc; c++) acc[c] = 0.f;
    #pragma unroll
    for (int kk = 0; kk < 8; kk++) {
        float x = hn[kk];
        const float* wr = &w2s[(k0+kk)*NCc];
        #pragma unroll
        for (int c = 0; c < NCc; c++) acc[c] += x * wr[c];
    }
    #pragma unroll
    for (int c = 0; c < NCc; c++) {
        #pragma unroll
        for (int o = 16; o; o >>= 1) acc[c] += __shfl_down_sync(0xffffffffu, acc[c], o);
    }
    if (lane == 0) {
        #pragma unroll
        for (int c = 0; c < NCc; c++) out[row*NCc + c] = acc[c] + __ldg(bh2 + c);
    }
}

// ---------------- launch ----------------
extern "C" void kernel_launch(void* const* d_in, const int* in_sizes, int n_in,
                              void* d_out, int out_size)
{
    const float* feat  = (const float*)d_in[0];
    const float* W1    = (const float*)d_in[1];
    const float* b1    = (const float*)d_in[2];
    const float* W2    = (const float*)d_in[3];
    const float* b2    = (const float*)d_in[4];
    const float* gs    = (const float*)d_in[5];
    const float* go    = (const float*)d_in[6];
    const float* P     = (const float*)d_in[7];
    const float* Wh1   = (const float*)d_in[8];
    const float* bh1   = (const float*)d_in[9];
    const float* gamma = (const float*)d_in[10];
    const float* beta  = (const float*)d_in[11];
    const float* Wh2   = (const float*)d_in[12];
    const float* bh2   = (const float*)d_in[13];
    float* out = (float*)d_out;

    cudaFuncSetAttribute(flow_fused, cudaFuncAttributeMaxDynamicSharedMemorySize, SMEMSZ);

    float* bufA = nullptr;
    cudaGetSymbolAddress((void**)&bufA, g_bufA);

    prep_scale<<<Lc, 256>>>(gs);
    prep_wimg<<<(Lc*32768 + Lc*65536 + 65536)/256, 256>>>(W1, W2, Wh1);
    prep_pimg<<<(Lc*65536 + Lc*256)/256, 256>>>(P, go);

    flow_fused<<<NBLK, NTHR, SMEMSZ>>>(feat, bufA, b1, b2, bh1, out);

    stats_kernel<<<1, 256>>>(gamma, beta);
    logits_kernel<<<Bsz/8, 256>>>(bufA, Wh2, bh2, out + Bsz);
}